// round 10
// baseline (speedup 1.0000x reference)
#include <cuda_runtime.h>
#include <cuda_fp16.h>
#include <math.h>
#include <stdint.h>

// Problem dims
#define L_ 12
#define B_ 2
#define T_ 1024
#define D_ 1024
#define H_ 16
#define HD_ 64
#define F_ 4096
#define V_ 50257
#define VPAD_ 50304
#define BT_ (B_*T_)

// ================= scratch (__device__ globals) =================
__device__ float g_x  [BT_*D_];
__device__ float g_qkv[BT_*3072];
__device__ float g_att[(size_t)B_*H_*T_*T_];

__device__ __align__(256) __half g_hh [BT_*D_];
__device__ __align__(256) __half g_hl [BT_*D_];
__device__ __align__(256) __half g_obh[BT_*D_];
__device__ __align__(256) __half g_obl[BT_*D_];
__device__ __align__(256) __half g_mph[BT_*F_];
__device__ __align__(256) __half g_mpl[BT_*F_];

// attention operands
__device__ __align__(256) __half g_qTh[BT_*D_];
__device__ __align__(256) __half g_qTl[BT_*D_];
__device__ __align__(256) __half g_kTh[BT_*D_];          // K single fp16
__device__ __align__(256) __half g_vTh[BT_*D_];          // V single fp16, [B,H,HD,T]
__device__ __align__(256) __half g_ph [(size_t)B_*H_*T_*T_];
__device__ __align__(256) __half g_pl [(size_t)B_*H_*T_*T_];

// converted+transposed weights [N,K] layout, single fp16
__device__ __align__(256) __half g_wqkv[(size_t)L_*3072*D_];
__device__ __align__(256) __half g_wo  [(size_t)L_*D_*D_];
__device__ __align__(256) __half g_w1  [(size_t)L_*F_*D_];
__device__ __align__(256) __half g_w2  [(size_t)L_*D_*F_];
__device__ __align__(256) __half g_wlm [(size_t)VPAD_*D_];

// ================= small helpers =================
__device__ __forceinline__ uint32_t smem_u32(const void* p) {
    uint32_t a;
    asm("{ .reg .u64 t; cvta.to.shared.u64 t, %1; cvt.u32.u64 %0, t; }" : "=r"(a) : "l"(p));
    return a;
}
__device__ __forceinline__ void fp16_split(float v, __half& hi, __half& lo) {
    hi = __float2half(v);
    lo = __float2half(v - __half2float(hi));
}

// ================= elementwise / conversion kernels =================
__global__ void embed_kernel(const int* __restrict__ ids, const float* __restrict__ emb,
                             const float* __restrict__ pos, float* __restrict__ x) {
    int idx = blockIdx.x * 256 + threadIdx.x;
    int row = idx >> 10;
    int c   = idx & 1023;
    int t   = row & (T_-1);
    x[idx] = emb[(size_t)ids[row]*D_ + c] + pos[(size_t)t*D_ + c];
}

// W [K,N] fp32 -> out [Npad,K] fp16 (transposed, zero-padded), batched over z
__global__ void wconv_kernel(const float* __restrict__ W, __half* __restrict__ oh,
                             int K, int N, long long srcStride, long long dstStride) {
    __shared__ float tile[32][33];
    const float* Ws = W + (size_t)blockIdx.z * srcStride;
    __half* ohz = oh + (size_t)blockIdx.z * dstStride;
    int n0 = blockIdx.x * 32, k0 = blockIdx.y * 32;
    #pragma unroll
    for (int j = 0; j < 32; j += 8) {
        int kk = k0 + threadIdx.y + j;
        int nn = n0 + threadIdx.x;
        tile[threadIdx.y + j][threadIdx.x] = (nn < N) ? Ws[(size_t)kk*N + nn] : 0.f;
    }
    __syncthreads();
    #pragma unroll
    for (int j = 0; j < 32; j += 8) {
        int nn = n0 + threadIdx.y + j;
        int kk = k0 + threadIdx.x;
        ohz[(size_t)nn*K + kk] = __float2half(tile[threadIdx.x][threadIdx.y + j]);
    }
}

// Wq/Wk/Wv [L][K,N] fp32 -> g_wqkv [L][3072,K] fp16, z in [0, 3L)
__global__ void wconv3_kernel(const float* __restrict__ Wq, const float* __restrict__ Wk,
                              const float* __restrict__ Wv, __half* __restrict__ dst) {
    __shared__ float tile[32][33];
    int z = blockIdx.z;
    int l = z / 3, sel = z % 3;
    const float* Ws = (sel == 0 ? Wq : sel == 1 ? Wk : Wv) + (size_t)l * D_ * D_;
    __half* od = dst + ((size_t)l * 3072 + sel * D_) * D_;
    int n0 = blockIdx.x * 32, k0 = blockIdx.y * 32;
    #pragma unroll
    for (int j = 0; j < 32; j += 8) {
        tile[threadIdx.y + j][threadIdx.x] = Ws[(size_t)(k0 + threadIdx.y + j)*D_ + n0 + threadIdx.x];
    }
    __syncthreads();
    #pragma unroll
    for (int j = 0; j < 32; j += 8) {
        int nn = n0 + threadIdx.y + j;
        int kk = k0 + threadIdx.x;
        od[(size_t)nn*D_ + kk] = __float2half(tile[threadIdx.x][threadIdx.y + j]);
    }
}

__global__ void rmsnorm_split_kernel(const float* __restrict__ x, const float* __restrict__ w,
                                     __half* __restrict__ oh, __half* __restrict__ ol) {
    __shared__ float red[256];
    int row = blockIdx.x;
    const float* xr = x + (size_t)row * D_;
    float v[4]; float ss = 0.f;
    #pragma unroll
    for (int i = 0; i < 4; i++) { v[i] = xr[threadIdx.x + 256*i]; ss += v[i]*v[i]; }
    red[threadIdx.x] = ss; __syncthreads();
    for (int s = 128; s > 0; s >>= 1) {
        if (threadIdx.x < s) red[threadIdx.x] += red[threadIdx.x + s];
        __syncthreads();
    }
    float r = rsqrtf(red[0] / (float)D_ + 1e-5f);
    #pragma unroll
    for (int i = 0; i < 4; i++) {
        int c = threadIdx.x + 256*i;
        float y = w[c] * v[i] * r;
        __half hi, lo; fp16_split(y, hi, lo);
        oh[(size_t)row*D_ + c] = hi;
        ol[(size_t)row*D_ + c] = lo;
    }
}

// RMS over head_dim + transpose [B,T,3D] -> [B,H,T,HD] fp16 (lo optional). One warp per (b,t,h).
__global__ void qknorm_split_kernel(const float* __restrict__ qkv, int colOff,
                                    const float* __restrict__ w,
                                    __half* __restrict__ qh, __half* __restrict__ ql) {
    int warp = (blockIdx.x * blockDim.x + threadIdx.x) >> 5;
    int lane = threadIdx.x & 31;
    int h  = warp & (H_-1);
    int bt = warp >> 4;
    int t  = bt & (T_-1);
    int b  = bt >> 10;
    const float* src = qkv + (size_t)bt * 3072 + colOff + h * HD_;
    float x0 = src[lane], x1 = src[lane + 32];
    float ss = x0*x0 + x1*x1;
    #pragma unroll
    for (int o = 16; o > 0; o >>= 1) ss += __shfl_xor_sync(0xffffffffu, ss, o);
    float r = rsqrtf(ss / (float)HD_ + 1e-5f);
    size_t dst = ((size_t)((b*H_ + h)*T_ + t)) * HD_;
    float y0 = w[lane] * x0 * r;
    float y1 = w[lane + 32] * x1 * r;
    __half h0 = __float2half(y0);
    __half h1 = __float2half(y1);
    qh[dst + lane]      = h0;
    qh[dst + lane + 32] = h1;
    if (ql) {
        ql[dst + lane]      = __float2half(y0 - __half2float(h0));
        ql[dst + lane + 32] = __float2half(y1 - __half2float(h1));
    }
}

// V: [B,T,3D](col 2048+) -> [B,H,HD,T] single fp16 via 32x32 tile transpose
__global__ void vtrans_kernel(const float* __restrict__ qkv, __half* __restrict__ vh) {
    __shared__ float tile[32][33];
    int z = blockIdx.z;           // b*H+h
    int b = z >> 4, h = z & 15;
    int t0 = blockIdx.x * 32, d0 = blockIdx.y * 32;
    #pragma unroll
    for (int j = 0; j < 32; j += 8) {
        int t = t0 + threadIdx.y + j;
        tile[threadIdx.y + j][threadIdx.x] =
            qkv[(size_t)(b*T_ + t)*3072 + 2048 + h*HD_ + d0 + threadIdx.x];
    }
    __syncthreads();
    #pragma unroll
    for (int j = 0; j < 32; j += 8) {
        int d = d0 + threadIdx.y + j;
        size_t o = ((size_t)z * HD_ + d) * T_ + t0 + threadIdx.x;
        vh[o] = __float2half(tile[threadIdx.x][threadIdx.y + j]);
    }
}

// causal softmax, scale 1/8, per-head gate; writes P fp16 hi/lo only up to
// qlim = roundup(q+1, 64) (PV's 64-aligned causal K-limit never reads beyond it)
__global__ void softmax_kernel(const float* __restrict__ S, const float* __restrict__ gate,
                               __half* __restrict__ ph, __half* __restrict__ pl) {
    __shared__ float red[256];
    int row = blockIdx.x;
    int q = row & (T_-1);
    int h = (row >> 10) & (H_-1);
    const float* s = S + (size_t)row * T_;
    const float scale = 0.125f;
    float vals[4]; float m = -3.4e38f;
    #pragma unroll
    for (int i = 0; i < 4; i++) {
        int j = threadIdx.x + 256*i;
        float v = (j <= q) ? s[j] * scale : -3.4e38f;
        vals[i] = v; m = fmaxf(m, v);
    }
    red[threadIdx.x] = m; __syncthreads();
    for (int t = 128; t > 0; t >>= 1) {
        if (threadIdx.x < t) red[threadIdx.x] = fmaxf(red[threadIdx.x], red[threadIdx.x + t]);
        __syncthreads();
    }
    m = red[0]; __syncthreads();
    float sum = 0.f;
    #pragma unroll
    for (int i = 0; i < 4; i++) {
        int j = threadIdx.x + 256*i;
        float e = (j <= q) ? __expf(vals[i] - m) : 0.f;
        vals[i] = e; sum += e;
    }
    red[threadIdx.x] = sum; __syncthreads();
    for (int t = 128; t > 0; t >>= 1) {
        if (threadIdx.x < t) red[threadIdx.x] += red[threadIdx.x + t];
        __syncthreads();
    }
    float inv = gate[h] / red[0];
    int qlim = (q & ~63) + 64;
    #pragma unroll
    for (int i = 0; i < 4; i++) {
        int j = threadIdx.x + 256*i;
        if (j < qlim) {
            float p = vals[i] * inv;
            __half hi, lo; fp16_split(p, hi, lo);
            ph[(size_t)row*T_ + j] = hi;
            pl[(size_t)row*T_ + j] = lo;
        }
    }
}

// ================= shared HMMA building blocks =================
#define HG_ROWB 80

__device__ __forceinline__ void hg_ldm4(uint32_t addr, uint32_t* r) {
    asm volatile("ldmatrix.sync.aligned.m8n8.x4.shared.b16 {%0,%1,%2,%3}, [%4];"
        : "=r"(r[0]), "=r"(r[1]), "=r"(r[2]), "=r"(r[3]) : "r"(addr));
}
__device__ __forceinline__ void hg_mma(float* d, const uint32_t* a, uint32_t b0, uint32_t b1) {
    asm volatile("mma.sync.aligned.m16n8k16.row.col.f32.f16.f16.f32 "
        "{%0,%1,%2,%3}, {%4,%5,%6,%7}, {%8,%9}, {%0,%1,%2,%3};"
        : "+f"(d[0]), "+f"(d[1]), "+f"(d[2]), "+f"(d[3])
        : "r"(a[0]), "r"(a[1]), "r"(a[2]), "r"(a[3]), "r"(b0), "r"(b1));
}

template<int BM, int BN>
__device__ __forceinline__ void hg_load2(uint32_t stg,
    const __half* Ah, const __half* Al, const __half* Bh,
    int m0, int n0, int K, int k0, int tid)
{
    constexpr int CA = BM * 4;         // 16B chunks per A matrix
    constexpr int CB = BN * 4;
    constexpr int TOT = 2*CA + CB;
    #pragma unroll
    for (int p = 0; p < TOT/256; p++) {
        int c = tid + p * 256;
        const __half* base; int r0; uint32_t mo; int rr;
        if (c < CA)        { base = Ah; r0 = m0; mo = 0;            rr = c; }
        else if (c < 2*CA) { base = Al; r0 = m0; mo = BM*HG_ROWB;   rr = c - CA; }
        else               { base = Bh; r0 = n0; mo = 2*BM*HG_ROWB; rr = c - 2*CA; }
        int r = rr >> 2, kc = rr & 3;
        uint32_t so = stg + mo + r * HG_ROWB + kc * 16;
        const void* ga = (const void*)(base + (size_t)(r0 + r) * K + k0 + kc * 8);
        asm volatile("cp.async.cg.shared.global [%0], [%1], 16;\n" :: "r"(so), "l"(ga));
    }
    asm volatile("cp.async.commit_group;\n" ::: "memory");
}

// ======== dense GEMM: 64x128 tile, pair double-buffer + REGISTER fragment
// double-buffer: LDSMs for sub-step s+1 are issued BEFORE the MMAs of sub-step s,
// hiding ldmatrix latency inside the chunk. MMA order per accumulator unchanged.
// C[M,N] = (Ah+Al)[M,K] @ Bh[N,K]^T.  MODE: 0=plain(guard Nout), 1=+RES, 2=GELU->split
struct HgFrag { uint32_t ah[4]; uint32_t al[4]; uint32_t bh[4][4]; };

__device__ __forceinline__ void hgd_ldfrag(uint32_t st, uint32_t kb,
                                           int warpM, int warpN,
                                           uint32_t aoff, uint32_t boff, HgFrag& f)
{
    constexpr int MATA = 64 * HG_ROWB;
    uint32_t rb = (uint32_t)(warpM * HG_ROWB) + kb;
    hg_ldm4(st            + rb + aoff, f.ah);
    hg_ldm4(st + MATA     + rb + aoff, f.al);
    uint32_t sBh = st + 2*MATA;
    #pragma unroll
    for (int nt = 0; nt < 4; nt++) {
        uint32_t rbn = (uint32_t)((warpN + nt * 16) * HG_ROWB) + kb;
        hg_ldm4(sBh + rbn + boff, f.bh[nt]);
    }
}

template<int MODE>
__global__ __launch_bounds__(256, 2)
void hgemmd_kernel(const __half* __restrict__ Ah, const __half* __restrict__ Al,
                   const __half* __restrict__ Bh,
                   const float* __restrict__ AUX, float* __restrict__ C,
                   __half* __restrict__ Gh, __half* __restrict__ Gl,
                   int K, int Nout, int ldc)
{
    constexpr int BM = 64, BN = 128;
    constexpr int STAGE = (2*BM + BN) * HG_ROWB;   // 20480
    constexpr int NJ = 8;

    extern __shared__ char dsm[];
    uint32_t sb = smem_u32(dsm);

    const int tid  = threadIdx.x;
    const int lane = tid & 31;
    const int wid  = tid >> 5;
    const int warpM = (wid & 3) * 16;
    const int warpN = (wid >> 2) * 64;

    const int m0 = blockIdx.y * BM;
    const int n0 = blockIdx.x * BN;

    const uint32_t aoff = (uint32_t)((lane & 15) * HG_ROWB + (lane >> 4) * 16);
    const uint32_t boff = (uint32_t)(((lane & 7) + ((lane >> 4) & 1) * 8) * HG_ROWB
                                     + ((lane >> 3) & 1) * 16);

    float acc[NJ][4];
    #pragma unroll
    for (int j = 0; j < NJ; j++)
        #pragma unroll
        for (int u = 0; u < 4; u++) acc[j][u] = 0.f;

    const int nk = K / 32;          // even, >= 4 (K = 1024 or 4096)
    const int np = nk / 2;

    // preload pair 0 (chunks 0,1) -> stages 0,1
    hg_load2<BM,BN>(sb,          Ah, Al, Bh, m0, n0, K, 0,  tid);
    hg_load2<BM,BN>(sb + STAGE,  Ah, Al, Bh, m0, n0, K, 32, tid);

    HgFrag fr[2];

    for (int ip = 0; ip < np; ip++) {
        int c0 = 2 * ip;
        asm volatile("cp.async.wait_group 0;\n" ::: "memory");
        __syncthreads();
        // issue pair ip+1 into pair ip-1's stages (freed by the sync)
        if (c0 + 2 < nk) {
            hg_load2<BM,BN>(sb + ((c0 + 2) & 3) * STAGE, Ah, Al, Bh, m0, n0, K, (c0 + 2) * 32, tid);
            hg_load2<BM,BN>(sb + ((c0 + 3) & 3) * STAGE, Ah, Al, Bh, m0, n0, K, (c0 + 3) * 32, tid);
        }

        const uint32_t stA = sb + ((c0)     & 3) * STAGE;
        const uint32_t stB = sb + ((c0 + 1) & 3) * STAGE;

        // 4 sub-steps: (stA,kq0) (stA,kq1) (stB,kq0) (stB,kq1), frags double-buffered
        hgd_ldfrag(stA, 0, warpM, warpN, aoff, boff, fr[0]);
        int buf = 0;
        #pragma unroll
        for (int s = 0; s < 4; s++) {
            if (s < 3) {
                uint32_t stn = (s == 0) ? stA : stB;
                uint32_t kbn = (s == 1) ? 0u : 32u;   // s=0 -> (stA,32); s=1 -> (stB,0); s=2 -> (stB,32)
                hgd_ldfrag(stn, kbn, warpM, warpN, aoff, boff, fr[buf ^ 1]);
            }
            HgFrag& f = fr[buf];
            #pragma unroll
            for (int nj = 0; nj < NJ; nj++) {
                uint32_t b0 = f.bh[nj >> 1][(nj & 1) * 2];
                uint32_t b1 = f.bh[nj >> 1][(nj & 1) * 2 + 1];
                hg_mma(acc[nj], f.ah, b0, b1);
                hg_mma(acc[nj], f.al, b0, b1);
            }
            buf ^= 1;
        }
    }

    // epilogue
    const int g = lane >> 2;
    const int tq = lane & 3;
    int row0 = m0 + warpM + g;
    int row1 = row0 + 8;
    #pragma unroll
    for (int nj = 0; nj < NJ; nj++) {
        int col = n0 + warpN + nj * 8 + tq * 2;
        float* a = acc[nj];
        if (MODE == 1) {
            size_t o0 = (size_t)row0 * ldc + col;
            size_t o1 = (size_t)row1 * ldc + col;
            C[o0]     = a[0] + AUX[o0];
            C[o0 + 1] = a[1] + AUX[o0 + 1];
            C[o1]     = a[2] + AUX[o1];
            C[o1 + 1] = a[3] + AUX[o1 + 1];
        } else if (MODE == 2) {
            #pragma unroll
            for (int half = 0; half < 2; half++) {
                int r = half ? row1 : row0;
                float v0 = a[half * 2], v1 = a[half * 2 + 1];
                float g0 = 0.5f * v0 * (1.0f + erff(v0 * 0.70710678118654752f));
                float g1 = 0.5f * v1 * (1.0f + erff(v1 * 0.70710678118654752f));
                __half h0, l0, h1, l1;
                fp16_split(g0, h0, l0); fp16_split(g1, h1, l1);
                __half2 hp; hp.x = h0; hp.y = h1;
                __half2 lp; lp.x = l0; lp.y = l1;
                size_t o = (size_t)r * ldc + col;
                *(__half2*)&Gh[o] = hp;
                *(__half2*)&Gl[o] = lp;
            }
        } else {
            if (col < Nout) {
                C[(size_t)row0 * ldc + col] = a[0];
                C[(size_t)row1 * ldc + col] = a[2];
            }
            if (col + 1 < Nout) {
                C[(size_t)row0 * ldc + col + 1] = a[1];
                C[(size_t)row1 * ldc + col + 1] = a[3];
            }
        }
    }
}

// ======== attention GEMM (scores / PV): 3-stage, batched (unchanged, proven) ========
// MODE: 0 = fp32 store, 3 = PV merge->fp16 split
template<int BM, int BN, int MODE, bool CSKIP, bool CKLIM>
__global__ __launch_bounds__(256, 2)
void hgemm2_kernel(const __half* __restrict__ Ah, const __half* __restrict__ Al,
                   const __half* __restrict__ Bh,
                   const float* __restrict__ AUX, float* __restrict__ C,
                   __half* __restrict__ Gh, __half* __restrict__ Gl,
                   int K, int Nout, int ldc,
                   long long sA, long long sB, long long sC)
{
    constexpr int MATA  = BM * HG_ROWB;
    constexpr int STAGE = (2*BM + BN) * HG_ROWB;
    constexpr int MI = BM / 64;
    constexpr int NJ = BN / 16;
    constexpr int NT = BN / 32;

    extern __shared__ char dsm[];
    uint32_t sb = smem_u32(dsm);

    const int tid  = threadIdx.x;
    const int lane = tid & 31;
    const int wid  = tid >> 5;
    const int warpM = (wid & 3) * (BM/4);
    const int warpN = (wid >> 2) * (BN/2);

    const int m0 = blockIdx.y * BM;
    const int n0 = blockIdx.x * BN;
    if (CSKIP && n0 > m0 + BM - 1) return;

    const int z = blockIdx.z;
    Ah += (size_t)z * sA; Al += (size_t)z * sA;
    Bh += (size_t)z * sB;
    if (MODE == 0) C += (size_t)z * sC;

    const uint32_t aoff = (uint32_t)((lane & 15) * HG_ROWB + (lane >> 4) * 16);
    const uint32_t boff = (uint32_t)(((lane & 7) + ((lane >> 4) & 1) * 8) * HG_ROWB
                                     + ((lane >> 3) & 1) * 16);

    float acc[MI][NJ][4];
    #pragma unroll
    for (int i = 0; i < MI; i++)
        #pragma unroll
        for (int j = 0; j < NJ; j++)
            #pragma unroll
            for (int u = 0; u < 4; u++) acc[i][j][u] = 0.f;

    const int kend = CKLIM ? (K < m0 + BM ? K : m0 + BM) : K;
    const int nk = kend / 32;

    hg_load2<BM,BN>(sb,          Ah, Al, Bh, m0, n0, K, 0,  tid);
    if (nk > 1)
        hg_load2<BM,BN>(sb + STAGE, Ah, Al, Bh, m0, n0, K, 32, tid);

    for (int it = 0; it < nk; it++) {
        int s = it % 3;
        if (it + 1 < nk) {
            asm volatile("cp.async.wait_group 1;\n" ::: "memory");
        } else {
            asm volatile("cp.async.wait_group 0;\n" ::: "memory");
        }
        __syncthreads();
        if (it + 2 < nk) {
            hg_load2<BM,BN>(sb + ((it + 2) % 3) * STAGE, Ah, Al, Bh, m0, n0, K, (it + 2) * 32, tid);
        }

        uint32_t st  = sb + s * STAGE;
        uint32_t sAh = st;
        uint32_t sAl = st + MATA;
        uint32_t sBh = st + 2*MATA;

        #pragma unroll
        for (int kq = 0; kq < 2; kq++) {
            uint32_t kb = kq * 32;
            uint32_t ah[MI][4], al[MI][4], bh[NT][4];
            #pragma unroll
            for (int mi = 0; mi < MI; mi++) {
                uint32_t rb = (uint32_t)((warpM + mi * 16) * HG_ROWB) + kb;
                hg_ldm4(sAh + rb + aoff, ah[mi]);
                hg_ldm4(sAl + rb + aoff, al[mi]);
            }
            #pragma unroll
            for (int nt = 0; nt < NT; nt++) {
                uint32_t rb = (uint32_t)((warpN + nt * 16) * HG_ROWB) + kb;
                hg_ldm4(sBh + rb + boff, bh[nt]);
            }
            #pragma unroll
            for (int mi = 0; mi < MI; mi++) {
                #pragma unroll
                for (int nj = 0; nj < NJ; nj++) {
                    uint32_t b0 = bh[nj >> 1][(nj & 1) * 2];
                    uint32_t b1 = bh[nj >> 1][(nj & 1) * 2 + 1];
                    hg_mma(acc[mi][nj], ah[mi], b0, b1);
                    hg_mma(acc[mi][nj], al[mi], b0, b1);
                }
            }
        }
    }

    const int g = lane >> 2;
    const int tq = lane & 3;
    #pragma unroll
    for (int mi = 0; mi < MI; mi++) {
        int row0 = m0 + warpM + mi * 16 + g;
        int row1 = row0 + 8;
        #pragma unroll
        for (int nj = 0; nj < NJ; nj++) {
            int col = n0 + warpN + nj * 8 + tq * 2;
            float* a = acc[mi][nj];
            if (MODE == 3) {
                int b  = z >> 4, h = z & 15;
                #pragma unroll
                for (int half = 0; half < 2; half++) {
                    int q = half ? row1 : row0;
                    size_t vsrc = (size_t)(b*T_ + q)*3072 + 2048 + h*HD_ + col;
                    float v0 = a[half * 2]     + AUX[vsrc];
                    float v1 = a[half * 2 + 1] + AUX[vsrc + 1];
                    __half h0, l0, h1, l1;
                    fp16_split(v0, h0, l0); fp16_split(v1, h1, l1);
                    __half2 hp; hp.x = h0; hp.y = h1;
                    __half2 lp; lp.x = l0; lp.y = l1;
                    size_t o = (size_t)(b*T_ + q)*D_ + h*HD_ + col;
                    *(__half2*)&Gh[o] = hp;
                    *(__half2*)&Gl[o] = lp;
                }
            } else {
                C[(size_t)row0 * ldc + col] = a[0];
                C[(size_t)row0 * ldc + col + 1] = a[1];
                C[(size_t)row1 * ldc + col] = a[2];
                C[(size_t)row1 * ldc + col + 1] = a[3];
            }
        }
    }
}

// ================= launcher =================
extern "C" void kernel_launch(void* const* d_in, const int* in_sizes, int n_in,
                              void* d_out, int out_size) {
    const int*   ids   = (const int*)  d_in[0];
    const float* embed = (const float*)d_in[1];
    const float* pos   = (const float*)d_in[2];
    const float* Wq    = (const float*)d_in[3];
    const float* Wk    = (const float*)d_in[4];
    const float* Wv    = (const float*)d_in[5];
    const float* Wo    = (const float*)d_in[6];
    const float* ln1   = (const float*)d_in[7];
    const float* ln2   = (const float*)d_in[8];
    const float* qnw   = (const float*)d_in[9];
    const float* knw   = (const float*)d_in[10];
    const float* gate  = (const float*)d_in[11];
    const float* W1    = (const float*)d_in[12];
    const float* W2    = (const float*)d_in[13];
    const float* lnf   = (const float*)d_in[14];
    const float* Wlm   = (const float*)d_in[15];
    float* out = (float*)d_out;

    float *x,*qkv,*att;
    __half *hh,*hl,*obh,*obl,*mph,*mpl;
    __half *qTh,*qTl,*kTh,*vTh,*ph,*pl;
    __half *wqkv,*wo,*w1,*w2,*wlm;
    cudaGetSymbolAddress((void**)&x,   g_x);
    cudaGetSymbolAddress((void**)&qkv, g_qkv);
    cudaGetSymbolAddress((void**)&att, g_att);
    cudaGetSymbolAddress((void**)&hh,  g_hh);
    cudaGetSymbolAddress((void**)&hl,  g_hl);
    cudaGetSymbolAddress((void**)&obh, g_obh);
    cudaGetSymbolAddress((void**)&obl, g_obl);
    cudaGetSymbolAddress((void**)&mph, g_mph);
    cudaGetSymbolAddress((void**)&mpl, g_mpl);
    cudaGetSymbolAddress((void**)&qTh, g_qTh);
    cudaGetSymbolAddress((void**)&qTl, g_qTl);
    cudaGetSymbolAddress((void**)&kTh, g_kTh);
    cudaGetSymbolAddress((void**)&vTh, g_vTh);
    cudaGetSymbolAddress((void**)&ph,  g_ph);
    cudaGetSymbolAddress((void**)&pl,  g_pl);
    cudaGetSymbolAddress((void**)&wqkv, g_wqkv);
    cudaGetSymbolAddress((void**)&wo,  g_wo);
    cudaGetSymbolAddress((void**)&w1,  g_w1);
    cudaGetSymbolAddress((void**)&w2,  g_w2);
    cudaGetSymbolAddress((void**)&wlm, g_wlm);

    const int SDENSE  = 4 * (2*64 + 128) * HG_ROWB;    // 81920
    const int S128128 = 3 * (2*128 + 128) * HG_ROWB;   // 92160
    const int S6464   = 3 * (2*64  + 64 ) * HG_ROWB;   // 46080
    cudaFuncSetAttribute(hgemmd_kernel<0>, cudaFuncAttributeMaxDynamicSharedMemorySize, SDENSE);
    cudaFuncSetAttribute(hgemmd_kernel<1>, cudaFuncAttributeMaxDynamicSharedMemorySize, SDENSE);
    cudaFuncSetAttribute(hgemmd_kernel<2>, cudaFuncAttributeMaxDynamicSharedMemorySize, SDENSE);
    cudaFuncSetAttribute(hgemm2_kernel<128,128,0,true, false>, cudaFuncAttributeMaxDynamicSharedMemorySize, S128128);
    cudaFuncSetAttribute(hgemm2_kernel<64, 64, 3,false,true >, cudaFuncAttributeMaxDynamicSharedMemorySize, S6464);

    const long long sQK = (long long)T_ * HD_;
    const long long sS  = (long long)T_ * T_;
    dim3 wb(32, 8);

    embed_kernel<<<BT_*D_/256, 256>>>(ids, embed, pos, x);
    rmsnorm_split_kernel<<<BT_, 256>>>(x, ln1, hh, hl);
    wconv3_kernel<<<dim3(D_/32, D_/32, 3*L_), wb>>>(Wq, Wk, Wv, wqkv);
    // fused QKV layer 0
    hgemmd_kernel<0><<<dim3(3072/128, BT_/64), 256, SDENSE>>>(
        hh, hl, wqkv, nullptr, qkv, nullptr, nullptr, D_, 3072, 3072);

    // remaining weight conversions
    wconv_kernel<<<dim3(D_/32, D_/32, L_), wb>>>(Wo, wo, D_, D_, (long long)D_*D_, (long long)D_*D_);
    wconv_kernel<<<dim3(F_/32, D_/32, L_), wb>>>(W1, w1, D_, F_, (long long)D_*F_, (long long)F_*D_);
    wconv_kernel<<<dim3(D_/32, F_/32, L_), wb>>>(W2, w2, F_, D_, (long long)F_*D_, (long long)D_*F_);
    wconv_kernel<<<dim3(VPAD_/32, D_/32, 1), wb>>>(Wlm, wlm, D_, V_, 0, 0);

    for (int l = 0; l < L_; l++) {
        qknorm_split_kernel<<<(B_*T_*H_)/8, 256>>>(qkv, 0,    qnw + (size_t)l*HD_, qTh, qTl);
        qknorm_split_kernel<<<(B_*T_*H_)/8, 256>>>(qkv, 1024, knw + (size_t)l*HD_, kTh, nullptr);
        vtrans_kernel<<<dim3(T_/32, HD_/32, B_*H_), dim3(32,8)>>>(qkv, vTh);

        // scores: per (b,h) Q[1024,64] @ K[1024,64]^T, causal tile-skip
        hgemm2_kernel<128,128,0,true,false><<<dim3(T_/128, T_/128, B_*H_), 256, S128128>>>(
            qTh, qTl, kTh, nullptr, att, nullptr, nullptr, HD_, T_, T_, sQK, sQK, sS);

        softmax_kernel<<<B_*H_*T_, 256>>>(att, gate + (size_t)l*H_, ph, pl);

        // PV: per (b,h) P[1024,1024] @ V^T, causal K-limit, fused vres merge+split
        hgemm2_kernel<64,64,3,false,true><<<dim3(1, T_/64, B_*H_), 256, S6464>>>(
            ph, pl, vTh, qkv, nullptr, obh, obl, T_, HD_, HD_, sS, sQK, 0);

        // Wo with fused residual into x
        hgemmd_kernel<1><<<dim3(D_/128, BT_/64), 256, SDENSE>>>(
            obh, obl, wo + (size_t)l*D_*D_, x, x, nullptr, nullptr, D_, D_, D_);

        // MLP
        rmsnorm_split_kernel<<<BT_, 256>>>(x, ln2 + (size_t)l*D_, hh, hl);
        hgemmd_kernel<2><<<dim3(F_/128, BT_/64), 256, SDENSE>>>(
            hh, hl, w1 + (size_t)l*F_*D_, nullptr, nullptr, mph, mpl, D_, F_, F_);
        hgemmd_kernel<1><<<dim3(D_/128, BT_/64), 256, SDENSE>>>(
            mph, mpl, w2 + (size_t)l*D_*F_, x, x, nullptr, nullptr, F_, D_, D_);

        // next layer's pre-attention norm + QKV
        if (l + 1 < L_) {
            rmsnorm_split_kernel<<<BT_, 256>>>(x, ln1 + (size_t)(l+1)*D_, hh, hl);
            hgemmd_kernel<0><<<dim3(3072/128, BT_/64), 256, SDENSE>>>(
                hh, hl, wqkv + (size_t)(l+1)*3072*D_, nullptr, qkv, nullptr, nullptr,
                D_, 3072, 3072);
        }
    }

    rmsnorm_split_kernel<<<BT_, 256>>>(x, lnf, hh, hl);
    hgemmd_kernel<0><<<dim3(VPAD_/128, BT_/64), 256, SDENSE>>>(
        hh, hl, wlm, nullptr, out, nullptr, nullptr, D_, V_, V_);
}

// round 11
// speedup vs baseline: 1.1191x; 1.1191x over previous
#include <cuda_runtime.h>
#include <cuda_fp16.h>
#include <math.h>
#include <stdint.h>

// Problem dims
#define L_ 12
#define B_ 2
#define T_ 1024
#define D_ 1024
#define H_ 16
#define HD_ 64
#define F_ 4096
#define V_ 50257
#define VPAD_ 50304
#define BT_ (B_*T_)

// ================= scratch (__device__ globals) =================
__device__ float g_x  [BT_*D_];
__device__ float g_qkv[BT_*3072];
__device__ float g_att[(size_t)B_*H_*T_*T_];

__device__ __align__(256) __half g_hh [BT_*D_];
__device__ __align__(256) __half g_obh[BT_*D_];
__device__ __align__(256) __half g_obl[BT_*D_];
__device__ __align__(256) __half g_mph[BT_*F_];
__device__ __align__(256) __half g_mpl[BT_*F_];

// attention operands
__device__ __align__(256) __half g_qTh[BT_*D_];
__device__ __align__(256) __half g_qTl[BT_*D_];
__device__ __align__(256) __half g_kTh[BT_*D_];          // K single fp16
__device__ __align__(256) __half g_vTh[BT_*D_];          // V single fp16, [B,H,HD,T]
__device__ __align__(256) __half g_ph [(size_t)B_*H_*T_*T_];
__device__ __align__(256) __half g_pl [(size_t)B_*H_*T_*T_];

// converted+transposed weights [N,K] layout, single fp16
__device__ __align__(256) __half g_wqkv[(size_t)L_*3072*D_];
__device__ __align__(256) __half g_wo  [(size_t)L_*D_*D_];
__device__ __align__(256) __half g_w1  [(size_t)L_*F_*D_];
__device__ __align__(256) __half g_w2  [(size_t)L_*D_*F_];
__device__ __align__(256) __half g_wlm [(size_t)VPAD_*D_];

// ================= small helpers =================
__device__ __forceinline__ uint32_t smem_u32(const void* p) {
    uint32_t a;
    asm("{ .reg .u64 t; cvta.to.shared.u64 t, %1; cvt.u32.u64 %0, t; }" : "=r"(a) : "l"(p));
    return a;
}
__device__ __forceinline__ void fp16_split(float v, __half& hi, __half& lo) {
    hi = __float2half(v);
    lo = __float2half(v - __half2float(hi));
}

// ================= elementwise / conversion kernels =================
__global__ void embed_kernel(const int* __restrict__ ids, const float* __restrict__ emb,
                             const float* __restrict__ pos, float* __restrict__ x) {
    int idx = blockIdx.x * 256 + threadIdx.x;
    int row = idx >> 10;
    int c   = idx & 1023;
    int t   = row & (T_-1);
    x[idx] = emb[(size_t)ids[row]*D_ + c] + pos[(size_t)t*D_ + c];
}

// W [K,N] fp32 -> out [Npad,K] fp16 (transposed, zero-padded), batched over z
__global__ void wconv_kernel(const float* __restrict__ W, __half* __restrict__ oh,
                             int K, int N, long long srcStride, long long dstStride) {
    __shared__ float tile[32][33];
    const float* Ws = W + (size_t)blockIdx.z * srcStride;
    __half* ohz = oh + (size_t)blockIdx.z * dstStride;
    int n0 = blockIdx.x * 32, k0 = blockIdx.y * 32;
    #pragma unroll
    for (int j = 0; j < 32; j += 8) {
        int kk = k0 + threadIdx.y + j;
        int nn = n0 + threadIdx.x;
        tile[threadIdx.y + j][threadIdx.x] = (nn < N) ? Ws[(size_t)kk*N + nn] : 0.f;
    }
    __syncthreads();
    #pragma unroll
    for (int j = 0; j < 32; j += 8) {
        int nn = n0 + threadIdx.y + j;
        int kk = k0 + threadIdx.x;
        ohz[(size_t)nn*K + kk] = __float2half(tile[threadIdx.x][threadIdx.y + j]);
    }
}

// Wq/Wk/Wv [L][K,N] fp32 -> g_wqkv [L][3072,K] fp16, z in [0, 3L)
__global__ void wconv3_kernel(const float* __restrict__ Wq, const float* __restrict__ Wk,
                              const float* __restrict__ Wv, __half* __restrict__ dst) {
    __shared__ float tile[32][33];
    int z = blockIdx.z;
    int l = z / 3, sel = z % 3;
    const float* Ws = (sel == 0 ? Wq : sel == 1 ? Wk : Wv) + (size_t)l * D_ * D_;
    __half* od = dst + ((size_t)l * 3072 + sel * D_) * D_;
    int n0 = blockIdx.x * 32, k0 = blockIdx.y * 32;
    #pragma unroll
    for (int j = 0; j < 32; j += 8) {
        tile[threadIdx.y + j][threadIdx.x] = Ws[(size_t)(k0 + threadIdx.y + j)*D_ + n0 + threadIdx.x];
    }
    __syncthreads();
    #pragma unroll
    for (int j = 0; j < 32; j += 8) {
        int nn = n0 + threadIdx.y + j;
        int kk = k0 + threadIdx.x;
        od[(size_t)nn*D_ + kk] = __float2half(tile[threadIdx.x][threadIdx.y + j]);
    }
}

// rmsnorm writing fp16 hi only (all consumers are 1-term now)
__global__ void rmsnorm_h_kernel(const float* __restrict__ x, const float* __restrict__ w,
                                 __half* __restrict__ oh) {
    __shared__ float red[256];
    int row = blockIdx.x;
    const float* xr = x + (size_t)row * D_;
    float v[4]; float ss = 0.f;
    #pragma unroll
    for (int i = 0; i < 4; i++) { v[i] = xr[threadIdx.x + 256*i]; ss += v[i]*v[i]; }
    red[threadIdx.x] = ss; __syncthreads();
    for (int s = 128; s > 0; s >>= 1) {
        if (threadIdx.x < s) red[threadIdx.x] += red[threadIdx.x + s];
        __syncthreads();
    }
    float r = rsqrtf(red[0] / (float)D_ + 1e-5f);
    #pragma unroll
    for (int i = 0; i < 4; i++) {
        int c = threadIdx.x + 256*i;
        oh[(size_t)row*D_ + c] = __float2half(w[c] * v[i] * r);
    }
}

// RMS over head_dim + transpose [B,T,3D] -> [B,H,T,HD] fp16 (lo optional). One warp per (b,t,h).
__global__ void qknorm_split_kernel(const float* __restrict__ qkv, int colOff,
                                    const float* __restrict__ w,
                                    __half* __restrict__ qh, __half* __restrict__ ql) {
    int warp = (blockIdx.x * blockDim.x + threadIdx.x) >> 5;
    int lane = threadIdx.x & 31;
    int h  = warp & (H_-1);
    int bt = warp >> 4;
    int t  = bt & (T_-1);
    int b  = bt >> 10;
    const float* src = qkv + (size_t)bt * 3072 + colOff + h * HD_;
    float x0 = src[lane], x1 = src[lane + 32];
    float ss = x0*x0 + x1*x1;
    #pragma unroll
    for (int o = 16; o > 0; o >>= 1) ss += __shfl_xor_sync(0xffffffffu, ss, o);
    float r = rsqrtf(ss / (float)HD_ + 1e-5f);
    size_t dst = ((size_t)((b*H_ + h)*T_ + t)) * HD_;
    float y0 = w[lane] * x0 * r;
    float y1 = w[lane + 32] * x1 * r;
    __half h0 = __float2half(y0);
    __half h1 = __float2half(y1);
    qh[dst + lane]      = h0;
    qh[dst + lane + 32] = h1;
    if (ql) {
        ql[dst + lane]      = __float2half(y0 - __half2float(h0));
        ql[dst + lane + 32] = __float2half(y1 - __half2float(h1));
    }
}

// V: [B,T,3D](col 2048+) -> [B,H,HD,T] single fp16 via 32x32 tile transpose
__global__ void vtrans_kernel(const float* __restrict__ qkv, __half* __restrict__ vh) {
    __shared__ float tile[32][33];
    int z = blockIdx.z;           // b*H+h
    int b = z >> 4, h = z & 15;
    int t0 = blockIdx.x * 32, d0 = blockIdx.y * 32;
    #pragma unroll
    for (int j = 0; j < 32; j += 8) {
        int t = t0 + threadIdx.y + j;
        tile[threadIdx.y + j][threadIdx.x] =
            qkv[(size_t)(b*T_ + t)*3072 + 2048 + h*HD_ + d0 + threadIdx.x];
    }
    __syncthreads();
    #pragma unroll
    for (int j = 0; j < 32; j += 8) {
        int d = d0 + threadIdx.y + j;
        size_t o = ((size_t)z * HD_ + d) * T_ + t0 + threadIdx.x;
        vh[o] = __float2half(tile[threadIdx.x][threadIdx.y + j]);
    }
}

// causal softmax, scale 1/8, per-head gate; writes P fp16 hi/lo only up to
// qlim = roundup(q+1, 64)
__global__ void softmax_kernel(const float* __restrict__ S, const float* __restrict__ gate,
                               __half* __restrict__ ph, __half* __restrict__ pl) {
    __shared__ float red[256];
    int row = blockIdx.x;
    int q = row & (T_-1);
    int h = (row >> 10) & (H_-1);
    const float* s = S + (size_t)row * T_;
    const float scale = 0.125f;
    float vals[4]; float m = -3.4e38f;
    #pragma unroll
    for (int i = 0; i < 4; i++) {
        int j = threadIdx.x + 256*i;
        float v = (j <= q) ? s[j] * scale : -3.4e38f;
        vals[i] = v; m = fmaxf(m, v);
    }
    red[threadIdx.x] = m; __syncthreads();
    for (int t = 128; t > 0; t >>= 1) {
        if (threadIdx.x < t) red[threadIdx.x] = fmaxf(red[threadIdx.x], red[threadIdx.x + t]);
        __syncthreads();
    }
    m = red[0]; __syncthreads();
    float sum = 0.f;
    #pragma unroll
    for (int i = 0; i < 4; i++) {
        int j = threadIdx.x + 256*i;
        float e = (j <= q) ? __expf(vals[i] - m) : 0.f;
        vals[i] = e; sum += e;
    }
    red[threadIdx.x] = sum; __syncthreads();
    for (int t = 128; t > 0; t >>= 1) {
        if (threadIdx.x < t) red[threadIdx.x] += red[threadIdx.x + t];
        __syncthreads();
    }
    float inv = gate[h] / red[0];
    int qlim = (q & ~63) + 64;
    #pragma unroll
    for (int i = 0; i < 4; i++) {
        int j = threadIdx.x + 256*i;
        if (j < qlim) {
            float p = vals[i] * inv;
            __half hi, lo; fp16_split(p, hi, lo);
            ph[(size_t)row*T_ + j] = hi;
            pl[(size_t)row*T_ + j] = lo;
        }
    }
}

// ================= shared HMMA building blocks =================
#define HG_ROWB 80

__device__ __forceinline__ void hg_ldm4(uint32_t addr, uint32_t* r) {
    asm volatile("ldmatrix.sync.aligned.m8n8.x4.shared.b16 {%0,%1,%2,%3}, [%4];"
        : "=r"(r[0]), "=r"(r[1]), "=r"(r[2]), "=r"(r[3]) : "r"(addr));
}
__device__ __forceinline__ void hg_mma(float* d, const uint32_t* a, uint32_t b0, uint32_t b1) {
    asm volatile("mma.sync.aligned.m16n8k16.row.col.f32.f16.f16.f32 "
        "{%0,%1,%2,%3}, {%4,%5,%6,%7}, {%8,%9}, {%0,%1,%2,%3};"
        : "+f"(d[0]), "+f"(d[1]), "+f"(d[2]), "+f"(d[3])
        : "r"(a[0]), "r"(a[1]), "r"(a[2]), "r"(a[3]), "r"(b0), "r"(b1));
}

// load TERMS*A-tiles + B-tile into one stage
template<int BM, int BN, int TERMS>
__device__ __forceinline__ void hg_load2(uint32_t stg,
    const __half* Ah, const __half* Al, const __half* Bh,
    int m0, int n0, int K, int k0, int tid)
{
    constexpr int CA = BM * 4;         // 16B chunks per A matrix
    constexpr int CB = BN * 4;
    constexpr int TOT = TERMS*CA + CB;
    #pragma unroll
    for (int p = 0; p < TOT/256; p++) {
        int c = tid + p * 256;
        const __half* base; int r0; uint32_t mo; int rr;
        if (c < CA)                          { base = Ah; r0 = m0; mo = 0;                 rr = c; }
        else if (TERMS == 2 && c < 2*CA)     { base = Al; r0 = m0; mo = BM*HG_ROWB;        rr = c - CA; }
        else                                 { base = Bh; r0 = n0; mo = TERMS*BM*HG_ROWB;  rr = c - TERMS*CA; }
        int r = rr >> 2, kc = rr & 3;
        uint32_t so = stg + mo + r * HG_ROWB + kc * 16;
        const void* ga = (const void*)(base + (size_t)(r0 + r) * K + k0 + kc * 8);
        asm volatile("cp.async.cg.shared.global [%0], [%1], 16;\n" :: "r"(so), "l"(ga));
    }
    asm volatile("cp.async.commit_group;\n" ::: "memory");
}

// ======== dense GEMM: 64x128 tile, pair double-buffer, TERMS A-side terms ========
// C[M,N] = (Ah[+Al])[M,K] @ Bh[N,K]^T.  MODE: 0=plain(guard Nout), 1=+RES, 2=GELU->split
template<int MODE, int TERMS>
__global__ __launch_bounds__(256, 2)
void hgemmd_kernel(const __half* __restrict__ Ah, const __half* __restrict__ Al,
                   const __half* __restrict__ Bh,
                   const float* __restrict__ AUX, float* __restrict__ C,
                   __half* __restrict__ Gh, __half* __restrict__ Gl,
                   int K, int Nout, int ldc)
{
    constexpr int BM = 64, BN = 128;
    constexpr int MATA  = BM * HG_ROWB;
    constexpr int STAGE = (TERMS*BM + BN) * HG_ROWB;
    constexpr int NJ = 8, NT = 4;

    extern __shared__ char dsm[];
    uint32_t sb = smem_u32(dsm);

    const int tid  = threadIdx.x;
    const int lane = tid & 31;
    const int wid  = tid >> 5;
    const int warpM = (wid & 3) * 16;
    const int warpN = (wid >> 2) * 64;

    const int m0 = blockIdx.y * BM;
    const int n0 = blockIdx.x * BN;

    const uint32_t aoff = (uint32_t)((lane & 15) * HG_ROWB + (lane >> 4) * 16);
    const uint32_t boff = (uint32_t)(((lane & 7) + ((lane >> 4) & 1) * 8) * HG_ROWB
                                     + ((lane >> 3) & 1) * 16);

    float acc[NJ][4];
    #pragma unroll
    for (int j = 0; j < NJ; j++)
        #pragma unroll
        for (int u = 0; u < 4; u++) acc[j][u] = 0.f;

    const int nk = K / 32;          // even, >= 4
    const int np = nk / 2;

    hg_load2<BM,BN,TERMS>(sb,          Ah, Al, Bh, m0, n0, K, 0,  tid);
    hg_load2<BM,BN,TERMS>(sb + STAGE,  Ah, Al, Bh, m0, n0, K, 32, tid);

    for (int ip = 0; ip < np; ip++) {
        int c0 = 2 * ip;
        asm volatile("cp.async.wait_group 0;\n" ::: "memory");
        __syncthreads();
        if (c0 + 2 < nk) {
            hg_load2<BM,BN,TERMS>(sb + ((c0 + 2) & 3) * STAGE, Ah, Al, Bh, m0, n0, K, (c0 + 2) * 32, tid);
            hg_load2<BM,BN,TERMS>(sb + ((c0 + 3) & 3) * STAGE, Ah, Al, Bh, m0, n0, K, (c0 + 3) * 32, tid);
        }

        #pragma unroll
        for (int half = 0; half < 2; half++) {
            uint32_t st  = sb + ((c0 + half) & 3) * STAGE;
            uint32_t sAh = st;
            uint32_t sAl = st + MATA;
            uint32_t sBh = st + TERMS*MATA;
            #pragma unroll
            for (int kq = 0; kq < 2; kq++) {
                uint32_t kb = kq * 32;
                uint32_t ah[4], al[4], bh[NT][4];
                uint32_t rb = (uint32_t)(warpM * HG_ROWB) + kb;
                hg_ldm4(sAh + rb + aoff, ah);
                if (TERMS == 2) hg_ldm4(sAl + rb + aoff, al);
                #pragma unroll
                for (int nt = 0; nt < NT; nt++) {
                    uint32_t rbn = (uint32_t)((warpN + nt * 16) * HG_ROWB) + kb;
                    hg_ldm4(sBh + rbn + boff, bh[nt]);
                }
                #pragma unroll
                for (int nj = 0; nj < NJ; nj++) {
                    uint32_t b0 = bh[nj >> 1][(nj & 1) * 2];
                    uint32_t b1 = bh[nj >> 1][(nj & 1) * 2 + 1];
                    hg_mma(acc[nj], ah, b0, b1);
                    if (TERMS == 2) hg_mma(acc[nj], al, b0, b1);
                }
            }
        }
    }

    // epilogue
    const int g = lane >> 2;
    const int tq = lane & 3;
    int row0 = m0 + warpM + g;
    int row1 = row0 + 8;
    #pragma unroll
    for (int nj = 0; nj < NJ; nj++) {
        int col = n0 + warpN + nj * 8 + tq * 2;
        float* a = acc[nj];
        if (MODE == 1) {
            size_t o0 = (size_t)row0 * ldc + col;
            size_t o1 = (size_t)row1 * ldc + col;
            C[o0]     = a[0] + AUX[o0];
            C[o0 + 1] = a[1] + AUX[o0 + 1];
            C[o1]     = a[2] + AUX[o1];
            C[o1 + 1] = a[3] + AUX[o1 + 1];
        } else if (MODE == 2) {
            #pragma unroll
            for (int half = 0; half < 2; half++) {
                int r = half ? row1 : row0;
                float v0 = a[half * 2], v1 = a[half * 2 + 1];
                float g0 = 0.5f * v0 * (1.0f + erff(v0 * 0.70710678118654752f));
                float g1 = 0.5f * v1 * (1.0f + erff(v1 * 0.70710678118654752f));
                __half h0, l0, h1, l1;
                fp16_split(g0, h0, l0); fp16_split(g1, h1, l1);
                __half2 hp; hp.x = h0; hp.y = h1;
                __half2 lp; lp.x = l0; lp.y = l1;
                size_t o = (size_t)r * ldc + col;
                *(__half2*)&Gh[o] = hp;
                *(__half2*)&Gl[o] = lp;
            }
        } else {
            if (col < Nout) {
                C[(size_t)row0 * ldc + col] = a[0];
                C[(size_t)row1 * ldc + col] = a[2];
            }
            if (col + 1 < Nout) {
                C[(size_t)row0 * ldc + col + 1] = a[1];
                C[(size_t)row1 * ldc + col + 1] = a[3];
            }
        }
    }
}

// ======== attention GEMM (scores / PV): 3-stage, batched (unchanged, proven) ========
// MODE: 0 = fp32 store, 3 = PV merge->fp16 split
template<int BM, int BN, int MODE, bool CSKIP, bool CKLIM>
__global__ __launch_bounds__(256, 2)
void hgemm2_kernel(const __half* __restrict__ Ah, const __half* __restrict__ Al,
                   const __half* __restrict__ Bh,
                   const float* __restrict__ AUX, float* __restrict__ C,
                   __half* __restrict__ Gh, __half* __restrict__ Gl,
                   int K, int Nout, int ldc,
                   long long sA, long long sB, long long sC)
{
    constexpr int MATA  = BM * HG_ROWB;
    constexpr int STAGE = (2*BM + BN) * HG_ROWB;
    constexpr int MI = BM / 64;
    constexpr int NJ = BN / 16;
    constexpr int NT = BN / 32;

    extern __shared__ char dsm[];
    uint32_t sb = smem_u32(dsm);

    const int tid  = threadIdx.x;
    const int lane = tid & 31;
    const int wid  = tid >> 5;
    const int warpM = (wid & 3) * (BM/4);
    const int warpN = (wid >> 2) * (BN/2);

    const int m0 = blockIdx.y * BM;
    const int n0 = blockIdx.x * BN;
    if (CSKIP && n0 > m0 + BM - 1) return;

    const int z = blockIdx.z;
    Ah += (size_t)z * sA; Al += (size_t)z * sA;
    Bh += (size_t)z * sB;
    if (MODE == 0) C += (size_t)z * sC;

    const uint32_t aoff = (uint32_t)((lane & 15) * HG_ROWB + (lane >> 4) * 16);
    const uint32_t boff = (uint32_t)(((lane & 7) + ((lane >> 4) & 1) * 8) * HG_ROWB
                                     + ((lane >> 3) & 1) * 16);

    float acc[MI][NJ][4];
    #pragma unroll
    for (int i = 0; i < MI; i++)
        #pragma unroll
        for (int j = 0; j < NJ; j++)
            #pragma unroll
            for (int u = 0; u < 4; u++) acc[i][j][u] = 0.f;

    const int kend = CKLIM ? (K < m0 + BM ? K : m0 + BM) : K;
    const int nk = kend / 32;

    hg_load2<BM,BN,2>(sb,          Ah, Al, Bh, m0, n0, K, 0,  tid);
    if (nk > 1)
        hg_load2<BM,BN,2>(sb + STAGE, Ah, Al, Bh, m0, n0, K, 32, tid);

    for (int it = 0; it < nk; it++) {
        int s = it % 3;
        if (it + 1 < nk) {
            asm volatile("cp.async.wait_group 1;\n" ::: "memory");
        } else {
            asm volatile("cp.async.wait_group 0;\n" ::: "memory");
        }
        __syncthreads();
        if (it + 2 < nk) {
            hg_load2<BM,BN,2>(sb + ((it + 2) % 3) * STAGE, Ah, Al, Bh, m0, n0, K, (it + 2) * 32, tid);
        }

        uint32_t st  = sb + s * STAGE;
        uint32_t sAh = st;
        uint32_t sAl = st + MATA;
        uint32_t sBh = st + 2*MATA;

        #pragma unroll
        for (int kq = 0; kq < 2; kq++) {
            uint32_t kb = kq * 32;
            uint32_t ah[MI][4], al[MI][4], bh[NT][4];
            #pragma unroll
            for (int mi = 0; mi < MI; mi++) {
                uint32_t rb = (uint32_t)((warpM + mi * 16) * HG_ROWB) + kb;
                hg_ldm4(sAh + rb + aoff, ah[mi]);
                hg_ldm4(sAl + rb + aoff, al[mi]);
            }
            #pragma unroll
            for (int nt = 0; nt < NT; nt++) {
                uint32_t rb = (uint32_t)((warpN + nt * 16) * HG_ROWB) + kb;
                hg_ldm4(sBh + rb + boff, bh[nt]);
            }
            #pragma unroll
            for (int mi = 0; mi < MI; mi++) {
                #pragma unroll
                for (int nj = 0; nj < NJ; nj++) {
                    uint32_t b0 = bh[nj >> 1][(nj & 1) * 2];
                    uint32_t b1 = bh[nj >> 1][(nj & 1) * 2 + 1];
                    hg_mma(acc[mi][nj], ah[mi], b0, b1);
                    hg_mma(acc[mi][nj], al[mi], b0, b1);
                }
            }
        }
    }

    const int g = lane >> 2;
    const int tq = lane & 3;
    #pragma unroll
    for (int mi = 0; mi < MI; mi++) {
        int row0 = m0 + warpM + mi * 16 + g;
        int row1 = row0 + 8;
        #pragma unroll
        for (int nj = 0; nj < NJ; nj++) {
            int col = n0 + warpN + nj * 8 + tq * 2;
            float* a = acc[mi][nj];
            if (MODE == 3) {
                int b  = z >> 4, h = z & 15;
                #pragma unroll
                for (int half = 0; half < 2; half++) {
                    int q = half ? row1 : row0;
                    size_t vsrc = (size_t)(b*T_ + q)*3072 + 2048 + h*HD_ + col;
                    float v0 = a[half * 2]     + AUX[vsrc];
                    float v1 = a[half * 2 + 1] + AUX[vsrc + 1];
                    __half h0, l0, h1, l1;
                    fp16_split(v0, h0, l0); fp16_split(v1, h1, l1);
                    __half2 hp; hp.x = h0; hp.y = h1;
                    __half2 lp; lp.x = l0; lp.y = l1;
                    size_t o = (size_t)(b*T_ + q)*D_ + h*HD_ + col;
                    *(__half2*)&Gh[o] = hp;
                    *(__half2*)&Gl[o] = lp;
                }
            } else {
                C[(size_t)row0 * ldc + col] = a[0];
                C[(size_t)row0 * ldc + col + 1] = a[1];
                C[(size_t)row1 * ldc + col] = a[2];
                C[(size_t)row1 * ldc + col + 1] = a[3];
            }
        }
    }
}

// ================= launcher =================
extern "C" void kernel_launch(void* const* d_in, const int* in_sizes, int n_in,
                              void* d_out, int out_size) {
    const int*   ids   = (const int*)  d_in[0];
    const float* embed = (const float*)d_in[1];
    const float* pos   = (const float*)d_in[2];
    const float* Wq    = (const float*)d_in[3];
    const float* Wk    = (const float*)d_in[4];
    const float* Wv    = (const float*)d_in[5];
    const float* Wo    = (const float*)d_in[6];
    const float* ln1   = (const float*)d_in[7];
    const float* ln2   = (const float*)d_in[8];
    const float* qnw   = (const float*)d_in[9];
    const float* knw   = (const float*)d_in[10];
    const float* gate  = (const float*)d_in[11];
    const float* W1    = (const float*)d_in[12];
    const float* W2    = (const float*)d_in[13];
    const float* lnf   = (const float*)d_in[14];
    const float* Wlm   = (const float*)d_in[15];
    float* out = (float*)d_out;

    float *x,*qkv,*att;
    __half *hh,*obh,*obl,*mph,*mpl;
    __half *qTh,*qTl,*kTh,*vTh,*ph,*pl;
    __half *wqkv,*wo,*w1,*w2,*wlm;
    cudaGetSymbolAddress((void**)&x,   g_x);
    cudaGetSymbolAddress((void**)&qkv, g_qkv);
    cudaGetSymbolAddress((void**)&att, g_att);
    cudaGetSymbolAddress((void**)&hh,  g_hh);
    cudaGetSymbolAddress((void**)&obh, g_obh);
    cudaGetSymbolAddress((void**)&obl, g_obl);
    cudaGetSymbolAddress((void**)&mph, g_mph);
    cudaGetSymbolAddress((void**)&mpl, g_mpl);
    cudaGetSymbolAddress((void**)&qTh, g_qTh);
    cudaGetSymbolAddress((void**)&qTl, g_qTl);
    cudaGetSymbolAddress((void**)&kTh, g_kTh);
    cudaGetSymbolAddress((void**)&vTh, g_vTh);
    cudaGetSymbolAddress((void**)&ph,  g_ph);
    cudaGetSymbolAddress((void**)&pl,  g_pl);
    cudaGetSymbolAddress((void**)&wqkv, g_wqkv);
    cudaGetSymbolAddress((void**)&wo,  g_wo);
    cudaGetSymbolAddress((void**)&w1,  g_w1);
    cudaGetSymbolAddress((void**)&w2,  g_w2);
    cudaGetSymbolAddress((void**)&wlm, g_wlm);

    const int SD1 = 4 * (1*64 + 128) * HG_ROWB;        // 61440 (1-term)
    const int SD2 = 4 * (2*64 + 128) * HG_ROWB;        // 81920 (2-term)
    const int S128128 = 3 * (2*128 + 128) * HG_ROWB;   // 92160
    const int S6464   = 3 * (2*64  + 64 ) * HG_ROWB;   // 46080
    cudaFuncSetAttribute(hgemmd_kernel<0,1>, cudaFuncAttributeMaxDynamicSharedMemorySize, SD1);
    cudaFuncSetAttribute(hgemmd_kernel<2,1>, cudaFuncAttributeMaxDynamicSharedMemorySize, SD1);
    cudaFuncSetAttribute(hgemmd_kernel<1,2>, cudaFuncAttributeMaxDynamicSharedMemorySize, SD2);
    cudaFuncSetAttribute(hgemm2_kernel<128,128,0,true, false>, cudaFuncAttributeMaxDynamicSharedMemorySize, S128128);
    cudaFuncSetAttribute(hgemm2_kernel<64, 64, 3,false,true >, cudaFuncAttributeMaxDynamicSharedMemorySize, S6464);

    const long long sQK = (long long)T_ * HD_;
    const long long sS  = (long long)T_ * T_;
    dim3 wb(32, 8);

    embed_kernel<<<BT_*D_/256, 256>>>(ids, embed, pos, x);
    rmsnorm_h_kernel<<<BT_, 256>>>(x, ln1, hh);
    wconv3_kernel<<<dim3(D_/32, D_/32, 3*L_), wb>>>(Wq, Wk, Wv, wqkv);
    // fused QKV layer 0 (1-term)
    hgemmd_kernel<0,1><<<dim3(3072/128, BT_/64), 256, SD1>>>(
        hh, nullptr, wqkv, nullptr, qkv, nullptr, nullptr, D_, 3072, 3072);

    // remaining weight conversions
    wconv_kernel<<<dim3(D_/32, D_/32, L_), wb>>>(Wo, wo, D_, D_, (long long)D_*D_, (long long)D_*D_);
    wconv_kernel<<<dim3(F_/32, D_/32, L_), wb>>>(W1, w1, D_, F_, (long long)D_*F_, (long long)F_*D_);
    wconv_kernel<<<dim3(D_/32, F_/32, L_), wb>>>(W2, w2, F_, D_, (long long)F_*D_, (long long)D_*F_);
    wconv_kernel<<<dim3(VPAD_/32, D_/32, 1), wb>>>(Wlm, wlm, D_, V_, 0, 0);

    for (int l = 0; l < L_; l++) {
        qknorm_split_kernel<<<(B_*T_*H_)/8, 256>>>(qkv, 0,    qnw + (size_t)l*HD_, qTh, qTl);
        qknorm_split_kernel<<<(B_*T_*H_)/8, 256>>>(qkv, 1024, knw + (size_t)l*HD_, kTh, nullptr);
        vtrans_kernel<<<dim3(T_/32, HD_/32, B_*H_), dim3(32,8)>>>(qkv, vTh);

        // scores: per (b,h) Q[1024,64] @ K[1024,64]^T, causal tile-skip (2-term A)
        hgemm2_kernel<128,128,0,true,false><<<dim3(T_/128, T_/128, B_*H_), 256, S128128>>>(
            qTh, qTl, kTh, nullptr, att, nullptr, nullptr, HD_, T_, T_, sQK, sQK, sS);

        softmax_kernel<<<B_*H_*T_, 256>>>(att, gate + (size_t)l*H_, ph, pl);

        // PV: per (b,h) P[1024,1024] @ V^T, causal K-limit, fused vres merge+split (2-term)
        hgemm2_kernel<64,64,3,false,true><<<dim3(1, T_/64, B_*H_), 256, S6464>>>(
            ph, pl, vTh, qkv, nullptr, obh, obl, T_, HD_, HD_, sS, sQK, 0);

        // Wo with fused residual into x (2-term: residual-stream writer)
        hgemmd_kernel<1,2><<<dim3(D_/128, BT_/64), 256, SD2>>>(
            obh, obl, wo + (size_t)l*D_*D_, x, x, nullptr, nullptr, D_, D_, D_);

        // MLP: W1 1-term, W2 2-term
        rmsnorm_h_kernel<<<BT_, 256>>>(x, ln2 + (size_t)l*D_, hh);
        hgemmd_kernel<2,1><<<dim3(F_/128, BT_/64), 256, SD1>>>(
            hh, nullptr, w1 + (size_t)l*F_*D_, nullptr, nullptr, mph, mpl, D_, F_, F_);
        hgemmd_kernel<1,2><<<dim3(D_/128, BT_/64), 256, SD2>>>(
            mph, mpl, w2 + (size_t)l*D_*F_, x, x, nullptr, nullptr, F_, D_, D_);

        // next layer's pre-attention norm + QKV (1-term)
        if (l + 1 < L_) {
            rmsnorm_h_kernel<<<BT_, 256>>>(x, ln1 + (size_t)(l+1)*D_, hh);
            hgemmd_kernel<0,1><<<dim3(3072/128, BT_/64), 256, SD1>>>(
                hh, nullptr, wqkv + (size_t)(l+1)*3072*D_, nullptr, qkv, nullptr, nullptr,
                D_, 3072, 3072);
        }
    }

    rmsnorm_h_kernel<<<BT_, 256>>>(x, lnf, hh);
    // LM head (1-term)
    hgemmd_kernel<0,1><<<dim3(VPAD_/128, BT_/64), 256, SD1>>>(
        hh, nullptr, wlm, nullptr, out, nullptr, nullptr, D_, V_, V_);
}

// round 12
// speedup vs baseline: 1.2322x; 1.1010x over previous
#include <cuda_runtime.h>
#include <cuda_fp16.h>
#include <math.h>
#include <stdint.h>

// Problem dims
#define L_ 12
#define B_ 2
#define T_ 1024
#define D_ 1024
#define H_ 16
#define HD_ 64
#define F_ 4096
#define V_ 50257
#define VPAD_ 50304
#define BT_ (B_*T_)

// ================= scratch (__device__ globals) =================
__device__ float g_x  [BT_*D_];
__device__ float g_qkv[BT_*3072];
__device__ float g_att[(size_t)B_*H_*T_*T_];

__device__ __align__(256) __half g_hh [BT_*D_];
__device__ __align__(256) __half g_obh[BT_*D_];
__device__ __align__(256) __half g_obl[BT_*D_];
__device__ __align__(256) __half g_mph[BT_*F_];
__device__ __align__(256) __half g_mpl[BT_*F_];

// attention operands
__device__ __align__(256) __half g_qTh[BT_*D_];
__device__ __align__(256) __half g_qTl[BT_*D_];
__device__ __align__(256) __half g_kTh[BT_*D_];          // K single fp16
__device__ __align__(256) __half g_vTh[BT_*D_];          // V single fp16, [B,H,HD,T]
__device__ __align__(256) __half g_ph [(size_t)B_*H_*T_*T_];
__device__ __align__(256) __half g_pl [(size_t)B_*H_*T_*T_];

// converted+transposed weights [N,K] layout, single fp16
__device__ __align__(256) __half g_wqkv[(size_t)L_*3072*D_];
__device__ __align__(256) __half g_wo  [(size_t)L_*D_*D_];
__device__ __align__(256) __half g_w1  [(size_t)L_*F_*D_];
__device__ __align__(256) __half g_w2  [(size_t)L_*D_*F_];
__device__ __align__(256) __half g_wlm [(size_t)VPAD_*D_];

// ================= small helpers =================
__device__ __forceinline__ uint32_t smem_u32(const void* p) {
    uint32_t a;
    asm("{ .reg .u64 t; cvta.to.shared.u64 t, %1; cvt.u32.u64 %0, t; }" : "=r"(a) : "l"(p));
    return a;
}
__device__ __forceinline__ void fp16_split(float v, __half& hi, __half& lo) {
    hi = __float2half(v);
    lo = __float2half(v - __half2float(hi));
}

// ================= elementwise / conversion kernels =================
__global__ void embed_kernel(const int* __restrict__ ids, const float* __restrict__ emb,
                             const float* __restrict__ pos, float* __restrict__ x) {
    int idx = blockIdx.x * 256 + threadIdx.x;
    int row = idx >> 10;
    int c   = idx & 1023;
    int t   = row & (T_-1);
    x[idx] = emb[(size_t)ids[row]*D_ + c] + pos[(size_t)t*D_ + c];
}

// W [K,N] fp32 -> out [Npad,K] fp16 (transposed, zero-padded), batched over z
__global__ void wconv_kernel(const float* __restrict__ W, __half* __restrict__ oh,
                             int K, int N, long long srcStride, long long dstStride) {
    __shared__ float tile[32][33];
    const float* Ws = W + (size_t)blockIdx.z * srcStride;
    __half* ohz = oh + (size_t)blockIdx.z * dstStride;
    int n0 = blockIdx.x * 32, k0 = blockIdx.y * 32;
    #pragma unroll
    for (int j = 0; j < 32; j += 8) {
        int kk = k0 + threadIdx.y + j;
        int nn = n0 + threadIdx.x;
        tile[threadIdx.y + j][threadIdx.x] = (nn < N) ? Ws[(size_t)kk*N + nn] : 0.f;
    }
    __syncthreads();
    #pragma unroll
    for (int j = 0; j < 32; j += 8) {
        int nn = n0 + threadIdx.y + j;
        int kk = k0 + threadIdx.x;
        ohz[(size_t)nn*K + kk] = __float2half(tile[threadIdx.x][threadIdx.y + j]);
    }
}

// Wq/Wk/Wv [L][K,N] fp32 -> g_wqkv [L][3072,K] fp16, z in [0, 3L)
__global__ void wconv3_kernel(const float* __restrict__ Wq, const float* __restrict__ Wk,
                              const float* __restrict__ Wv, __half* __restrict__ dst) {
    __shared__ float tile[32][33];
    int z = blockIdx.z;
    int l = z / 3, sel = z % 3;
    const float* Ws = (sel == 0 ? Wq : sel == 1 ? Wk : Wv) + (size_t)l * D_ * D_;
    __half* od = dst + ((size_t)l * 3072 + sel * D_) * D_;
    int n0 = blockIdx.x * 32, k0 = blockIdx.y * 32;
    #pragma unroll
    for (int j = 0; j < 32; j += 8) {
        tile[threadIdx.y + j][threadIdx.x] = Ws[(size_t)(k0 + threadIdx.y + j)*D_ + n0 + threadIdx.x];
    }
    __syncthreads();
    #pragma unroll
    for (int j = 0; j < 32; j += 8) {
        int nn = n0 + threadIdx.y + j;
        int kk = k0 + threadIdx.x;
        od[(size_t)nn*D_ + kk] = __float2half(tile[threadIdx.x][threadIdx.y + j]);
    }
}

// rmsnorm writing fp16 hi only
__global__ void rmsnorm_h_kernel(const float* __restrict__ x, const float* __restrict__ w,
                                 __half* __restrict__ oh) {
    __shared__ float red[256];
    int row = blockIdx.x;
    const float* xr = x + (size_t)row * D_;
    float v[4]; float ss = 0.f;
    #pragma unroll
    for (int i = 0; i < 4; i++) { v[i] = xr[threadIdx.x + 256*i]; ss += v[i]*v[i]; }
    red[threadIdx.x] = ss; __syncthreads();
    for (int s = 128; s > 0; s >>= 1) {
        if (threadIdx.x < s) red[threadIdx.x] += red[threadIdx.x + s];
        __syncthreads();
    }
    float r = rsqrtf(red[0] / (float)D_ + 1e-5f);
    #pragma unroll
    for (int i = 0; i < 4; i++) {
        int c = threadIdx.x + 256*i;
        oh[(size_t)row*D_ + c] = __float2half(w[c] * v[i] * r);
    }
}

// RMS over head_dim + transpose [B,T,3D] -> [B,H,T,HD] fp16 (lo optional). One warp per (b,t,h).
__global__ void qknorm_split_kernel(const float* __restrict__ qkv, int colOff,
                                    const float* __restrict__ w,
                                    __half* __restrict__ qh, __half* __restrict__ ql) {
    int warp = (blockIdx.x * blockDim.x + threadIdx.x) >> 5;
    int lane = threadIdx.x & 31;
    int h  = warp & (H_-1);
    int bt = warp >> 4;
    int t  = bt & (T_-1);
    int b  = bt >> 10;
    const float* src = qkv + (size_t)bt * 3072 + colOff + h * HD_;
    float x0 = src[lane], x1 = src[lane + 32];
    float ss = x0*x0 + x1*x1;
    #pragma unroll
    for (int o = 16; o > 0; o >>= 1) ss += __shfl_xor_sync(0xffffffffu, ss, o);
    float r = rsqrtf(ss / (float)HD_ + 1e-5f);
    size_t dst = ((size_t)((b*H_ + h)*T_ + t)) * HD_;
    float y0 = w[lane] * x0 * r;
    float y1 = w[lane + 32] * x1 * r;
    __half h0 = __float2half(y0);
    __half h1 = __float2half(y1);
    qh[dst + lane]      = h0;
    qh[dst + lane + 32] = h1;
    if (ql) {
        ql[dst + lane]      = __float2half(y0 - __half2float(h0));
        ql[dst + lane + 32] = __float2half(y1 - __half2float(h1));
    }
}

// V: [B,T,3D](col 2048+) -> [B,H,HD,T] single fp16 via 32x32 tile transpose
__global__ void vtrans_kernel(const float* __restrict__ qkv, __half* __restrict__ vh) {
    __shared__ float tile[32][33];
    int z = blockIdx.z;           // b*H+h
    int b = z >> 4, h = z & 15;
    int t0 = blockIdx.x * 32, d0 = blockIdx.y * 32;
    #pragma unroll
    for (int j = 0; j < 32; j += 8) {
        int t = t0 + threadIdx.y + j;
        tile[threadIdx.y + j][threadIdx.x] =
            qkv[(size_t)(b*T_ + t)*3072 + 2048 + h*HD_ + d0 + threadIdx.x];
    }
    __syncthreads();
    #pragma unroll
    for (int j = 0; j < 32; j += 8) {
        int d = d0 + threadIdx.y + j;
        size_t o = ((size_t)z * HD_ + d) * T_ + t0 + threadIdx.x;
        vh[o] = __float2half(tile[threadIdx.x][threadIdx.y + j]);
    }
}

// causal softmax, scale 1/8, per-head gate; writes P fp16 hi/lo up to qlim
__global__ void softmax_kernel(const float* __restrict__ S, const float* __restrict__ gate,
                               __half* __restrict__ ph, __half* __restrict__ pl) {
    __shared__ float red[256];
    int row = blockIdx.x;
    int q = row & (T_-1);
    int h = (row >> 10) & (H_-1);
    const float* s = S + (size_t)row * T_;
    const float scale = 0.125f;
    float vals[4]; float m = -3.4e38f;
    #pragma unroll
    for (int i = 0; i < 4; i++) {
        int j = threadIdx.x + 256*i;
        float v = (j <= q) ? s[j] * scale : -3.4e38f;
        vals[i] = v; m = fmaxf(m, v);
    }
    red[threadIdx.x] = m; __syncthreads();
    for (int t = 128; t > 0; t >>= 1) {
        if (threadIdx.x < t) red[threadIdx.x] = fmaxf(red[threadIdx.x], red[threadIdx.x + t]);
        __syncthreads();
    }
    m = red[0]; __syncthreads();
    float sum = 0.f;
    #pragma unroll
    for (int i = 0; i < 4; i++) {
        int j = threadIdx.x + 256*i;
        float e = (j <= q) ? __expf(vals[i] - m) : 0.f;
        vals[i] = e; sum += e;
    }
    red[threadIdx.x] = sum; __syncthreads();
    for (int t = 128; t > 0; t >>= 1) {
        if (threadIdx.x < t) red[threadIdx.x] += red[threadIdx.x + t];
        __syncthreads();
    }
    float inv = gate[h] / red[0];
    int qlim = (q & ~63) + 64;
    #pragma unroll
    for (int i = 0; i < 4; i++) {
        int j = threadIdx.x + 256*i;
        if (j < qlim) {
            float p = vals[i] * inv;
            __half hi, lo; fp16_split(p, hi, lo);
            ph[(size_t)row*T_ + j] = hi;
            pl[(size_t)row*T_ + j] = lo;
        }
    }
}

// ================= shared HMMA building blocks =================
#define HG_ROWB 80

__device__ __forceinline__ void hg_ldm4(uint32_t addr, uint32_t* r) {
    asm volatile("ldmatrix.sync.aligned.m8n8.x4.shared.b16 {%0,%1,%2,%3}, [%4];"
        : "=r"(r[0]), "=r"(r[1]), "=r"(r[2]), "=r"(r[3]) : "r"(addr));
}
__device__ __forceinline__ void hg_mma(float* d, const uint32_t* a, uint32_t b0, uint32_t b1) {
    asm volatile("mma.sync.aligned.m16n8k16.row.col.f32.f16.f16.f32 "
        "{%0,%1,%2,%3}, {%4,%5,%6,%7}, {%8,%9}, {%0,%1,%2,%3};"
        : "+f"(d[0]), "+f"(d[1]), "+f"(d[2]), "+f"(d[3])
        : "r"(a[0]), "r"(a[1]), "r"(a[2]), "r"(a[3]), "r"(b0), "r"(b1));
}

// load TERMS*A-tiles + B-tile into one stage
template<int BM, int BN, int TERMS>
__device__ __forceinline__ void hg_load2(uint32_t stg,
    const __half* Ah, const __half* Al, const __half* Bh,
    int m0, int n0, int K, int k0, int tid)
{
    constexpr int CA = BM * 4;         // 16B chunks per A matrix
    constexpr int CB = BN * 4;
    constexpr int TOT = TERMS*CA + CB;
    #pragma unroll
    for (int p = 0; p < TOT/256; p++) {
        int c = tid + p * 256;
        const __half* base; int r0; uint32_t mo; int rr;
        if (c < CA)                          { base = Ah; r0 = m0; mo = 0;                 rr = c; }
        else if (TERMS == 2 && c < 2*CA)     { base = Al; r0 = m0; mo = BM*HG_ROWB;        rr = c - CA; }
        else                                 { base = Bh; r0 = n0; mo = TERMS*BM*HG_ROWB;  rr = c - TERMS*CA; }
        int r = rr >> 2, kc = rr & 3;
        uint32_t so = stg + mo + r * HG_ROWB + kc * 16;
        const void* ga = (const void*)(base + (size_t)(r0 + r) * K + k0 + kc * 8);
        asm volatile("cp.async.cg.shared.global [%0], [%1], 16;\n" :: "r"(so), "l"(ga));
    }
    asm volatile("cp.async.commit_group;\n" ::: "memory");
}

// ======== dense GEMM: BMx128 tile, pair double-buffer, TERMS A-side terms ========
// C[M,N] = (Ah[+Al])[M,K] @ Bh[N,K]^T.  MODE: 0=plain(guard Nout), 1=+RES, 2=GELU->split
template<int MODE, int TERMS, int BM>
__global__ __launch_bounds__(256, 2)
void hgemmd_kernel(const __half* __restrict__ Ah, const __half* __restrict__ Al,
                   const __half* __restrict__ Bh,
                   const float* __restrict__ AUX, float* __restrict__ C,
                   __half* __restrict__ Gh, __half* __restrict__ Gl,
                   int K, int Nout, int ldc)
{
    constexpr int BN = 128;
    constexpr int MATA  = BM * HG_ROWB;
    constexpr int STAGE = (TERMS*BM + BN) * HG_ROWB;
    constexpr int MI = BM / 64;        // 16-row A tiles per warp
    constexpr int NJ = 8, NT = 4;

    extern __shared__ char dsm[];
    uint32_t sb = smem_u32(dsm);

    const int tid  = threadIdx.x;
    const int lane = tid & 31;
    const int wid  = tid >> 5;
    const int warpM = (wid & 3) * (BM/4);
    const int warpN = (wid >> 2) * 64;

    const int m0 = blockIdx.y * BM;
    const int n0 = blockIdx.x * BN;

    const uint32_t aoff = (uint32_t)((lane & 15) * HG_ROWB + (lane >> 4) * 16);
    const uint32_t boff = (uint32_t)(((lane & 7) + ((lane >> 4) & 1) * 8) * HG_ROWB
                                     + ((lane >> 3) & 1) * 16);

    float acc[MI][NJ][4];
    #pragma unroll
    for (int i = 0; i < MI; i++)
        #pragma unroll
        for (int j = 0; j < NJ; j++)
            #pragma unroll
            for (int u = 0; u < 4; u++) acc[i][j][u] = 0.f;

    const int nk = K / 32;          // even, >= 4
    const int np = nk / 2;

    hg_load2<BM,BN,TERMS>(sb,          Ah, Al, Bh, m0, n0, K, 0,  tid);
    hg_load2<BM,BN,TERMS>(sb + STAGE,  Ah, Al, Bh, m0, n0, K, 32, tid);

    for (int ip = 0; ip < np; ip++) {
        int c0 = 2 * ip;
        asm volatile("cp.async.wait_group 0;\n" ::: "memory");
        __syncthreads();
        if (c0 + 2 < nk) {
            hg_load2<BM,BN,TERMS>(sb + ((c0 + 2) & 3) * STAGE, Ah, Al, Bh, m0, n0, K, (c0 + 2) * 32, tid);
            hg_load2<BM,BN,TERMS>(sb + ((c0 + 3) & 3) * STAGE, Ah, Al, Bh, m0, n0, K, (c0 + 3) * 32, tid);
        }

        #pragma unroll
        for (int half = 0; half < 2; half++) {
            uint32_t st  = sb + ((c0 + half) & 3) * STAGE;
            uint32_t sAh = st;
            uint32_t sAl = st + MATA;
            uint32_t sBh = st + TERMS*MATA;
            #pragma unroll
            for (int kq = 0; kq < 2; kq++) {
                uint32_t kb = kq * 32;
                uint32_t ah[MI][4], al[MI][4], bh[NT][4];
                #pragma unroll
                for (int mi = 0; mi < MI; mi++) {
                    uint32_t rb = (uint32_t)((warpM + mi * 16) * HG_ROWB) + kb;
                    hg_ldm4(sAh + rb + aoff, ah[mi]);
                    if (TERMS == 2) hg_ldm4(sAl + rb + aoff, al[mi]);
                }
                #pragma unroll
                for (int nt = 0; nt < NT; nt++) {
                    uint32_t rbn = (uint32_t)((warpN + nt * 16) * HG_ROWB) + kb;
                    hg_ldm4(sBh + rbn + boff, bh[nt]);
                }
                #pragma unroll
                for (int mi = 0; mi < MI; mi++) {
                    #pragma unroll
                    for (int nj = 0; nj < NJ; nj++) {
                        uint32_t b0 = bh[nj >> 1][(nj & 1) * 2];
                        uint32_t b1 = bh[nj >> 1][(nj & 1) * 2 + 1];
                        hg_mma(acc[mi][nj], ah[mi], b0, b1);
                        if (TERMS == 2) hg_mma(acc[mi][nj], al[mi], b0, b1);
                    }
                }
            }
        }
    }

    // epilogue
    const int g = lane >> 2;
    const int tq = lane & 3;
    #pragma unroll
    for (int mi = 0; mi < MI; mi++) {
        int row0 = m0 + warpM + mi * 16 + g;
        int row1 = row0 + 8;
        #pragma unroll
        for (int nj = 0; nj < NJ; nj++) {
            int col = n0 + warpN + nj * 8 + tq * 2;
            float* a = acc[mi][nj];
            if (MODE == 1) {
                size_t o0 = (size_t)row0 * ldc + col;
                size_t o1 = (size_t)row1 * ldc + col;
                C[o0]     = a[0] + AUX[o0];
                C[o0 + 1] = a[1] + AUX[o0 + 1];
                C[o1]     = a[2] + AUX[o1];
                C[o1 + 1] = a[3] + AUX[o1 + 1];
            } else if (MODE == 2) {
                #pragma unroll
                for (int half = 0; half < 2; half++) {
                    int r = half ? row1 : row0;
                    float v0 = a[half * 2], v1 = a[half * 2 + 1];
                    float g0 = 0.5f * v0 * (1.0f + erff(v0 * 0.70710678118654752f));
                    float g1 = 0.5f * v1 * (1.0f + erff(v1 * 0.70710678118654752f));
                    __half h0, l0, h1, l1;
                    fp16_split(g0, h0, l0); fp16_split(g1, h1, l1);
                    __half2 hp; hp.x = h0; hp.y = h1;
                    __half2 lp; lp.x = l0; lp.y = l1;
                    size_t o = (size_t)r * ldc + col;
                    *(__half2*)&Gh[o] = hp;
                    *(__half2*)&Gl[o] = lp;
                }
            } else {
                if (col < Nout) {
                    C[(size_t)row0 * ldc + col] = a[0];
                    C[(size_t)row1 * ldc + col] = a[2];
                }
                if (col + 1 < Nout) {
                    C[(size_t)row0 * ldc + col + 1] = a[1];
                    C[(size_t)row1 * ldc + col + 1] = a[3];
                }
            }
        }
    }
}

// ======== attention GEMM (scores / PV): 3-stage, batched (unchanged, proven) ========
// MODE: 0 = fp32 store, 3 = PV merge->fp16 split
template<int BM, int BN, int MODE, bool CSKIP, bool CKLIM>
__global__ __launch_bounds__(256, 2)
void hgemm2_kernel(const __half* __restrict__ Ah, const __half* __restrict__ Al,
                   const __half* __restrict__ Bh,
                   const float* __restrict__ AUX, float* __restrict__ C,
                   __half* __restrict__ Gh, __half* __restrict__ Gl,
                   int K, int Nout, int ldc,
                   long long sA, long long sB, long long sC)
{
    constexpr int MATA  = BM * HG_ROWB;
    constexpr int STAGE = (2*BM + BN) * HG_ROWB;
    constexpr int MI = BM / 64;
    constexpr int NJ = BN / 16;
    constexpr int NT = BN / 32;

    extern __shared__ char dsm[];
    uint32_t sb = smem_u32(dsm);

    const int tid  = threadIdx.x;
    const int lane = tid & 31;
    const int wid  = tid >> 5;
    const int warpM = (wid & 3) * (BM/4);
    const int warpN = (wid >> 2) * (BN/2);

    const int m0 = blockIdx.y * BM;
    const int n0 = blockIdx.x * BN;
    if (CSKIP && n0 > m0 + BM - 1) return;

    const int z = blockIdx.z;
    Ah += (size_t)z * sA; Al += (size_t)z * sA;
    Bh += (size_t)z * sB;
    if (MODE == 0) C += (size_t)z * sC;

    const uint32_t aoff = (uint32_t)((lane & 15) * HG_ROWB + (lane >> 4) * 16);
    const uint32_t boff = (uint32_t)(((lane & 7) + ((lane >> 4) & 1) * 8) * HG_ROWB
                                     + ((lane >> 3) & 1) * 16);

    float acc[MI][NJ][4];
    #pragma unroll
    for (int i = 0; i < MI; i++)
        #pragma unroll
        for (int j = 0; j < NJ; j++)
            #pragma unroll
            for (int u = 0; u < 4; u++) acc[i][j][u] = 0.f;

    const int kend = CKLIM ? (K < m0 + BM ? K : m0 + BM) : K;
    const int nk = kend / 32;

    hg_load2<BM,BN,2>(sb,          Ah, Al, Bh, m0, n0, K, 0,  tid);
    if (nk > 1)
        hg_load2<BM,BN,2>(sb + STAGE, Ah, Al, Bh, m0, n0, K, 32, tid);

    for (int it = 0; it < nk; it++) {
        int s = it % 3;
        if (it + 1 < nk) {
            asm volatile("cp.async.wait_group 1;\n" ::: "memory");
        } else {
            asm volatile("cp.async.wait_group 0;\n" ::: "memory");
        }
        __syncthreads();
        if (it + 2 < nk) {
            hg_load2<BM,BN,2>(sb + ((it + 2) % 3) * STAGE, Ah, Al, Bh, m0, n0, K, (it + 2) * 32, tid);
        }

        uint32_t st  = sb + s * STAGE;
        uint32_t sAh = st;
        uint32_t sAl = st + MATA;
        uint32_t sBh = st + 2*MATA;

        #pragma unroll
        for (int kq = 0; kq < 2; kq++) {
            uint32_t kb = kq * 32;
            uint32_t ah[MI][4], al[MI][4], bh[NT][4];
            #pragma unroll
            for (int mi = 0; mi < MI; mi++) {
                uint32_t rb = (uint32_t)((warpM + mi * 16) * HG_ROWB) + kb;
                hg_ldm4(sAh + rb + aoff, ah[mi]);
                hg_ldm4(sAl + rb + aoff, al[mi]);
            }
            #pragma unroll
            for (int nt = 0; nt < NT; nt++) {
                uint32_t rb = (uint32_t)((warpN + nt * 16) * HG_ROWB) + kb;
                hg_ldm4(sBh + rb + boff, bh[nt]);
            }
            #pragma unroll
            for (int mi = 0; mi < MI; mi++) {
                #pragma unroll
                for (int nj = 0; nj < NJ; nj++) {
                    uint32_t b0 = bh[nj >> 1][(nj & 1) * 2];
                    uint32_t b1 = bh[nj >> 1][(nj & 1) * 2 + 1];
                    hg_mma(acc[mi][nj], ah[mi], b0, b1);
                    hg_mma(acc[mi][nj], al[mi], b0, b1);
                }
            }
        }
    }

    const int g = lane >> 2;
    const int tq = lane & 3;
    #pragma unroll
    for (int mi = 0; mi < MI; mi++) {
        int row0 = m0 + warpM + mi * 16 + g;
        int row1 = row0 + 8;
        #pragma unroll
        for (int nj = 0; nj < NJ; nj++) {
            int col = n0 + warpN + nj * 8 + tq * 2;
            float* a = acc[mi][nj];
            if (MODE == 3) {
                int b  = z >> 4, h = z & 15;
                #pragma unroll
                for (int half = 0; half < 2; half++) {
                    int q = half ? row1 : row0;
                    size_t vsrc = (size_t)(b*T_ + q)*3072 + 2048 + h*HD_ + col;
                    float v0 = a[half * 2]     + AUX[vsrc];
                    float v1 = a[half * 2 + 1] + AUX[vsrc + 1];
                    __half h0, l0, h1, l1;
                    fp16_split(v0, h0, l0); fp16_split(v1, h1, l1);
                    __half2 hp; hp.x = h0; hp.y = h1;
                    __half2 lp; lp.x = l0; lp.y = l1;
                    size_t o = (size_t)(b*T_ + q)*D_ + h*HD_ + col;
                    *(__half2*)&Gh[o] = hp;
                    *(__half2*)&Gl[o] = lp;
                }
            } else {
                C[(size_t)row0 * ldc + col] = a[0];
                C[(size_t)row0 * ldc + col + 1] = a[1];
                C[(size_t)row1 * ldc + col] = a[2];
                C[(size_t)row1 * ldc + col + 1] = a[3];
            }
        }
    }
}

// ================= launcher =================
extern "C" void kernel_launch(void* const* d_in, const int* in_sizes, int n_in,
                              void* d_out, int out_size) {
    const int*   ids   = (const int*)  d_in[0];
    const float* embed = (const float*)d_in[1];
    const float* pos   = (const float*)d_in[2];
    const float* Wq    = (const float*)d_in[3];
    const float* Wk    = (const float*)d_in[4];
    const float* Wv    = (const float*)d_in[5];
    const float* Wo    = (const float*)d_in[6];
    const float* ln1   = (const float*)d_in[7];
    const float* ln2   = (const float*)d_in[8];
    const float* qnw   = (const float*)d_in[9];
    const float* knw   = (const float*)d_in[10];
    const float* gate  = (const float*)d_in[11];
    const float* W1    = (const float*)d_in[12];
    const float* W2    = (const float*)d_in[13];
    const float* lnf   = (const float*)d_in[14];
    const float* Wlm   = (const float*)d_in[15];
    float* out = (float*)d_out;

    float *x,*qkv,*att;
    __half *hh,*obh,*obl,*mph,*mpl;
    __half *qTh,*qTl,*kTh,*vTh,*ph,*pl;
    __half *wqkv,*wo,*w1,*w2,*wlm;
    cudaGetSymbolAddress((void**)&x,   g_x);
    cudaGetSymbolAddress((void**)&qkv, g_qkv);
    cudaGetSymbolAddress((void**)&att, g_att);
    cudaGetSymbolAddress((void**)&hh,  g_hh);
    cudaGetSymbolAddress((void**)&obh, g_obh);
    cudaGetSymbolAddress((void**)&obl, g_obl);
    cudaGetSymbolAddress((void**)&mph, g_mph);
    cudaGetSymbolAddress((void**)&mpl, g_mpl);
    cudaGetSymbolAddress((void**)&qTh, g_qTh);
    cudaGetSymbolAddress((void**)&qTl, g_qTl);
    cudaGetSymbolAddress((void**)&kTh, g_kTh);
    cudaGetSymbolAddress((void**)&vTh, g_vTh);
    cudaGetSymbolAddress((void**)&ph,  g_ph);
    cudaGetSymbolAddress((void**)&pl,  g_pl);
    cudaGetSymbolAddress((void**)&wqkv, g_wqkv);
    cudaGetSymbolAddress((void**)&wo,  g_wo);
    cudaGetSymbolAddress((void**)&w1,  g_w1);
    cudaGetSymbolAddress((void**)&w2,  g_w2);
    cudaGetSymbolAddress((void**)&wlm, g_wlm);

    const int SD1  = 4 * (1*128 + 128) * HG_ROWB;      // 81920 (1-term, BM=128)
    const int SD2  = 4 * (2*64  + 128) * HG_ROWB;      // 81920 (2-term, BM=64)
    const int S128128 = 3 * (2*128 + 128) * HG_ROWB;   // 92160
    const int S6464   = 3 * (2*64  + 64 ) * HG_ROWB;   // 46080
    cudaFuncSetAttribute(hgemmd_kernel<0,1,128>, cudaFuncAttributeMaxDynamicSharedMemorySize, SD1);
    cudaFuncSetAttribute(hgemmd_kernel<2,1,128>, cudaFuncAttributeMaxDynamicSharedMemorySize, SD1);
    cudaFuncSetAttribute(hgemmd_kernel<1,2,64>,  cudaFuncAttributeMaxDynamicSharedMemorySize, SD2);
    cudaFuncSetAttribute(hgemm2_kernel<128,128,0,true, false>, cudaFuncAttributeMaxDynamicSharedMemorySize, S128128);
    cudaFuncSetAttribute(hgemm2_kernel<64, 64, 3,false,true >, cudaFuncAttributeMaxDynamicSharedMemorySize, S6464);

    const long long sQK = (long long)T_ * HD_;
    const long long sS  = (long long)T_ * T_;
    dim3 wb(32, 8);

    embed_kernel<<<BT_*D_/256, 256>>>(ids, embed, pos, x);
    rmsnorm_h_kernel<<<BT_, 256>>>(x, ln1, hh);
    wconv3_kernel<<<dim3(D_/32, D_/32, 3*L_), wb>>>(Wq, Wk, Wv, wqkv);
    // fused QKV layer 0 (1-term, BM=128)
    hgemmd_kernel<0,1,128><<<dim3(3072/128, BT_/128), 256, SD1>>>(
        hh, nullptr, wqkv, nullptr, qkv, nullptr, nullptr, D_, 3072, 3072);

    // remaining weight conversions
    wconv_kernel<<<dim3(D_/32, D_/32, L_), wb>>>(Wo, wo, D_, D_, (long long)D_*D_, (long long)D_*D_);
    wconv_kernel<<<dim3(F_/32, D_/32, L_), wb>>>(W1, w1, D_, F_, (long long)D_*F_, (long long)F_*D_);
    wconv_kernel<<<dim3(D_/32, F_/32, L_), wb>>>(W2, w2, F_, D_, (long long)F_*D_, (long long)D_*F_);
    wconv_kernel<<<dim3(VPAD_/32, D_/32, 1), wb>>>(Wlm, wlm, D_, V_, 0, 0);

    for (int l = 0; l < L_; l++) {
        qknorm_split_kernel<<<(B_*T_*H_)/8, 256>>>(qkv, 0,    qnw + (size_t)l*HD_, qTh, qTl);
        qknorm_split_kernel<<<(B_*T_*H_)/8, 256>>>(qkv, 1024, knw + (size_t)l*HD_, kTh, nullptr);
        vtrans_kernel<<<dim3(T_/32, HD_/32, B_*H_), dim3(32,8)>>>(qkv, vTh);

        // scores: per (b,h) Q[1024,64] @ K[1024,64]^T, causal tile-skip (2-term A)
        hgemm2_kernel<128,128,0,true,false><<<dim3(T_/128, T_/128, B_*H_), 256, S128128>>>(
            qTh, qTl, kTh, nullptr, att, nullptr, nullptr, HD_, T_, T_, sQK, sQK, sS);

        softmax_kernel<<<B_*H_*T_, 256>>>(att, gate + (size_t)l*H_, ph, pl);

        // PV: per (b,h) P[1024,1024] @ V^T, causal K-limit, fused vres merge+split (2-term)
        hgemm2_kernel<64,64,3,false,true><<<dim3(1, T_/64, B_*H_), 256, S6464>>>(
            ph, pl, vTh, qkv, nullptr, obh, obl, T_, HD_, HD_, sS, sQK, 0);

        // Wo with fused residual into x (2-term, BM=64)
        hgemmd_kernel<1,2,64><<<dim3(D_/128, BT_/64), 256, SD2>>>(
            obh, obl, wo + (size_t)l*D_*D_, x, x, nullptr, nullptr, D_, D_, D_);

        // MLP: W1 1-term BM=128, W2 2-term BM=64
        rmsnorm_h_kernel<<<BT_, 256>>>(x, ln2 + (size_t)l*D_, hh);
        hgemmd_kernel<2,1,128><<<dim3(F_/128, BT_/128), 256, SD1>>>(
            hh, nullptr, w1 + (size_t)l*F_*D_, nullptr, nullptr, mph, mpl, D_, F_, F_);
        hgemmd_kernel<1,2,64><<<dim3(D_/128, BT_/64), 256, SD2>>>(
            mph, mpl, w2 + (size_t)l*D_*F_, x, x, nullptr, nullptr, F_, D_, D_);

        // next layer's pre-attention norm + QKV (1-term BM=128)
        if (l + 1 < L_) {
            rmsnorm_h_kernel<<<BT_, 256>>>(x, ln1 + (size_t)(l+1)*D_, hh);
            hgemmd_kernel<0,1,128><<<dim3(3072/128, BT_/128), 256, SD1>>>(
                hh, nullptr, wqkv + (size_t)(l+1)*3072*D_, nullptr, qkv, nullptr, nullptr,
                D_, 3072, 3072);
        }
    }

    rmsnorm_h_kernel<<<BT_, 256>>>(x, lnf, hh);
    // LM head (1-term BM=128)
    hgemmd_kernel<0,1,128><<<dim3(VPAD_/128, BT_/128), 256, SD1>>>(
        hh, nullptr, wlm, nullptr, out, nullptr, nullptr, D_, V_, V_);
}

// round 13
// speedup vs baseline: 1.3462x; 1.0926x over previous
#include <cuda_runtime.h>
#include <cuda_fp16.h>
#include <math.h>
#include <stdint.h>

// Problem dims
#define L_ 12
#define B_ 2
#define T_ 1024
#define D_ 1024
#define H_ 16
#define HD_ 64
#define F_ 4096
#define V_ 50257
#define VPAD_ 50304
#define BT_ (B_*T_)

// ================= scratch (__device__ globals) =================
__device__ float g_x  [BT_*D_];
__device__ float g_qkv[BT_*3072];
__device__ float g_att[(size_t)B_*H_*T_*T_];

__device__ __align__(256) __half g_hh [BT_*D_];
__device__ __align__(256) __half g_obh[BT_*D_];
__device__ __align__(256) __half g_mph[BT_*F_];

// attention operands
__device__ __align__(256) __half g_qTh[BT_*D_];
__device__ __align__(256) __half g_qTl[BT_*D_];
__device__ __align__(256) __half g_kTh[BT_*D_];          // K single fp16
__device__ __align__(256) __half g_vTh[BT_*D_];          // V single fp16, [B,H,HD,T]
__device__ __align__(256) __half g_ph [(size_t)B_*H_*T_*T_];
__device__ __align__(256) __half g_pl [(size_t)B_*H_*T_*T_];

// converted+transposed weights [N,K] layout, single fp16
__device__ __align__(256) __half g_wqkv[(size_t)L_*3072*D_];
__device__ __align__(256) __half g_wo  [(size_t)L_*D_*D_];
__device__ __align__(256) __half g_w1  [(size_t)L_*F_*D_];
__device__ __align__(256) __half g_w2  [(size_t)L_*D_*F_];
__device__ __align__(256) __half g_wlm [(size_t)VPAD_*D_];

// ================= small helpers =================
__device__ __forceinline__ uint32_t smem_u32(const void* p) {
    uint32_t a;
    asm("{ .reg .u64 t; cvta.to.shared.u64 t, %1; cvt.u32.u64 %0, t; }" : "=r"(a) : "l"(p));
    return a;
}
__device__ __forceinline__ void fp16_split(float v, __half& hi, __half& lo) {
    hi = __float2half(v);
    lo = __float2half(v - __half2float(hi));
}

// ================= elementwise / conversion kernels =================
__global__ void embed_kernel(const int* __restrict__ ids, const float* __restrict__ emb,
                             const float* __restrict__ pos, float* __restrict__ x) {
    int idx = blockIdx.x * 256 + threadIdx.x;
    int row = idx >> 10;
    int c   = idx & 1023;
    int t   = row & (T_-1);
    x[idx] = emb[(size_t)ids[row]*D_ + c] + pos[(size_t)t*D_ + c];
}

// W [K,N] fp32 -> out [Npad,K] fp16 (transposed, zero-padded), batched over z
__global__ void wconv_kernel(const float* __restrict__ W, __half* __restrict__ oh,
                             int K, int N, long long srcStride, long long dstStride) {
    __shared__ float tile[32][33];
    const float* Ws = W + (size_t)blockIdx.z * srcStride;
    __half* ohz = oh + (size_t)blockIdx.z * dstStride;
    int n0 = blockIdx.x * 32, k0 = blockIdx.y * 32;
    #pragma unroll
    for (int j = 0; j < 32; j += 8) {
        int kk = k0 + threadIdx.y + j;
        int nn = n0 + threadIdx.x;
        tile[threadIdx.y + j][threadIdx.x] = (nn < N) ? Ws[(size_t)kk*N + nn] : 0.f;
    }
    __syncthreads();
    #pragma unroll
    for (int j = 0; j < 32; j += 8) {
        int nn = n0 + threadIdx.y + j;
        int kk = k0 + threadIdx.x;
        ohz[(size_t)nn*K + kk] = __float2half(tile[threadIdx.x][threadIdx.y + j]);
    }
}

// Wq/Wk/Wv [L][K,N] fp32 -> g_wqkv [L][3072,K] fp16, z in [0, 3L)
__global__ void wconv3_kernel(const float* __restrict__ Wq, const float* __restrict__ Wk,
                              const float* __restrict__ Wv, __half* __restrict__ dst) {
    __shared__ float tile[32][33];
    int z = blockIdx.z;
    int l = z / 3, sel = z % 3;
    const float* Ws = (sel == 0 ? Wq : sel == 1 ? Wk : Wv) + (size_t)l * D_ * D_;
    __half* od = dst + ((size_t)l * 3072 + sel * D_) * D_;
    int n0 = blockIdx.x * 32, k0 = blockIdx.y * 32;
    #pragma unroll
    for (int j = 0; j < 32; j += 8) {
        tile[threadIdx.y + j][threadIdx.x] = Ws[(size_t)(k0 + threadIdx.y + j)*D_ + n0 + threadIdx.x];
    }
    __syncthreads();
    #pragma unroll
    for (int j = 0; j < 32; j += 8) {
        int nn = n0 + threadIdx.y + j;
        int kk = k0 + threadIdx.x;
        od[(size_t)nn*D_ + kk] = __float2half(tile[threadIdx.x][threadIdx.y + j]);
    }
}

// rmsnorm writing fp16 hi only
__global__ void rmsnorm_h_kernel(const float* __restrict__ x, const float* __restrict__ w,
                                 __half* __restrict__ oh) {
    __shared__ float red[256];
    int row = blockIdx.x;
    const float* xr = x + (size_t)row * D_;
    float v[4]; float ss = 0.f;
    #pragma unroll
    for (int i = 0; i < 4; i++) { v[i] = xr[threadIdx.x + 256*i]; ss += v[i]*v[i]; }
    red[threadIdx.x] = ss; __syncthreads();
    for (int s = 128; s > 0; s >>= 1) {
        if (threadIdx.x < s) red[threadIdx.x] += red[threadIdx.x + s];
        __syncthreads();
    }
    float r = rsqrtf(red[0] / (float)D_ + 1e-5f);
    #pragma unroll
    for (int i = 0; i < 4; i++) {
        int c = threadIdx.x + 256*i;
        oh[(size_t)row*D_ + c] = __float2half(w[c] * v[i] * r);
    }
}

// fused QK-norm: each warp handles one (b,t,h): Q row (hi+lo) and K row (hi only)
__global__ void qknorm2_kernel(const float* __restrict__ qkv,
                               const float* __restrict__ qw, const float* __restrict__ kw,
                               __half* __restrict__ qh, __half* __restrict__ ql,
                               __half* __restrict__ kh) {
    int warp = (blockIdx.x * blockDim.x + threadIdx.x) >> 5;
    int lane = threadIdx.x & 31;
    int h  = warp & (H_-1);
    int bt = warp >> 4;
    int t  = bt & (T_-1);
    int b  = bt >> 10;
    size_t dst = ((size_t)((b*H_ + h)*T_ + t)) * HD_;

    // Q (hi + lo)
    {
        const float* src = qkv + (size_t)bt * 3072 + h * HD_;
        float x0 = src[lane], x1 = src[lane + 32];
        float ss = x0*x0 + x1*x1;
        #pragma unroll
        for (int o = 16; o > 0; o >>= 1) ss += __shfl_xor_sync(0xffffffffu, ss, o);
        float r = rsqrtf(ss / (float)HD_ + 1e-5f);
        float y0 = qw[lane] * x0 * r;
        float y1 = qw[lane + 32] * x1 * r;
        __half h0 = __float2half(y0);
        __half h1 = __float2half(y1);
        qh[dst + lane]      = h0;
        qh[dst + lane + 32] = h1;
        ql[dst + lane]      = __float2half(y0 - __half2float(h0));
        ql[dst + lane + 32] = __float2half(y1 - __half2float(h1));
    }
    // K (hi only)
    {
        const float* src = qkv + (size_t)bt * 3072 + 1024 + h * HD_;
        float x0 = src[lane], x1 = src[lane + 32];
        float ss = x0*x0 + x1*x1;
        #pragma unroll
        for (int o = 16; o > 0; o >>= 1) ss += __shfl_xor_sync(0xffffffffu, ss, o);
        float r = rsqrtf(ss / (float)HD_ + 1e-5f);
        kh[dst + lane]      = __float2half(kw[lane] * x0 * r);
        kh[dst + lane + 32] = __float2half(kw[lane + 32] * x1 * r);
    }
}

// V: [B,T,3D](col 2048+) -> [B,H,HD,T] single fp16 via 32x32 tile transpose
__global__ void vtrans_kernel(const float* __restrict__ qkv, __half* __restrict__ vh) {
    __shared__ float tile[32][33];
    int z = blockIdx.z;           // b*H+h
    int b = z >> 4, h = z & 15;
    int t0 = blockIdx.x * 32, d0 = blockIdx.y * 32;
    #pragma unroll
    for (int j = 0; j < 32; j += 8) {
        int t = t0 + threadIdx.y + j;
        tile[threadIdx.y + j][threadIdx.x] =
            qkv[(size_t)(b*T_ + t)*3072 + 2048 + h*HD_ + d0 + threadIdx.x];
    }
    __syncthreads();
    #pragma unroll
    for (int j = 0; j < 32; j += 8) {
        int d = d0 + threadIdx.y + j;
        size_t o = ((size_t)z * HD_ + d) * T_ + t0 + threadIdx.x;
        vh[o] = __float2half(tile[threadIdx.x][threadIdx.y + j]);
    }
}

// causal softmax, scale 1/8, per-head gate; writes P fp16 hi/lo up to qlim
__global__ void softmax_kernel(const float* __restrict__ S, const float* __restrict__ gate,
                               __half* __restrict__ ph, __half* __restrict__ pl) {
    __shared__ float red[256];
    int row = blockIdx.x;
    int q = row & (T_-1);
    int h = (row >> 10) & (H_-1);
    const float* s = S + (size_t)row * T_;
    const float scale = 0.125f;
    float vals[4]; float m = -3.4e38f;
    #pragma unroll
    for (int i = 0; i < 4; i++) {
        int j = threadIdx.x + 256*i;
        float v = (j <= q) ? s[j] * scale : -3.4e38f;
        vals[i] = v; m = fmaxf(m, v);
    }
    red[threadIdx.x] = m; __syncthreads();
    for (int t = 128; t > 0; t >>= 1) {
        if (threadIdx.x < t) red[threadIdx.x] = fmaxf(red[threadIdx.x], red[threadIdx.x + t]);
        __syncthreads();
    }
    m = red[0]; __syncthreads();
    float sum = 0.f;
    #pragma unroll
    for (int i = 0; i < 4; i++) {
        int j = threadIdx.x + 256*i;
        float e = (j <= q) ? __expf(vals[i] - m) : 0.f;
        vals[i] = e; sum += e;
    }
    red[threadIdx.x] = sum; __syncthreads();
    for (int t = 128; t > 0; t >>= 1) {
        if (threadIdx.x < t) red[threadIdx.x] += red[threadIdx.x + t];
        __syncthreads();
    }
    float inv = gate[h] / red[0];
    int qlim = (q & ~63) + 64;
    #pragma unroll
    for (int i = 0; i < 4; i++) {
        int j = threadIdx.x + 256*i;
        if (j < qlim) {
            float p = vals[i] * inv;
            __half hi, lo; fp16_split(p, hi, lo);
            ph[(size_t)row*T_ + j] = hi;
            pl[(size_t)row*T_ + j] = lo;
        }
    }
}

// ================= shared HMMA building blocks =================
#define HG_ROWB 80

__device__ __forceinline__ void hg_ldm4(uint32_t addr, uint32_t* r) {
    asm volatile("ldmatrix.sync.aligned.m8n8.x4.shared.b16 {%0,%1,%2,%3}, [%4];"
        : "=r"(r[0]), "=r"(r[1]), "=r"(r[2]), "=r"(r[3]) : "r"(addr));
}
__device__ __forceinline__ void hg_mma(float* d, const uint32_t* a, uint32_t b0, uint32_t b1) {
    asm volatile("mma.sync.aligned.m16n8k16.row.col.f32.f16.f16.f32 "
        "{%0,%1,%2,%3}, {%4,%5,%6,%7}, {%8,%9}, {%0,%1,%2,%3};"
        : "+f"(d[0]), "+f"(d[1]), "+f"(d[2]), "+f"(d[3])
        : "r"(a[0]), "r"(a[1]), "r"(a[2]), "r"(a[3]), "r"(b0), "r"(b1));
}

// load TERMS*A-tiles + B-tile into one stage
template<int BM, int BN, int TERMS>
__device__ __forceinline__ void hg_load2(uint32_t stg,
    const __half* Ah, const __half* Al, const __half* Bh,
    int m0, int n0, int K, int k0, int tid)
{
    constexpr int CA = BM * 4;         // 16B chunks per A matrix
    constexpr int CB = BN * 4;
    constexpr int TOT = TERMS*CA + CB;
    #pragma unroll
    for (int p = 0; p < TOT/256; p++) {
        int c = tid + p * 256;
        const __half* base; int r0; uint32_t mo; int rr;
        if (c < CA)                          { base = Ah; r0 = m0; mo = 0;                 rr = c; }
        else if (TERMS == 2 && c < 2*CA)     { base = Al; r0 = m0; mo = BM*HG_ROWB;        rr = c - CA; }
        else                                 { base = Bh; r0 = n0; mo = TERMS*BM*HG_ROWB;  rr = c - TERMS*CA; }
        int r = rr >> 2, kc = rr & 3;
        uint32_t so = stg + mo + r * HG_ROWB + kc * 16;
        const void* ga = (const void*)(base + (size_t)(r0 + r) * K + k0 + kc * 8);
        asm volatile("cp.async.cg.shared.global [%0], [%1], 16;\n" :: "r"(so), "l"(ga));
    }
    asm volatile("cp.async.commit_group;\n" ::: "memory");
}

// ======== dense GEMM: BMx128 tile, pair double-buffer, TERMS A-side terms ========
// C[M,N] = (Ah[+Al])[M,K] @ Bh[N,K]^T.  MODE: 0=plain(guard Nout), 1=+RES, 2=GELU->fp16 hi
template<int MODE, int TERMS, int BM>
__global__ __launch_bounds__(256, 2)
void hgemmd_kernel(const __half* __restrict__ Ah, const __half* __restrict__ Al,
                   const __half* __restrict__ Bh,
                   const float* __restrict__ AUX, float* __restrict__ C,
                   __half* __restrict__ Gh,
                   int K, int Nout, int ldc)
{
    constexpr int BN = 128;
    constexpr int MATA  = BM * HG_ROWB;
    constexpr int STAGE = (TERMS*BM + BN) * HG_ROWB;
    constexpr int MI = BM / 64;        // 16-row A tiles per warp
    constexpr int NJ = 8, NT = 4;

    extern __shared__ char dsm[];
    uint32_t sb = smem_u32(dsm);

    const int tid  = threadIdx.x;
    const int lane = tid & 31;
    const int wid  = tid >> 5;
    const int warpM = (wid & 3) * (BM/4);
    const int warpN = (wid >> 2) * 64;

    const int m0 = blockIdx.y * BM;
    const int n0 = blockIdx.x * BN;

    const uint32_t aoff = (uint32_t)((lane & 15) * HG_ROWB + (lane >> 4) * 16);
    const uint32_t boff = (uint32_t)(((lane & 7) + ((lane >> 4) & 1) * 8) * HG_ROWB
                                     + ((lane >> 3) & 1) * 16);

    float acc[MI][NJ][4];
    #pragma unroll
    for (int i = 0; i < MI; i++)
        #pragma unroll
        for (int j = 0; j < NJ; j++)
            #pragma unroll
            for (int u = 0; u < 4; u++) acc[i][j][u] = 0.f;

    const int nk = K / 32;          // even, >= 4
    const int np = nk / 2;

    hg_load2<BM,BN,TERMS>(sb,          Ah, Al, Bh, m0, n0, K, 0,  tid);
    hg_load2<BM,BN,TERMS>(sb + STAGE,  Ah, Al, Bh, m0, n0, K, 32, tid);

    for (int ip = 0; ip < np; ip++) {
        int c0 = 2 * ip;
        asm volatile("cp.async.wait_group 0;\n" ::: "memory");
        __syncthreads();
        if (c0 + 2 < nk) {
            hg_load2<BM,BN,TERMS>(sb + ((c0 + 2) & 3) * STAGE, Ah, Al, Bh, m0, n0, K, (c0 + 2) * 32, tid);
            hg_load2<BM,BN,TERMS>(sb + ((c0 + 3) & 3) * STAGE, Ah, Al, Bh, m0, n0, K, (c0 + 3) * 32, tid);
        }

        #pragma unroll
        for (int half = 0; half < 2; half++) {
            uint32_t st  = sb + ((c0 + half) & 3) * STAGE;
            uint32_t sAh = st;
            uint32_t sAl = st + MATA;
            uint32_t sBh = st + TERMS*MATA;
            #pragma unroll
            for (int kq = 0; kq < 2; kq++) {
                uint32_t kb = kq * 32;
                uint32_t ah[MI][4], al[MI][4], bh[NT][4];
                #pragma unroll
                for (int mi = 0; mi < MI; mi++) {
                    uint32_t rb = (uint32_t)((warpM + mi * 16) * HG_ROWB) + kb;
                    hg_ldm4(sAh + rb + aoff, ah[mi]);
                    if (TERMS == 2) hg_ldm4(sAl + rb + aoff, al[mi]);
                }
                #pragma unroll
                for (int nt = 0; nt < NT; nt++) {
                    uint32_t rbn = (uint32_t)((warpN + nt * 16) * HG_ROWB) + kb;
                    hg_ldm4(sBh + rbn + boff, bh[nt]);
                }
                #pragma unroll
                for (int mi = 0; mi < MI; mi++) {
                    #pragma unroll
                    for (int nj = 0; nj < NJ; nj++) {
                        uint32_t b0 = bh[nj >> 1][(nj & 1) * 2];
                        uint32_t b1 = bh[nj >> 1][(nj & 1) * 2 + 1];
                        hg_mma(acc[mi][nj], ah[mi], b0, b1);
                        if (TERMS == 2) hg_mma(acc[mi][nj], al[mi], b0, b1);
                    }
                }
            }
        }
    }

    // epilogue
    const int g = lane >> 2;
    const int tq = lane & 3;
    #pragma unroll
    for (int mi = 0; mi < MI; mi++) {
        int row0 = m0 + warpM + mi * 16 + g;
        int row1 = row0 + 8;
        #pragma unroll
        for (int nj = 0; nj < NJ; nj++) {
            int col = n0 + warpN + nj * 8 + tq * 2;
            float* a = acc[mi][nj];
            if (MODE == 1) {
                size_t o0 = (size_t)row0 * ldc + col;
                size_t o1 = (size_t)row1 * ldc + col;
                C[o0]     = a[0] + AUX[o0];
                C[o0 + 1] = a[1] + AUX[o0 + 1];
                C[o1]     = a[2] + AUX[o1];
                C[o1 + 1] = a[3] + AUX[o1 + 1];
            } else if (MODE == 2) {
                #pragma unroll
                for (int half = 0; half < 2; half++) {
                    int r = half ? row1 : row0;
                    float v0 = a[half * 2], v1 = a[half * 2 + 1];
                    float g0 = 0.5f * v0 * (1.0f + erff(v0 * 0.70710678118654752f));
                    float g1 = 0.5f * v1 * (1.0f + erff(v1 * 0.70710678118654752f));
                    __half2 hp; hp.x = __float2half(g0); hp.y = __float2half(g1);
                    *(__half2*)&Gh[(size_t)r * ldc + col] = hp;
                }
            } else {
                if (col < Nout) {
                    C[(size_t)row0 * ldc + col] = a[0];
                    C[(size_t)row1 * ldc + col] = a[2];
                }
                if (col + 1 < Nout) {
                    C[(size_t)row0 * ldc + col + 1] = a[1];
                    C[(size_t)row1 * ldc + col + 1] = a[3];
                }
            }
        }
    }
}

// ======== attention GEMM (scores / PV): 3-stage, batched ========
// MODE: 0 = fp32 store, 3 = PV merge->fp16 hi only
template<int BM, int BN, int MODE, bool CSKIP, bool CKLIM>
__global__ __launch_bounds__(256, 2)
void hgemm2_kernel(const __half* __restrict__ Ah, const __half* __restrict__ Al,
                   const __half* __restrict__ Bh,
                   const float* __restrict__ AUX, float* __restrict__ C,
                   __half* __restrict__ Gh,
                   int K, int Nout, int ldc,
                   long long sA, long long sB, long long sC)
{
    constexpr int MATA  = BM * HG_ROWB;
    constexpr int STAGE = (2*BM + BN) * HG_ROWB;
    constexpr int MI = BM / 64;
    constexpr int NJ = BN / 16;
    constexpr int NT = BN / 32;

    extern __shared__ char dsm[];
    uint32_t sb = smem_u32(dsm);

    const int tid  = threadIdx.x;
    const int lane = tid & 31;
    const int wid  = tid >> 5;
    const int warpM = (wid & 3) * (BM/4);
    const int warpN = (wid >> 2) * (BN/2);

    const int m0 = blockIdx.y * BM;
    const int n0 = blockIdx.x * BN;
    if (CSKIP && n0 > m0 + BM - 1) return;

    const int z = blockIdx.z;
    Ah += (size_t)z * sA; Al += (size_t)z * sA;
    Bh += (size_t)z * sB;
    if (MODE == 0) C += (size_t)z * sC;

    const uint32_t aoff = (uint32_t)((lane & 15) * HG_ROWB + (lane >> 4) * 16);
    const uint32_t boff = (uint32_t)(((lane & 7) + ((lane >> 4) & 1) * 8) * HG_ROWB
                                     + ((lane >> 3) & 1) * 16);

    float acc[MI][NJ][4];
    #pragma unroll
    for (int i = 0; i < MI; i++)
        #pragma unroll
        for (int j = 0; j < NJ; j++)
            #pragma unroll
            for (int u = 0; u < 4; u++) acc[i][j][u] = 0.f;

    const int kend = CKLIM ? (K < m0 + BM ? K : m0 + BM) : K;
    const int nk = kend / 32;

    hg_load2<BM,BN,2>(sb,          Ah, Al, Bh, m0, n0, K, 0,  tid);
    if (nk > 1)
        hg_load2<BM,BN,2>(sb + STAGE, Ah, Al, Bh, m0, n0, K, 32, tid);

    for (int it = 0; it < nk; it++) {
        int s = it % 3;
        if (it + 1 < nk) {
            asm volatile("cp.async.wait_group 1;\n" ::: "memory");
        } else {
            asm volatile("cp.async.wait_group 0;\n" ::: "memory");
        }
        __syncthreads();
        if (it + 2 < nk) {
            hg_load2<BM,BN,2>(sb + ((it + 2) % 3) * STAGE, Ah, Al, Bh, m0, n0, K, (it + 2) * 32, tid);
        }

        uint32_t st  = sb + s * STAGE;
        uint32_t sAh = st;
        uint32_t sAl = st + MATA;
        uint32_t sBh = st + 2*MATA;

        #pragma unroll
        for (int kq = 0; kq < 2; kq++) {
            uint32_t kb = kq * 32;
            uint32_t ah[MI][4], al[MI][4], bh[NT][4];
            #pragma unroll
            for (int mi = 0; mi < MI; mi++) {
                uint32_t rb = (uint32_t)((warpM + mi * 16) * HG_ROWB) + kb;
                hg_ldm4(sAh + rb + aoff, ah[mi]);
                hg_ldm4(sAl + rb + aoff, al[mi]);
            }
            #pragma unroll
            for (int nt = 0; nt < NT; nt++) {
                uint32_t rb = (uint32_t)((warpN + nt * 16) * HG_ROWB) + kb;
                hg_ldm4(sBh + rb + boff, bh[nt]);
            }
            #pragma unroll
            for (int mi = 0; mi < MI; mi++) {
                #pragma unroll
                for (int nj = 0; nj < NJ; nj++) {
                    uint32_t b0 = bh[nj >> 1][(nj & 1) * 2];
                    uint32_t b1 = bh[nj >> 1][(nj & 1) * 2 + 1];
                    hg_mma(acc[mi][nj], ah[mi], b0, b1);
                    hg_mma(acc[mi][nj], al[mi], b0, b1);
                }
            }
        }
    }

    const int g = lane >> 2;
    const int tq = lane & 3;
    #pragma unroll
    for (int mi = 0; mi < MI; mi++) {
        int row0 = m0 + warpM + mi * 16 + g;
        int row1 = row0 + 8;
        #pragma unroll
        for (int nj = 0; nj < NJ; nj++) {
            int col = n0 + warpN + nj * 8 + tq * 2;
            float* a = acc[mi][nj];
            if (MODE == 3) {
                int b  = z >> 4, h = z & 15;
                #pragma unroll
                for (int half = 0; half < 2; half++) {
                    int q = half ? row1 : row0;
                    size_t vsrc = (size_t)(b*T_ + q)*3072 + 2048 + h*HD_ + col;
                    float v0 = a[half * 2]     + AUX[vsrc];
                    float v1 = a[half * 2 + 1] + AUX[vsrc + 1];
                    __half2 hp; hp.x = __float2half(v0); hp.y = __float2half(v1);
                    *(__half2*)&Gh[(size_t)(b*T_ + q)*D_ + h*HD_ + col] = hp;
                }
            } else {
                C[(size_t)row0 * ldc + col] = a[0];
                C[(size_t)row0 * ldc + col + 1] = a[1];
                C[(size_t)row1 * ldc + col] = a[2];
                C[(size_t)row1 * ldc + col + 1] = a[3];
            }
        }
    }
}

// ================= launcher =================
extern "C" void kernel_launch(void* const* d_in, const int* in_sizes, int n_in,
                              void* d_out, int out_size) {
    const int*   ids   = (const int*)  d_in[0];
    const float* embed = (const float*)d_in[1];
    const float* pos   = (const float*)d_in[2];
    const float* Wq    = (const float*)d_in[3];
    const float* Wk    = (const float*)d_in[4];
    const float* Wv    = (const float*)d_in[5];
    const float* Wo    = (const float*)d_in[6];
    const float* ln1   = (const float*)d_in[7];
    const float* ln2   = (const float*)d_in[8];
    const float* qnw   = (const float*)d_in[9];
    const float* knw   = (const float*)d_in[10];
    const float* gate  = (const float*)d_in[11];
    const float* W1    = (const float*)d_in[12];
    const float* W2    = (const float*)d_in[13];
    const float* lnf   = (const float*)d_in[14];
    const float* Wlm   = (const float*)d_in[15];
    float* out = (float*)d_out;

    float *x,*qkv,*att;
    __half *hh,*obh,*mph;
    __half *qTh,*qTl,*kTh,*vTh,*ph,*pl;
    __half *wqkv,*wo,*w1,*w2,*wlm;
    cudaGetSymbolAddress((void**)&x,   g_x);
    cudaGetSymbolAddress((void**)&qkv, g_qkv);
    cudaGetSymbolAddress((void**)&att, g_att);
    cudaGetSymbolAddress((void**)&hh,  g_hh);
    cudaGetSymbolAddress((void**)&obh, g_obh);
    cudaGetSymbolAddress((void**)&mph, g_mph);
    cudaGetSymbolAddress((void**)&qTh, g_qTh);
    cudaGetSymbolAddress((void**)&qTl, g_qTl);
    cudaGetSymbolAddress((void**)&kTh, g_kTh);
    cudaGetSymbolAddress((void**)&vTh, g_vTh);
    cudaGetSymbolAddress((void**)&ph,  g_ph);
    cudaGetSymbolAddress((void**)&pl,  g_pl);
    cudaGetSymbolAddress((void**)&wqkv, g_wqkv);
    cudaGetSymbolAddress((void**)&wo,  g_wo);
    cudaGetSymbolAddress((void**)&w1,  g_w1);
    cudaGetSymbolAddress((void**)&w2,  g_w2);
    cudaGetSymbolAddress((void**)&wlm, g_wlm);

    const int SD1_128 = 4 * (1*128 + 128) * HG_ROWB;   // 81920 (1-term, BM=128)
    const int SD1_64  = 4 * (1*64  + 128) * HG_ROWB;   // 61440 (1-term, BM=64)
    const int S128128 = 3 * (2*128 + 128) * HG_ROWB;   // 92160
    const int S6464   = 3 * (2*64  + 64 ) * HG_ROWB;   // 46080
    cudaFuncSetAttribute(hgemmd_kernel<0,1,128>, cudaFuncAttributeMaxDynamicSharedMemorySize, SD1_128);
    cudaFuncSetAttribute(hgemmd_kernel<2,1,128>, cudaFuncAttributeMaxDynamicSharedMemorySize, SD1_128);
    cudaFuncSetAttribute(hgemmd_kernel<1,1,64>,  cudaFuncAttributeMaxDynamicSharedMemorySize, SD1_64);
    cudaFuncSetAttribute(hgemm2_kernel<128,128,0,true, false>, cudaFuncAttributeMaxDynamicSharedMemorySize, S128128);
    cudaFuncSetAttribute(hgemm2_kernel<64, 64, 3,false,true >, cudaFuncAttributeMaxDynamicSharedMemorySize, S6464);

    const long long sQK = (long long)T_ * HD_;
    const long long sS  = (long long)T_ * T_;
    dim3 wb(32, 8);

    embed_kernel<<<BT_*D_/256, 256>>>(ids, embed, pos, x);
    rmsnorm_h_kernel<<<BT_, 256>>>(x, ln1, hh);
    wconv3_kernel<<<dim3(D_/32, D_/32, 3*L_), wb>>>(Wq, Wk, Wv, wqkv);
    // fused QKV layer 0 (1-term, BM=128)
    hgemmd_kernel<0,1,128><<<dim3(3072/128, BT_/128), 256, SD1_128>>>(
        hh, nullptr, wqkv, nullptr, qkv, nullptr, D_, 3072, 3072);

    // remaining weight conversions
    wconv_kernel<<<dim3(D_/32, D_/32, L_), wb>>>(Wo, wo, D_, D_, (long long)D_*D_, (long long)D_*D_);
    wconv_kernel<<<dim3(F_/32, D_/32, L_), wb>>>(W1, w1, D_, F_, (long long)D_*F_, (long long)F_*D_);
    wconv_kernel<<<dim3(D_/32, F_/32, L_), wb>>>(W2, w2, F_, D_, (long long)F_*D_, (long long)D_*F_);
    wconv_kernel<<<dim3(VPAD_/32, D_/32, 1), wb>>>(Wlm, wlm, D_, V_, 0, 0);

    for (int l = 0; l < L_; l++) {
        // fused QK-norm (Q hi/lo, K hi) + V transpose
        qknorm2_kernel<<<(B_*T_*H_)/8, 256>>>(qkv, qnw + (size_t)l*HD_, knw + (size_t)l*HD_,
                                              qTh, qTl, kTh);
        vtrans_kernel<<<dim3(T_/32, HD_/32, B_*H_), dim3(32,8)>>>(qkv, vTh);

        // scores: per (b,h) Q[1024,64] @ K[1024,64]^T, causal tile-skip (2-term A)
        hgemm2_kernel<128,128,0,true,false><<<dim3(T_/128, T_/128, B_*H_), 256, S128128>>>(
            qTh, qTl, kTh, nullptr, att, nullptr, HD_, T_, T_, sQK, sQK, sS);

        softmax_kernel<<<B_*H_*T_, 256>>>(att, gate + (size_t)l*H_, ph, pl);

        // PV: per (b,h) P[1024,1024] @ V^T, causal K-limit, fused vres merge (hi only)
        hgemm2_kernel<64,64,3,false,true><<<dim3(1, T_/64, B_*H_), 256, S6464>>>(
            ph, pl, vTh, qkv, nullptr, obh, T_, HD_, HD_, sS, sQK, 0);

        // Wo with fused residual into x (1-term, BM=64)
        hgemmd_kernel<1,1,64><<<dim3(D_/128, BT_/64), 256, SD1_64>>>(
            obh, nullptr, wo + (size_t)l*D_*D_, x, x, nullptr, D_, D_, D_);

        // MLP: W1 1-term BM=128 (GELU -> hi only), W2 1-term BM=64
        rmsnorm_h_kernel<<<BT_, 256>>>(x, ln2 + (size_t)l*D_, hh);
        hgemmd_kernel<2,1,128><<<dim3(F_/128, BT_/128), 256, SD1_128>>>(
            hh, nullptr, w1 + (size_t)l*F_*D_, nullptr, nullptr, mph, D_, F_, F_);
        hgemmd_kernel<1,1,64><<<dim3(D_/128, BT_/64), 256, SD1_64>>>(
            mph, nullptr, w2 + (size_t)l*D_*F_, x, x, nullptr, F_, D_, D_);

        // next layer's pre-attention norm + QKV (1-term BM=128)
        if (l + 1 < L_) {
            rmsnorm_h_kernel<<<BT_, 256>>>(x, ln1 + (size_t)(l+1)*D_, hh);
            hgemmd_kernel<0,1,128><<<dim3(3072/128, BT_/128), 256, SD1_128>>>(
                hh, nullptr, wqkv + (size_t)(l+1)*3072*D_, nullptr, qkv, nullptr,
                D_, 3072, 3072);
        }
    }

    rmsnorm_h_kernel<<<BT_, 256>>>(x, lnf, hh);
    // LM head (1-term BM=128)
    hgemmd_kernel<0,1,128><<<dim3(VPAD_/128, BT_/128), 256, SD1_128>>>(
        hh, nullptr, wlm, nullptr, out, nullptr, D_, V_, V_);
}

// round 14
// speedup vs baseline: 1.4156x; 1.0515x over previous
#include <cuda_runtime.h>
#include <cuda_fp16.h>
#include <math.h>
#include <stdint.h>

// Problem dims
#define L_ 12
#define B_ 2
#define T_ 1024
#define D_ 1024
#define H_ 16
#define HD_ 64
#define F_ 4096
#define V_ 50257
#define VPAD_ 50304
#define BT_ (B_*T_)

// ================= scratch (__device__ globals) =================
__device__ float g_x  [BT_*D_];
__device__ float g_qkv[BT_*3072];
__device__ float g_att[(size_t)B_*H_*T_*T_];

__device__ __align__(256) __half g_hh [BT_*D_];
__device__ __align__(256) __half g_obh[BT_*D_];
__device__ __align__(256) __half g_mph[BT_*F_];

// attention operands
__device__ __align__(256) __half g_qTh[BT_*D_];
__device__ __align__(256) __half g_qTl[BT_*D_];
__device__ __align__(256) __half g_kTh[BT_*D_];          // K single fp16
__device__ __align__(256) __half g_vTh[BT_*D_];          // V single fp16, [B,H,HD,T]
__device__ __align__(256) __half g_ph [(size_t)B_*H_*T_*T_];

// converted+transposed weights [N,K] layout, single fp16
__device__ __align__(256) __half g_wqkv[(size_t)L_*3072*D_];
__device__ __align__(256) __half g_wo  [(size_t)L_*D_*D_];
__device__ __align__(256) __half g_w1  [(size_t)L_*F_*D_];
__device__ __align__(256) __half g_w2  [(size_t)L_*D_*F_];
__device__ __align__(256) __half g_wlm [(size_t)VPAD_*D_];

// ================= small helpers =================
__device__ __forceinline__ uint32_t smem_u32(const void* p) {
    uint32_t a;
    asm("{ .reg .u64 t; cvta.to.shared.u64 t, %1; cvt.u32.u64 %0, t; }" : "=r"(a) : "l"(p));
    return a;
}
__device__ __forceinline__ void fp16_split(float v, __half& hi, __half& lo) {
    hi = __float2half(v);
    lo = __float2half(v - __half2float(hi));
}

// ================= elementwise / conversion kernels =================
__global__ void embed_kernel(const int* __restrict__ ids, const float* __restrict__ emb,
                             const float* __restrict__ pos, float* __restrict__ x) {
    int idx = blockIdx.x * 256 + threadIdx.x;
    int row = idx >> 10;
    int c   = idx & 1023;
    int t   = row & (T_-1);
    x[idx] = emb[(size_t)ids[row]*D_ + c] + pos[(size_t)t*D_ + c];
}

// W [K,N] fp32 -> out [Npad,K] fp16 (transposed, zero-padded), batched over z
__global__ void wconv_kernel(const float* __restrict__ W, __half* __restrict__ oh,
                             int K, int N, long long srcStride, long long dstStride) {
    __shared__ float tile[32][33];
    const float* Ws = W + (size_t)blockIdx.z * srcStride;
    __half* ohz = oh + (size_t)blockIdx.z * dstStride;
    int n0 = blockIdx.x * 32, k0 = blockIdx.y * 32;
    #pragma unroll
    for (int j = 0; j < 32; j += 8) {
        int kk = k0 + threadIdx.y + j;
        int nn = n0 + threadIdx.x;
        tile[threadIdx.y + j][threadIdx.x] = (nn < N) ? Ws[(size_t)kk*N + nn] : 0.f;
    }
    __syncthreads();
    #pragma unroll
    for (int j = 0; j < 32; j += 8) {
        int nn = n0 + threadIdx.y + j;
        int kk = k0 + threadIdx.x;
        ohz[(size_t)nn*K + kk] = __float2half(tile[threadIdx.x][threadIdx.y + j]);
    }
}

// Wq/Wk/Wv [L][K,N] fp32 -> g_wqkv [L][3072,K] fp16, z in [0, 3L)
__global__ void wconv3_kernel(const float* __restrict__ Wq, const float* __restrict__ Wk,
                              const float* __restrict__ Wv, __half* __restrict__ dst) {
    __shared__ float tile[32][33];
    int z = blockIdx.z;
    int l = z / 3, sel = z % 3;
    const float* Ws = (sel == 0 ? Wq : sel == 1 ? Wk : Wv) + (size_t)l * D_ * D_;
    __half* od = dst + ((size_t)l * 3072 + sel * D_) * D_;
    int n0 = blockIdx.x * 32, k0 = blockIdx.y * 32;
    #pragma unroll
    for (int j = 0; j < 32; j += 8) {
        tile[threadIdx.y + j][threadIdx.x] = Ws[(size_t)(k0 + threadIdx.y + j)*D_ + n0 + threadIdx.x];
    }
    __syncthreads();
    #pragma unroll
    for (int j = 0; j < 32; j += 8) {
        int nn = n0 + threadIdx.y + j;
        int kk = k0 + threadIdx.x;
        od[(size_t)nn*D_ + kk] = __float2half(tile[threadIdx.x][threadIdx.y + j]);
    }
}

// rmsnorm writing fp16 hi only
__global__ void rmsnorm_h_kernel(const float* __restrict__ x, const float* __restrict__ w,
                                 __half* __restrict__ oh) {
    __shared__ float red[256];
    int row = blockIdx.x;
    const float* xr = x + (size_t)row * D_;
    float v[4]; float ss = 0.f;
    #pragma unroll
    for (int i = 0; i < 4; i++) { v[i] = xr[threadIdx.x + 256*i]; ss += v[i]*v[i]; }
    red[threadIdx.x] = ss; __syncthreads();
    for (int s = 128; s > 0; s >>= 1) {
        if (threadIdx.x < s) red[threadIdx.x] += red[threadIdx.x + s];
        __syncthreads();
    }
    float r = rsqrtf(red[0] / (float)D_ + 1e-5f);
    #pragma unroll
    for (int i = 0; i < 4; i++) {
        int c = threadIdx.x + 256*i;
        oh[(size_t)row*D_ + c] = __float2half(w[c] * v[i] * r);
    }
}

// fused QK-norm: each warp handles one (b,t,h): Q row (hi+lo) and K row (hi only)
__global__ void qknorm2_kernel(const float* __restrict__ qkv,
                               const float* __restrict__ qw, const float* __restrict__ kw,
                               __half* __restrict__ qh, __half* __restrict__ ql,
                               __half* __restrict__ kh) {
    int warp = (blockIdx.x * blockDim.x + threadIdx.x) >> 5;
    int lane = threadIdx.x & 31;
    int h  = warp & (H_-1);
    int bt = warp >> 4;
    int t  = bt & (T_-1);
    int b  = bt >> 10;
    size_t dst = ((size_t)((b*H_ + h)*T_ + t)) * HD_;

    // Q (hi + lo)
    {
        const float* src = qkv + (size_t)bt * 3072 + h * HD_;
        float x0 = src[lane], x1 = src[lane + 32];
        float ss = x0*x0 + x1*x1;
        #pragma unroll
        for (int o = 16; o > 0; o >>= 1) ss += __shfl_xor_sync(0xffffffffu, ss, o);
        float r = rsqrtf(ss / (float)HD_ + 1e-5f);
        float y0 = qw[lane] * x0 * r;
        float y1 = qw[lane + 32] * x1 * r;
        __half h0 = __float2half(y0);
        __half h1 = __float2half(y1);
        qh[dst + lane]      = h0;
        qh[dst + lane + 32] = h1;
        ql[dst + lane]      = __float2half(y0 - __half2float(h0));
        ql[dst + lane + 32] = __float2half(y1 - __half2float(h1));
    }
    // K (hi only)
    {
        const float* src = qkv + (size_t)bt * 3072 + 1024 + h * HD_;
        float x0 = src[lane], x1 = src[lane + 32];
        float ss = x0*x0 + x1*x1;
        #pragma unroll
        for (int o = 16; o > 0; o >>= 1) ss += __shfl_xor_sync(0xffffffffu, ss, o);
        float r = rsqrtf(ss / (float)HD_ + 1e-5f);
        kh[dst + lane]      = __float2half(kw[lane] * x0 * r);
        kh[dst + lane + 32] = __float2half(kw[lane + 32] * x1 * r);
    }
}

// V: [B,T,3D](col 2048+) -> [B,H,HD,T] single fp16 via 32x32 tile transpose
__global__ void vtrans_kernel(const float* __restrict__ qkv, __half* __restrict__ vh) {
    __shared__ float tile[32][33];
    int z = blockIdx.z;           // b*H+h
    int b = z >> 4, h = z & 15;
    int t0 = blockIdx.x * 32, d0 = blockIdx.y * 32;
    #pragma unroll
    for (int j = 0; j < 32; j += 8) {
        int t = t0 + threadIdx.y + j;
        tile[threadIdx.y + j][threadIdx.x] =
            qkv[(size_t)(b*T_ + t)*3072 + 2048 + h*HD_ + d0 + threadIdx.x];
    }
    __syncthreads();
    #pragma unroll
    for (int j = 0; j < 32; j += 8) {
        int d = d0 + threadIdx.y + j;
        size_t o = ((size_t)z * HD_ + d) * T_ + t0 + threadIdx.x;
        vh[o] = __float2half(tile[threadIdx.x][threadIdx.y + j]);
    }
}

// causal softmax, scale 1/8, per-head gate; writes P fp16 hi only up to qlim
__global__ void softmax_kernel(const float* __restrict__ S, const float* __restrict__ gate,
                               __half* __restrict__ ph) {
    __shared__ float red[256];
    int row = blockIdx.x;
    int q = row & (T_-1);
    int h = (row >> 10) & (H_-1);
    const float* s = S + (size_t)row * T_;
    const float scale = 0.125f;
    float vals[4]; float m = -3.4e38f;
    #pragma unroll
    for (int i = 0; i < 4; i++) {
        int j = threadIdx.x + 256*i;
        float v = (j <= q) ? s[j] * scale : -3.4e38f;
        vals[i] = v; m = fmaxf(m, v);
    }
    red[threadIdx.x] = m; __syncthreads();
    for (int t = 128; t > 0; t >>= 1) {
        if (threadIdx.x < t) red[threadIdx.x] = fmaxf(red[threadIdx.x], red[threadIdx.x + t]);
        __syncthreads();
    }
    m = red[0]; __syncthreads();
    float sum = 0.f;
    #pragma unroll
    for (int i = 0; i < 4; i++) {
        int j = threadIdx.x + 256*i;
        float e = (j <= q) ? __expf(vals[i] - m) : 0.f;
        vals[i] = e; sum += e;
    }
    red[threadIdx.x] = sum; __syncthreads();
    for (int t = 128; t > 0; t >>= 1) {
        if (threadIdx.x < t) red[threadIdx.x] += red[threadIdx.x + t];
        __syncthreads();
    }
    float inv = gate[h] / red[0];
    int qlim = (q & ~63) + 64;
    #pragma unroll
    for (int i = 0; i < 4; i++) {
        int j = threadIdx.x + 256*i;
        if (j < qlim) {
            ph[(size_t)row*T_ + j] = __float2half(vals[i] * inv);
        }
    }
}

// ================= shared HMMA building blocks =================
#define HG_ROWB 80

__device__ __forceinline__ void hg_ldm4(uint32_t addr, uint32_t* r) {
    asm volatile("ldmatrix.sync.aligned.m8n8.x4.shared.b16 {%0,%1,%2,%3}, [%4];"
        : "=r"(r[0]), "=r"(r[1]), "=r"(r[2]), "=r"(r[3]) : "r"(addr));
}
__device__ __forceinline__ void hg_mma(float* d, const uint32_t* a, uint32_t b0, uint32_t b1) {
    asm volatile("mma.sync.aligned.m16n8k16.row.col.f32.f16.f16.f32 "
        "{%0,%1,%2,%3}, {%4,%5,%6,%7}, {%8,%9}, {%0,%1,%2,%3};"
        : "+f"(d[0]), "+f"(d[1]), "+f"(d[2]), "+f"(d[3])
        : "r"(a[0]), "r"(a[1]), "r"(a[2]), "r"(a[3]), "r"(b0), "r"(b1));
}

// load TERMS*A-tiles + B-tile into one stage
template<int BM, int BN, int TERMS>
__device__ __forceinline__ void hg_load2(uint32_t stg,
    const __half* Ah, const __half* Al, const __half* Bh,
    int m0, int n0, int K, int k0, int tid)
{
    constexpr int CA = BM * 4;         // 16B chunks per A matrix
    constexpr int CB = BN * 4;
    constexpr int TOT = TERMS*CA + CB;
    #pragma unroll
    for (int p = 0; p < TOT/256; p++) {
        int c = tid + p * 256;
        const __half* base; int r0; uint32_t mo; int rr;
        if (c < CA)                          { base = Ah; r0 = m0; mo = 0;                 rr = c; }
        else if (TERMS == 2 && c < 2*CA)     { base = Al; r0 = m0; mo = BM*HG_ROWB;        rr = c - CA; }
        else                                 { base = Bh; r0 = n0; mo = TERMS*BM*HG_ROWB;  rr = c - TERMS*CA; }
        int r = rr >> 2, kc = rr & 3;
        uint32_t so = stg + mo + r * HG_ROWB + kc * 16;
        const void* ga = (const void*)(base + (size_t)(r0 + r) * K + k0 + kc * 8);
        asm volatile("cp.async.cg.shared.global [%0], [%1], 16;\n" :: "r"(so), "l"(ga));
    }
    asm volatile("cp.async.commit_group;\n" ::: "memory");
}

// ======== dense GEMM: BMx128 tile, pair double-buffer, TERMS A-side terms ========
// BM=128: warps 4(M)x2(N), warp tile 32x64. BM=64: warps 2(M)x4(N), warp tile 32x32.
// C[M,N] = (Ah[+Al])[M,K] @ Bh[N,K]^T.  MODE: 0=plain(guard Nout), 1=+RES, 2=GELU->fp16 hi
template<int MODE, int TERMS, int BM>
__global__ __launch_bounds__(256, 2)
void hgemmd_kernel(const __half* __restrict__ Ah, const __half* __restrict__ Al,
                   const __half* __restrict__ Bh,
                   const float* __restrict__ AUX, float* __restrict__ C,
                   __half* __restrict__ Gh,
                   int K, int Nout, int ldc)
{
    constexpr int BN = 128;
    constexpr int MATA  = BM * HG_ROWB;
    constexpr int STAGE = (TERMS*BM + BN) * HG_ROWB;
    constexpr int MI = 2;                       // both layouts use 32-row warp M tiles
    constexpr int NJ = (BM == 64) ? 4 : 8;
    constexpr int NT = (BM == 64) ? 2 : 4;

    extern __shared__ char dsm[];
    uint32_t sb = smem_u32(dsm);

    const int tid  = threadIdx.x;
    const int lane = tid & 31;
    const int wid  = tid >> 5;
    const int warpM = (BM == 64) ? (wid & 1) * 32 : (wid & 3) * 32;
    const int warpN = (BM == 64) ? (wid >> 1) * 32 : (wid >> 2) * 64;

    const int m0 = blockIdx.y * BM;
    const int n0 = blockIdx.x * BN;

    const uint32_t aoff = (uint32_t)((lane & 15) * HG_ROWB + (lane >> 4) * 16);
    const uint32_t boff = (uint32_t)(((lane & 7) + ((lane >> 4) & 1) * 8) * HG_ROWB
                                     + ((lane >> 3) & 1) * 16);

    float acc[MI][NJ][4];
    #pragma unroll
    for (int i = 0; i < MI; i++)
        #pragma unroll
        for (int j = 0; j < NJ; j++)
            #pragma unroll
            for (int u = 0; u < 4; u++) acc[i][j][u] = 0.f;

    const int nk = K / 32;          // even, >= 4
    const int np = nk / 2;

    hg_load2<BM,BN,TERMS>(sb,          Ah, Al, Bh, m0, n0, K, 0,  tid);
    hg_load2<BM,BN,TERMS>(sb + STAGE,  Ah, Al, Bh, m0, n0, K, 32, tid);

    for (int ip = 0; ip < np; ip++) {
        int c0 = 2 * ip;
        asm volatile("cp.async.wait_group 0;\n" ::: "memory");
        __syncthreads();
        if (c0 + 2 < nk) {
            hg_load2<BM,BN,TERMS>(sb + ((c0 + 2) & 3) * STAGE, Ah, Al, Bh, m0, n0, K, (c0 + 2) * 32, tid);
            hg_load2<BM,BN,TERMS>(sb + ((c0 + 3) & 3) * STAGE, Ah, Al, Bh, m0, n0, K, (c0 + 3) * 32, tid);
        }

        #pragma unroll
        for (int half = 0; half < 2; half++) {
            uint32_t st  = sb + ((c0 + half) & 3) * STAGE;
            uint32_t sAh = st;
            uint32_t sAl = st + MATA;
            uint32_t sBh = st + TERMS*MATA;
            #pragma unroll
            for (int kq = 0; kq < 2; kq++) {
                uint32_t kb = kq * 32;
                uint32_t ah[MI][4], al[MI][4], bh[NT][4];
                #pragma unroll
                for (int mi = 0; mi < MI; mi++) {
                    uint32_t rb = (uint32_t)((warpM + mi * 16) * HG_ROWB) + kb;
                    hg_ldm4(sAh + rb + aoff, ah[mi]);
                    if (TERMS == 2) hg_ldm4(sAl + rb + aoff, al[mi]);
                }
                #pragma unroll
                for (int nt = 0; nt < NT; nt++) {
                    uint32_t rbn = (uint32_t)((warpN + nt * 16) * HG_ROWB) + kb;
                    hg_ldm4(sBh + rbn + boff, bh[nt]);
                }
                #pragma unroll
                for (int mi = 0; mi < MI; mi++) {
                    #pragma unroll
                    for (int nj = 0; nj < NJ; nj++) {
                        uint32_t b0 = bh[nj >> 1][(nj & 1) * 2];
                        uint32_t b1 = bh[nj >> 1][(nj & 1) * 2 + 1];
                        hg_mma(acc[mi][nj], ah[mi], b0, b1);
                        if (TERMS == 2) hg_mma(acc[mi][nj], al[mi], b0, b1);
                    }
                }
            }
        }
    }

    // epilogue
    const int g = lane >> 2;
    const int tq = lane & 3;
    #pragma unroll
    for (int mi = 0; mi < MI; mi++) {
        int row0 = m0 + warpM + mi * 16 + g;
        int row1 = row0 + 8;
        #pragma unroll
        for (int nj = 0; nj < NJ; nj++) {
            int col = n0 + warpN + nj * 8 + tq * 2;
            float* a = acc[mi][nj];
            if (MODE == 1) {
                size_t o0 = (size_t)row0 * ldc + col;
                size_t o1 = (size_t)row1 * ldc + col;
                C[o0]     = a[0] + AUX[o0];
                C[o0 + 1] = a[1] + AUX[o0 + 1];
                C[o1]     = a[2] + AUX[o1];
                C[o1 + 1] = a[3] + AUX[o1 + 1];
            } else if (MODE == 2) {
                #pragma unroll
                for (int half = 0; half < 2; half++) {
                    int r = half ? row1 : row0;
                    float v0 = a[half * 2], v1 = a[half * 2 + 1];
                    float g0 = 0.5f * v0 * (1.0f + erff(v0 * 0.70710678118654752f));
                    float g1 = 0.5f * v1 * (1.0f + erff(v1 * 0.70710678118654752f));
                    __half2 hp; hp.x = __float2half(g0); hp.y = __float2half(g1);
                    *(__half2*)&Gh[(size_t)r * ldc + col] = hp;
                }
            } else {
                if (col < Nout) {
                    C[(size_t)row0 * ldc + col] = a[0];
                    C[(size_t)row1 * ldc + col] = a[2];
                }
                if (col + 1 < Nout) {
                    C[(size_t)row0 * ldc + col + 1] = a[1];
                    C[(size_t)row1 * ldc + col + 1] = a[3];
                }
            }
        }
    }
}

// ======== attention GEMM (scores / PV): 3-stage, batched, TERMS A-side terms ========
// MODE: 0 = fp32 store, 3 = PV merge->fp16 hi only
template<int BM, int BN, int MODE, bool CSKIP, bool CKLIM, int TERMS>
__global__ __launch_bounds__(256, 2)
void hgemm2_kernel(const __half* __restrict__ Ah, const __half* __restrict__ Al,
                   const __half* __restrict__ Bh,
                   const float* __restrict__ AUX, float* __restrict__ C,
                   __half* __restrict__ Gh,
                   int K, int Nout, int ldc,
                   long long sA, long long sB, long long sC)
{
    constexpr int MATA  = BM * HG_ROWB;
    constexpr int STAGE = (TERMS*BM + BN) * HG_ROWB;
    constexpr int MI = BM / 64;
    constexpr int NJ = BN / 16;
    constexpr int NT = BN / 32;

    extern __shared__ char dsm[];
    uint32_t sb = smem_u32(dsm);

    const int tid  = threadIdx.x;
    const int lane = tid & 31;
    const int wid  = tid >> 5;
    const int warpM = (wid & 3) * (BM/4);
    const int warpN = (wid >> 2) * (BN/2);

    const int m0 = blockIdx.y * BM;
    const int n0 = blockIdx.x * BN;
    if (CSKIP && n0 > m0 + BM - 1) return;

    const int z = blockIdx.z;
    Ah += (size_t)z * sA;
    if (TERMS == 2) Al += (size_t)z * sA;
    Bh += (size_t)z * sB;
    if (MODE == 0) C += (size_t)z * sC;

    const uint32_t aoff = (uint32_t)((lane & 15) * HG_ROWB + (lane >> 4) * 16);
    const uint32_t boff = (uint32_t)(((lane & 7) + ((lane >> 4) & 1) * 8) * HG_ROWB
                                     + ((lane >> 3) & 1) * 16);

    float acc[MI][NJ][4];
    #pragma unroll
    for (int i = 0; i < MI; i++)
        #pragma unroll
        for (int j = 0; j < NJ; j++)
            #pragma unroll
            for (int u = 0; u < 4; u++) acc[i][j][u] = 0.f;

    const int kend = CKLIM ? (K < m0 + BM ? K : m0 + BM) : K;
    const int nk = kend / 32;

    hg_load2<BM,BN,TERMS>(sb,          Ah, Al, Bh, m0, n0, K, 0,  tid);
    if (nk > 1)
        hg_load2<BM,BN,TERMS>(sb + STAGE, Ah, Al, Bh, m0, n0, K, 32, tid);

    for (int it = 0; it < nk; it++) {
        int s = it % 3;
        if (it + 1 < nk) {
            asm volatile("cp.async.wait_group 1;\n" ::: "memory");
        } else {
            asm volatile("cp.async.wait_group 0;\n" ::: "memory");
        }
        __syncthreads();
        if (it + 2 < nk) {
            hg_load2<BM,BN,TERMS>(sb + ((it + 2) % 3) * STAGE, Ah, Al, Bh, m0, n0, K, (it + 2) * 32, tid);
        }

        uint32_t st  = sb + s * STAGE;
        uint32_t sAh = st;
        uint32_t sAl = st + MATA;
        uint32_t sBh = st + TERMS*MATA;

        #pragma unroll
        for (int kq = 0; kq < 2; kq++) {
            uint32_t kb = kq * 32;
            uint32_t ah[MI][4], al[MI][4], bh[NT][4];
            #pragma unroll
            for (int mi = 0; mi < MI; mi++) {
                uint32_t rb = (uint32_t)((warpM + mi * 16) * HG_ROWB) + kb;
                hg_ldm4(sAh + rb + aoff, ah[mi]);
                if (TERMS == 2) hg_ldm4(sAl + rb + aoff, al[mi]);
            }
            #pragma unroll
            for (int nt = 0; nt < NT; nt++) {
                uint32_t rb = (uint32_t)((warpN + nt * 16) * HG_ROWB) + kb;
                hg_ldm4(sBh + rb + boff, bh[nt]);
            }
            #pragma unroll
            for (int mi = 0; mi < MI; mi++) {
                #pragma unroll
                for (int nj = 0; nj < NJ; nj++) {
                    uint32_t b0 = bh[nj >> 1][(nj & 1) * 2];
                    uint32_t b1 = bh[nj >> 1][(nj & 1) * 2 + 1];
                    hg_mma(acc[mi][nj], ah[mi], b0, b1);
                    if (TERMS == 2) hg_mma(acc[mi][nj], al[mi], b0, b1);
                }
            }
        }
    }

    const int g = lane >> 2;
    const int tq = lane & 3;
    #pragma unroll
    for (int mi = 0; mi < MI; mi++) {
        int row0 = m0 + warpM + mi * 16 + g;
        int row1 = row0 + 8;
        #pragma unroll
        for (int nj = 0; nj < NJ; nj++) {
            int col = n0 + warpN + nj * 8 + tq * 2;
            float* a = acc[mi][nj];
            if (MODE == 3) {
                int b  = z >> 4, h = z & 15;
                #pragma unroll
                for (int half = 0; half < 2; half++) {
                    int q = half ? row1 : row0;
                    size_t vsrc = (size_t)(b*T_ + q)*3072 + 2048 + h*HD_ + col;
                    float v0 = a[half * 2]     + AUX[vsrc];
                    float v1 = a[half * 2 + 1] + AUX[vsrc + 1];
                    __half2 hp; hp.x = __float2half(v0); hp.y = __float2half(v1);
                    *(__half2*)&Gh[(size_t)(b*T_ + q)*D_ + h*HD_ + col] = hp;
                }
            } else {
                C[(size_t)row0 * ldc + col] = a[0];
                C[(size_t)row0 * ldc + col + 1] = a[1];
                C[(size_t)row1 * ldc + col] = a[2];
                C[(size_t)row1 * ldc + col + 1] = a[3];
            }
        }
    }
}

// ================= launcher =================
extern "C" void kernel_launch(void* const* d_in, const int* in_sizes, int n_in,
                              void* d_out, int out_size) {
    const int*   ids   = (const int*)  d_in[0];
    const float* embed = (const float*)d_in[1];
    const float* pos   = (const float*)d_in[2];
    const float* Wq    = (const float*)d_in[3];
    const float* Wk    = (const float*)d_in[4];
    const float* Wv    = (const float*)d_in[5];
    const float* Wo    = (const float*)d_in[6];
    const float* ln1   = (const float*)d_in[7];
    const float* ln2   = (const float*)d_in[8];
    const float* qnw   = (const float*)d_in[9];
    const float* knw   = (const float*)d_in[10];
    const float* gate  = (const float*)d_in[11];
    const float* W1    = (const float*)d_in[12];
    const float* W2    = (const float*)d_in[13];
    const float* lnf   = (const float*)d_in[14];
    const float* Wlm   = (const float*)d_in[15];
    float* out = (float*)d_out;

    float *x,*qkv,*att;
    __half *hh,*obh,*mph;
    __half *qTh,*qTl,*kTh,*vTh,*ph;
    __half *wqkv,*wo,*w1,*w2,*wlm;
    cudaGetSymbolAddress((void**)&x,   g_x);
    cudaGetSymbolAddress((void**)&qkv, g_qkv);
    cudaGetSymbolAddress((void**)&att, g_att);
    cudaGetSymbolAddress((void**)&hh,  g_hh);
    cudaGetSymbolAddress((void**)&obh, g_obh);
    cudaGetSymbolAddress((void**)&mph, g_mph);
    cudaGetSymbolAddress((void**)&qTh, g_qTh);
    cudaGetSymbolAddress((void**)&qTl, g_qTl);
    cudaGetSymbolAddress((void**)&kTh, g_kTh);
    cudaGetSymbolAddress((void**)&vTh, g_vTh);
    cudaGetSymbolAddress((void**)&ph,  g_ph);
    cudaGetSymbolAddress((void**)&wqkv, g_wqkv);
    cudaGetSymbolAddress((void**)&wo,  g_wo);
    cudaGetSymbolAddress((void**)&w1,  g_w1);
    cudaGetSymbolAddress((void**)&w2,  g_w2);
    cudaGetSymbolAddress((void**)&wlm, g_wlm);

    const int SD1_128 = 4 * (1*128 + 128) * HG_ROWB;   // 81920 (1-term, BM=128)
    const int SD1_64  = 4 * (1*64  + 128) * HG_ROWB;   // 61440 (1-term, BM=64)
    const int S128128 = 3 * (2*128 + 128) * HG_ROWB;   // 92160 (scores, 2-term)
    const int S6464_1 = 3 * (1*64  + 64 ) * HG_ROWB;   // 30720 (PV, 1-term)
    cudaFuncSetAttribute(hgemmd_kernel<0,1,128>, cudaFuncAttributeMaxDynamicSharedMemorySize, SD1_128);
    cudaFuncSetAttribute(hgemmd_kernel<2,1,128>, cudaFuncAttributeMaxDynamicSharedMemorySize, SD1_128);
    cudaFuncSetAttribute(hgemmd_kernel<1,1,64>,  cudaFuncAttributeMaxDynamicSharedMemorySize, SD1_64);
    cudaFuncSetAttribute(hgemm2_kernel<128,128,0,true, false,2>, cudaFuncAttributeMaxDynamicSharedMemorySize, S128128);
    cudaFuncSetAttribute(hgemm2_kernel<64, 64, 3,false,true ,1>, cudaFuncAttributeMaxDynamicSharedMemorySize, S6464_1);

    const long long sQK = (long long)T_ * HD_;
    const long long sS  = (long long)T_ * T_;
    dim3 wb(32, 8);

    embed_kernel<<<BT_*D_/256, 256>>>(ids, embed, pos, x);
    rmsnorm_h_kernel<<<BT_, 256>>>(x, ln1, hh);
    wconv3_kernel<<<dim3(D_/32, D_/32, 3*L_), wb>>>(Wq, Wk, Wv, wqkv);
    // fused QKV layer 0 (1-term, BM=128)
    hgemmd_kernel<0,1,128><<<dim3(3072/128, BT_/128), 256, SD1_128>>>(
        hh, nullptr, wqkv, nullptr, qkv, nullptr, D_, 3072, 3072);

    // remaining weight conversions
    wconv_kernel<<<dim3(D_/32, D_/32, L_), wb>>>(Wo, wo, D_, D_, (long long)D_*D_, (long long)D_*D_);
    wconv_kernel<<<dim3(F_/32, D_/32, L_), wb>>>(W1, w1, D_, F_, (long long)D_*F_, (long long)F_*D_);
    wconv_kernel<<<dim3(D_/32, F_/32, L_), wb>>>(W2, w2, F_, D_, (long long)F_*D_, (long long)D_*F_);
    wconv_kernel<<<dim3(VPAD_/32, D_/32, 1), wb>>>(Wlm, wlm, D_, V_, 0, 0);

    for (int l = 0; l < L_; l++) {
        // fused QK-norm (Q hi/lo, K hi) + V transpose
        qknorm2_kernel<<<(B_*T_*H_)/8, 256>>>(qkv, qnw + (size_t)l*HD_, knw + (size_t)l*HD_,
                                              qTh, qTl, kTh);
        vtrans_kernel<<<dim3(T_/32, HD_/32, B_*H_), dim3(32,8)>>>(qkv, vTh);

        // scores: per (b,h) Q[1024,64] @ K[1024,64]^T, causal tile-skip (2-term A)
        hgemm2_kernel<128,128,0,true,false,2><<<dim3(T_/128, T_/128, B_*H_), 256, S128128>>>(
            qTh, qTl, kTh, nullptr, att, nullptr, HD_, T_, T_, sQK, sQK, sS);

        softmax_kernel<<<B_*H_*T_, 256>>>(att, gate + (size_t)l*H_, ph);

        // PV: per (b,h) P[1024,1024] @ V^T, causal K-limit, fused vres merge (1-term, hi only)
        hgemm2_kernel<64,64,3,false,true,1><<<dim3(1, T_/64, B_*H_), 256, S6464_1>>>(
            ph, nullptr, vTh, qkv, nullptr, obh, T_, HD_, HD_, sS, sQK, 0);

        // Wo with fused residual into x (1-term, BM=64, 2x4 warp layout)
        hgemmd_kernel<1,1,64><<<dim3(D_/128, BT_/64), 256, SD1_64>>>(
            obh, nullptr, wo + (size_t)l*D_*D_, x, x, nullptr, D_, D_, D_);

        // MLP: W1 1-term BM=128 (GELU -> hi only), W2 1-term BM=64
        rmsnorm_h_kernel<<<BT_, 256>>>(x, ln2 + (size_t)l*D_, hh);
        hgemmd_kernel<2,1,128><<<dim3(F_/128, BT_/128), 256, SD1_128>>>(
            hh, nullptr, w1 + (size_t)l*F_*D_, nullptr, nullptr, mph, D_, F_, F_);
        hgemmd_kernel<1,1,64><<<dim3(D_/128, BT_/64), 256, SD1_64>>>(
            mph, nullptr, w2 + (size_t)l*D_*F_, x, x, nullptr, F_, D_, D_);

        // next layer's pre-attention norm + QKV (1-term BM=128)
        if (l + 1 < L_) {
            rmsnorm_h_kernel<<<BT_, 256>>>(x, ln1 + (size_t)(l+1)*D_, hh);
            hgemmd_kernel<0,1,128><<<dim3(3072/128, BT_/128), 256, SD1_128>>>(
                hh, nullptr, wqkv + (size_t)(l+1)*3072*D_, nullptr, qkv, nullptr,
                D_, 3072, 3072);
        }
    }

    rmsnorm_h_kernel<<<BT_, 256>>>(x, lnf, hh);
    // LM head (1-term BM=128)
    hgemmd_kernel<0,1,128><<<dim3(VPAD_/128, BT_/128), 256, SD1_128>>>(
        hh, nullptr, wlm, nullptr, out, nullptr, D_, V_, V_);
}

// round 15
// speedup vs baseline: 1.7328x; 1.2241x over previous
#include <cuda_runtime.h>
#include <cuda_fp16.h>
#include <math.h>
#include <stdint.h>

// Problem dims
#define L_ 12
#define B_ 2
#define T_ 1024
#define D_ 1024
#define H_ 16
#define HD_ 64
#define F_ 4096
#define V_ 50257
#define VPAD_ 50304
#define BT_ (B_*T_)

// ================= scratch (__device__ globals) =================
__device__ float g_x  [BT_*D_];
__device__ float g_qkv[BT_*3072];

__device__ __align__(256) __half g_hh [BT_*D_];
__device__ __align__(256) __half g_obh[BT_*D_];
__device__ __align__(256) __half g_mph[BT_*F_];

// attention operands
__device__ __align__(256) __half g_qTh[BT_*D_];
__device__ __align__(256) __half g_qTl[BT_*D_];
__device__ __align__(256) __half g_kTh[BT_*D_];          // K single fp16, [B,H,T,HD]
__device__ __align__(256) __half g_vTh[BT_*D_];          // V single fp16, [B,H,HD,T]

// converted+transposed weights [N,K] layout, single fp16
__device__ __align__(256) __half g_wqkv[(size_t)L_*3072*D_];
__device__ __align__(256) __half g_wo  [(size_t)L_*D_*D_];
__device__ __align__(256) __half g_w1  [(size_t)L_*F_*D_];
__device__ __align__(256) __half g_w2  [(size_t)L_*D_*F_];
__device__ __align__(256) __half g_wlm [(size_t)VPAD_*D_];

// ================= small helpers =================
__device__ __forceinline__ uint32_t smem_u32(const void* p) {
    uint32_t a;
    asm("{ .reg .u64 t; cvta.to.shared.u64 t, %1; cvt.u32.u64 %0, t; }" : "=r"(a) : "l"(p));
    return a;
}
__device__ __forceinline__ void fp16_split(float v, __half& hi, __half& lo) {
    hi = __float2half(v);
    lo = __float2half(v - __half2float(hi));
}

// ================= elementwise / conversion kernels =================
__global__ void embed_kernel(const int* __restrict__ ids, const float* __restrict__ emb,
                             const float* __restrict__ pos, float* __restrict__ x) {
    int idx = blockIdx.x * 256 + threadIdx.x;
    int row = idx >> 10;
    int c   = idx & 1023;
    int t   = row & (T_-1);
    x[idx] = emb[(size_t)ids[row]*D_ + c] + pos[(size_t)t*D_ + c];
}

__global__ void wconv_kernel(const float* __restrict__ W, __half* __restrict__ oh,
                             int K, int N, long long srcStride, long long dstStride) {
    __shared__ float tile[32][33];
    const float* Ws = W + (size_t)blockIdx.z * srcStride;
    __half* ohz = oh + (size_t)blockIdx.z * dstStride;
    int n0 = blockIdx.x * 32, k0 = blockIdx.y * 32;
    #pragma unroll
    for (int j = 0; j < 32; j += 8) {
        int kk = k0 + threadIdx.y + j;
        int nn = n0 + threadIdx.x;
        tile[threadIdx.y + j][threadIdx.x] = (nn < N) ? Ws[(size_t)kk*N + nn] : 0.f;
    }
    __syncthreads();
    #pragma unroll
    for (int j = 0; j < 32; j += 8) {
        int nn = n0 + threadIdx.y + j;
        int kk = k0 + threadIdx.x;
        ohz[(size_t)nn*K + kk] = __float2half(tile[threadIdx.x][threadIdx.y + j]);
    }
}

__global__ void wconv3_kernel(const float* __restrict__ Wq, const float* __restrict__ Wk,
                              const float* __restrict__ Wv, __half* __restrict__ dst) {
    __shared__ float tile[32][33];
    int z = blockIdx.z;
    int l = z / 3, sel = z % 3;
    const float* Ws = (sel == 0 ? Wq : sel == 1 ? Wk : Wv) + (size_t)l * D_ * D_;
    __half* od = dst + ((size_t)l * 3072 + sel * D_) * D_;
    int n0 = blockIdx.x * 32, k0 = blockIdx.y * 32;
    #pragma unroll
    for (int j = 0; j < 32; j += 8) {
        tile[threadIdx.y + j][threadIdx.x] = Ws[(size_t)(k0 + threadIdx.y + j)*D_ + n0 + threadIdx.x];
    }
    __syncthreads();
    #pragma unroll
    for (int j = 0; j < 32; j += 8) {
        int nn = n0 + threadIdx.y + j;
        int kk = k0 + threadIdx.x;
        od[(size_t)nn*D_ + kk] = __float2half(tile[threadIdx.x][threadIdx.y + j]);
    }
}

__global__ void rmsnorm_h_kernel(const float* __restrict__ x, const float* __restrict__ w,
                                 __half* __restrict__ oh) {
    __shared__ float red[256];
    int row = blockIdx.x;
    const float* xr = x + (size_t)row * D_;
    float v[4]; float ss = 0.f;
    #pragma unroll
    for (int i = 0; i < 4; i++) { v[i] = xr[threadIdx.x + 256*i]; ss += v[i]*v[i]; }
    red[threadIdx.x] = ss; __syncthreads();
    for (int s = 128; s > 0; s >>= 1) {
        if (threadIdx.x < s) red[threadIdx.x] += red[threadIdx.x + s];
        __syncthreads();
    }
    float r = rsqrtf(red[0] / (float)D_ + 1e-5f);
    #pragma unroll
    for (int i = 0; i < 4; i++) {
        int c = threadIdx.x + 256*i;
        oh[(size_t)row*D_ + c] = __float2half(w[c] * v[i] * r);
    }
}

// fused QK-norm: Q row (hi+lo) and K row (hi only), one warp per (b,t,h)
__global__ void qknorm2_kernel(const float* __restrict__ qkv,
                               const float* __restrict__ qw, const float* __restrict__ kw,
                               __half* __restrict__ qh, __half* __restrict__ ql,
                               __half* __restrict__ kh) {
    int warp = (blockIdx.x * blockDim.x + threadIdx.x) >> 5;
    int lane = threadIdx.x & 31;
    int h  = warp & (H_-1);
    int bt = warp >> 4;
    int t  = bt & (T_-1);
    int b  = bt >> 10;
    size_t dst = ((size_t)((b*H_ + h)*T_ + t)) * HD_;

    {
        const float* src = qkv + (size_t)bt * 3072 + h * HD_;
        float x0 = src[lane], x1 = src[lane + 32];
        float ss = x0*x0 + x1*x1;
        #pragma unroll
        for (int o = 16; o > 0; o >>= 1) ss += __shfl_xor_sync(0xffffffffu, ss, o);
        float r = rsqrtf(ss / (float)HD_ + 1e-5f);
        float y0 = qw[lane] * x0 * r;
        float y1 = qw[lane + 32] * x1 * r;
        __half h0 = __float2half(y0);
        __half h1 = __float2half(y1);
        qh[dst + lane]      = h0;
        qh[dst + lane + 32] = h1;
        ql[dst + lane]      = __float2half(y0 - __half2float(h0));
        ql[dst + lane + 32] = __float2half(y1 - __half2float(h1));
    }
    {
        const float* src = qkv + (size_t)bt * 3072 + 1024 + h * HD_;
        float x0 = src[lane], x1 = src[lane + 32];
        float ss = x0*x0 + x1*x1;
        #pragma unroll
        for (int o = 16; o > 0; o >>= 1) ss += __shfl_xor_sync(0xffffffffu, ss, o);
        float r = rsqrtf(ss / (float)HD_ + 1e-5f);
        kh[dst + lane]      = __float2half(kw[lane] * x0 * r);
        kh[dst + lane + 32] = __float2half(kw[lane + 32] * x1 * r);
    }
}

// V: [B,T,3D](col 2048+) -> [B,H,HD,T] single fp16 via 32x32 tile transpose
__global__ void vtrans_kernel(const float* __restrict__ qkv, __half* __restrict__ vh) {
    __shared__ float tile[32][33];
    int z = blockIdx.z;
    int b = z >> 4, h = z & 15;
    int t0 = blockIdx.x * 32, d0 = blockIdx.y * 32;
    #pragma unroll
    for (int j = 0; j < 32; j += 8) {
        int t = t0 + threadIdx.y + j;
        tile[threadIdx.y + j][threadIdx.x] =
            qkv[(size_t)(b*T_ + t)*3072 + 2048 + h*HD_ + d0 + threadIdx.x];
    }
    __syncthreads();
    #pragma unroll
    for (int j = 0; j < 32; j += 8) {
        int d = d0 + threadIdx.y + j;
        size_t o = ((size_t)z * HD_ + d) * T_ + t0 + threadIdx.x;
        vh[o] = __float2half(tile[threadIdx.x][threadIdx.y + j]);
    }
}

// ================= shared HMMA building blocks =================
#define HG_ROWB 80

__device__ __forceinline__ void hg_ldm4(uint32_t addr, uint32_t* r) {
    asm volatile("ldmatrix.sync.aligned.m8n8.x4.shared.b16 {%0,%1,%2,%3}, [%4];"
        : "=r"(r[0]), "=r"(r[1]), "=r"(r[2]), "=r"(r[3]) : "r"(addr));
}
__device__ __forceinline__ void hg_mma(float* d, const uint32_t* a, uint32_t b0, uint32_t b1) {
    asm volatile("mma.sync.aligned.m16n8k16.row.col.f32.f16.f16.f32 "
        "{%0,%1,%2,%3}, {%4,%5,%6,%7}, {%8,%9}, {%0,%1,%2,%3};"
        : "+f"(d[0]), "+f"(d[1]), "+f"(d[2]), "+f"(d[3])
        : "r"(a[0]), "r"(a[1]), "r"(a[2]), "r"(a[3]), "r"(b0), "r"(b1));
}

// load TERMS*A-tiles + B-tile into one stage (dense GEMMs)
template<int BM, int BN, int TERMS>
__device__ __forceinline__ void hg_load2(uint32_t stg,
    const __half* Ah, const __half* Al, const __half* Bh,
    int m0, int n0, int K, int k0, int tid)
{
    constexpr int CA = BM * 4;
    constexpr int CB = BN * 4;
    constexpr int TOT = TERMS*CA + CB;
    #pragma unroll
    for (int p = 0; p < TOT/256; p++) {
        int c = tid + p * 256;
        const __half* base; int r0; uint32_t mo; int rr;
        if (c < CA)                          { base = Ah; r0 = m0; mo = 0;                 rr = c; }
        else if (TERMS == 2 && c < 2*CA)     { base = Al; r0 = m0; mo = BM*HG_ROWB;        rr = c - CA; }
        else                                 { base = Bh; r0 = n0; mo = TERMS*BM*HG_ROWB;  rr = c - TERMS*CA; }
        int r = rr >> 2, kc = rr & 3;
        uint32_t so = stg + mo + r * HG_ROWB + kc * 16;
        const void* ga = (const void*)(base + (size_t)(r0 + r) * K + k0 + kc * 8);
        asm volatile("cp.async.cg.shared.global [%0], [%1], 16;\n" :: "r"(so), "l"(ga));
    }
    asm volatile("cp.async.commit_group;\n" ::: "memory");
}

// ======== dense GEMM: BMx128 tile, pair double-buffer, TERMS A-side terms ========
template<int MODE, int TERMS, int BM>
__global__ __launch_bounds__(256, 2)
void hgemmd_kernel(const __half* __restrict__ Ah, const __half* __restrict__ Al,
                   const __half* __restrict__ Bh,
                   const float* __restrict__ AUX, float* __restrict__ C,
                   __half* __restrict__ Gh,
                   int K, int Nout, int ldc)
{
    constexpr int BN = 128;
    constexpr int MATA  = BM * HG_ROWB;
    constexpr int STAGE = (TERMS*BM + BN) * HG_ROWB;
    constexpr int MI = 2;
    constexpr int NJ = (BM == 64) ? 4 : 8;
    constexpr int NT = (BM == 64) ? 2 : 4;

    extern __shared__ char dsm[];
    uint32_t sb = smem_u32(dsm);

    const int tid  = threadIdx.x;
    const int lane = tid & 31;
    const int wid  = tid >> 5;
    const int warpM = (BM == 64) ? (wid & 1) * 32 : (wid & 3) * 32;
    const int warpN = (BM == 64) ? (wid >> 1) * 32 : (wid >> 2) * 64;

    const int m0 = blockIdx.y * BM;
    const int n0 = blockIdx.x * BN;

    const uint32_t aoff = (uint32_t)((lane & 15) * HG_ROWB + (lane >> 4) * 16);
    const uint32_t boff = (uint32_t)(((lane & 7) + ((lane >> 4) & 1) * 8) * HG_ROWB
                                     + ((lane >> 3) & 1) * 16);

    float acc[MI][NJ][4];
    #pragma unroll
    for (int i = 0; i < MI; i++)
        #pragma unroll
        for (int j = 0; j < NJ; j++)
            #pragma unroll
            for (int u = 0; u < 4; u++) acc[i][j][u] = 0.f;

    const int nk = K / 32;
    const int np = nk / 2;

    hg_load2<BM,128,TERMS>(sb,          Ah, Al, Bh, m0, n0, K, 0,  tid);
    hg_load2<BM,128,TERMS>(sb + STAGE,  Ah, Al, Bh, m0, n0, K, 32, tid);

    for (int ip = 0; ip < np; ip++) {
        int c0 = 2 * ip;
        asm volatile("cp.async.wait_group 0;\n" ::: "memory");
        __syncthreads();
        if (c0 + 2 < nk) {
            hg_load2<BM,128,TERMS>(sb + ((c0 + 2) & 3) * STAGE, Ah, Al, Bh, m0, n0, K, (c0 + 2) * 32, tid);
            hg_load2<BM,128,TERMS>(sb + ((c0 + 3) & 3) * STAGE, Ah, Al, Bh, m0, n0, K, (c0 + 3) * 32, tid);
        }

        #pragma unroll
        for (int half = 0; half < 2; half++) {
            uint32_t st  = sb + ((c0 + half) & 3) * STAGE;
            uint32_t sAh = st;
            uint32_t sAl = st + MATA;
            uint32_t sBh = st + TERMS*MATA;
            #pragma unroll
            for (int kq = 0; kq < 2; kq++) {
                uint32_t kb = kq * 32;
                uint32_t ah[MI][4], al[MI][4], bh[NT][4];
                #pragma unroll
                for (int mi = 0; mi < MI; mi++) {
                    uint32_t rb = (uint32_t)((warpM + mi * 16) * HG_ROWB) + kb;
                    hg_ldm4(sAh + rb + aoff, ah[mi]);
                    if (TERMS == 2) hg_ldm4(sAl + rb + aoff, al[mi]);
                }
                #pragma unroll
                for (int nt = 0; nt < NT; nt++) {
                    uint32_t rbn = (uint32_t)((warpN + nt * 16) * HG_ROWB) + kb;
                    hg_ldm4(sBh + rbn + boff, bh[nt]);
                }
                #pragma unroll
                for (int mi = 0; mi < MI; mi++) {
                    #pragma unroll
                    for (int nj = 0; nj < NJ; nj++) {
                        uint32_t b0 = bh[nj >> 1][(nj & 1) * 2];
                        uint32_t b1 = bh[nj >> 1][(nj & 1) * 2 + 1];
                        hg_mma(acc[mi][nj], ah[mi], b0, b1);
                        if (TERMS == 2) hg_mma(acc[mi][nj], al[mi], b0, b1);
                    }
                }
            }
        }
    }

    const int g = lane >> 2;
    const int tq = lane & 3;
    #pragma unroll
    for (int mi = 0; mi < MI; mi++) {
        int row0 = m0 + warpM + mi * 16 + g;
        int row1 = row0 + 8;
        #pragma unroll
        for (int nj = 0; nj < NJ; nj++) {
            int col = n0 + warpN + nj * 8 + tq * 2;
            float* a = acc[mi][nj];
            if (MODE == 1) {
                size_t o0 = (size_t)row0 * ldc + col;
                size_t o1 = (size_t)row1 * ldc + col;
                C[o0]     = a[0] + AUX[o0];
                C[o0 + 1] = a[1] + AUX[o0 + 1];
                C[o1]     = a[2] + AUX[o1];
                C[o1 + 1] = a[3] + AUX[o1 + 1];
            } else if (MODE == 2) {
                #pragma unroll
                for (int half = 0; half < 2; half++) {
                    int r = half ? row1 : row0;
                    float v0 = a[half * 2], v1 = a[half * 2 + 1];
                    float g0 = 0.5f * v0 * (1.0f + erff(v0 * 0.70710678118654752f));
                    float g1 = 0.5f * v1 * (1.0f + erff(v1 * 0.70710678118654752f));
                    __half2 hp; hp.x = __float2half(g0); hp.y = __float2half(g1);
                    *(__half2*)&Gh[(size_t)r * ldc + col] = hp;
                }
            } else {
                if (col < Nout) {
                    C[(size_t)row0 * ldc + col] = a[0];
                    C[(size_t)row1 * ldc + col] = a[2];
                }
                if (col + 1 < Nout) {
                    C[(size_t)row0 * ldc + col + 1] = a[1];
                    C[(size_t)row1 * ldc + col + 1] = a[3];
                }
            }
        }
    }
}

// ================= fused flash attention =================
// 64x64 fp16 tile -> 2 chunks of [64 rows, 32 cols], rows padded to 80B
__device__ __forceinline__ void fa_load64(uint32_t dst, const __half* __restrict__ src,
                                          int r0, int c0, int ld, int tid) {
    #pragma unroll
    for (int p = 0; p < 4; p++) {
        int c = tid + p * 128;      // 0..511
        int r = c >> 3, kc = c & 7;
        uint32_t so = dst + (uint32_t)((kc >> 2) * 5120 + r * HG_ROWB + (kc & 3) * 16);
        const void* ga = (const void*)(src + (size_t)(r0 + r) * ld + c0 + kc * 8);
        asm volatile("cp.async.cg.shared.global [%0], [%1], 16;\n" :: "r"(so), "l"(ga));
    }
}

// per CTA: one (b,h,q-tile of 64). 4 warps x 16 q-rows. Streams K/V tiles of 64.
// Q 2-term; online softmax (scale 1/8, causal); O = P@V; epilogue: gate/sum, +vres, fp16 store.
__global__ __launch_bounds__(128, 2)
void flash_kernel(const __half* __restrict__ qTh, const __half* __restrict__ qTl,
                  const __half* __restrict__ kTh, const __half* __restrict__ vTh,
                  const float* __restrict__ qkv, const float* __restrict__ gate,
                  __half* __restrict__ obh)
{
    extern __shared__ char dsm[];
    uint32_t sb = smem_u32(dsm);
    const uint32_t smQ  = sb;                 // Q hi 10240 + Q lo 10240
    const uint32_t smKV = sb + 20480;         // 2 stages x (K 10240 + V 10240)

    const int tid  = threadIdx.x;
    const int lane = tid & 31;
    const int wid  = tid >> 5;
    const int qt = (int)(gridDim.x - 1 - blockIdx.x);   // heaviest first
    const int bh = blockIdx.y;
    const int b = bh >> 4, h = bh & 15;

    const __half* qh_b = qTh + (size_t)bh * T_ * HD_;
    const __half* ql_b = qTl + (size_t)bh * T_ * HD_;
    const __half* kh_b = kTh + (size_t)bh * T_ * HD_;
    const __half* vh_b = vTh + (size_t)bh * HD_ * T_;

    // preload Q (hi+lo) and K/V stage 0 in one group
    fa_load64(smQ,          qh_b, qt*64, 0, HD_, tid);
    fa_load64(smQ + 10240,  ql_b, qt*64, 0, HD_, tid);
    fa_load64(smKV,         kh_b, 0, 0, HD_, tid);
    fa_load64(smKV + 10240, vh_b, 0, 0, T_, tid);
    asm volatile("cp.async.commit_group;\n" ::: "memory");

    const uint32_t aoff = (uint32_t)((lane & 15) * HG_ROWB + (lane >> 4) * 16);
    const uint32_t boff = (uint32_t)(((lane & 7) + ((lane >> 4) & 1) * 8) * HG_ROWB
                                     + ((lane >> 3) & 1) * 16);
    const int warpM = wid * 16;
    const int g  = lane >> 2;
    const int tq = lane & 3;

    float ofr[8][4];
    #pragma unroll
    for (int j = 0; j < 8; j++)
        #pragma unroll
        for (int u = 0; u < 4; u++) ofr[j][u] = 0.f;
    float m0 = -1e30f, m1 = -1e30f, s0 = 0.f, s1 = 0.f;

    for (int kt = 0; kt <= qt; kt++) {
        asm volatile("cp.async.wait_group 0;\n" ::: "memory");
        __syncthreads();
        uint32_t stage = smKV + (uint32_t)((kt & 1) * 20480);
        if (kt < qt) {
            uint32_t nst = smKV + (uint32_t)(((kt + 1) & 1) * 20480);
            fa_load64(nst,         kh_b, (kt+1)*64, 0, HD_, tid);
            fa_load64(nst + 10240, vh_b, 0, (kt+1)*64, T_, tid);
            asm volatile("cp.async.commit_group;\n" ::: "memory");
        }

        // ---- S = Q @ K^T (2-term Q), fp32 frags ----
        float sfr[8][4];
        #pragma unroll
        for (int j = 0; j < 8; j++)
            #pragma unroll
            for (int u = 0; u < 4; u++) sfr[j][u] = 0.f;

        #pragma unroll
        for (int ks = 0; ks < 4; ks++) {
            int ch = ks >> 1;
            uint32_t kb = (uint32_t)((ks & 1) * 32);
            uint32_t aq[4], aql[4], bk[4][4];
            uint32_t qb = smQ + (uint32_t)(ch * 5120 + warpM * HG_ROWB) + kb;
            hg_ldm4(qb + aoff, aq);
            hg_ldm4(qb + 10240 + aoff, aql);
            uint32_t kbb = stage + (uint32_t)(ch * 5120) + kb;
            #pragma unroll
            for (int nt = 0; nt < 4; nt++)
                hg_ldm4(kbb + (uint32_t)(nt * 16 * HG_ROWB) + boff, bk[nt]);
            #pragma unroll
            for (int nj = 0; nj < 8; nj++) {
                uint32_t b0 = bk[nj >> 1][(nj & 1) * 2];
                uint32_t b1 = bk[nj >> 1][(nj & 1) * 2 + 1];
                hg_mma(sfr[nj], aq, b0, b1);
                hg_mma(sfr[nj], aql, b0, b1);
            }
        }

        // ---- scale + causal mask ----
        const bool diag = (kt == qt);
        #pragma unroll
        for (int nj = 0; nj < 8; nj++) {
            #pragma unroll
            for (int u = 0; u < 4; u++) {
                float v = sfr[nj][u] * 0.125f;
                if (diag) {
                    int cl = nj * 8 + tq * 2 + (u & 1);
                    int rl = warpM + g + ((u >> 1) ? 8 : 0);
                    if (cl > rl) v = -1e30f;
                }
                sfr[nj][u] = v;
            }
        }

        // ---- online softmax update ----
        float mx0 = -1e30f, mx1 = -1e30f;
        #pragma unroll
        for (int nj = 0; nj < 8; nj++) {
            mx0 = fmaxf(mx0, fmaxf(sfr[nj][0], sfr[nj][1]));
            mx1 = fmaxf(mx1, fmaxf(sfr[nj][2], sfr[nj][3]));
        }
        #pragma unroll
        for (int o = 1; o <= 2; o <<= 1) {
            mx0 = fmaxf(mx0, __shfl_xor_sync(0xffffffffu, mx0, o));
            mx1 = fmaxf(mx1, __shfl_xor_sync(0xffffffffu, mx1, o));
        }
        float nm0 = fmaxf(m0, mx0), nm1 = fmaxf(m1, mx1);
        float c0 = __expf(m0 - nm0), c1 = __expf(m1 - nm1);
        s0 *= c0; s1 *= c1;
        #pragma unroll
        for (int nj = 0; nj < 8; nj++) {
            ofr[nj][0] *= c0; ofr[nj][1] *= c0;
            ofr[nj][2] *= c1; ofr[nj][3] *= c1;
        }
        float rs0 = 0.f, rs1 = 0.f;
        #pragma unroll
        for (int nj = 0; nj < 8; nj++) {
            float p00 = __expf(sfr[nj][0] - nm0);
            float p01 = __expf(sfr[nj][1] - nm0);
            float p10 = __expf(sfr[nj][2] - nm1);
            float p11 = __expf(sfr[nj][3] - nm1);
            sfr[nj][0] = p00; sfr[nj][1] = p01; sfr[nj][2] = p10; sfr[nj][3] = p11;
            rs0 += p00 + p01; rs1 += p10 + p11;
        }
        #pragma unroll
        for (int o = 1; o <= 2; o <<= 1) {
            rs0 += __shfl_xor_sync(0xffffffffu, rs0, o);
            rs1 += __shfl_xor_sync(0xffffffffu, rs1, o);
        }
        s0 += rs0; s1 += rs1;
        m0 = nm0; m1 = nm1;

        // ---- O += P @ V  (P frags reinterpret as A frags) ----
        #pragma unroll
        for (int ks = 0; ks < 4; ks++) {
            uint32_t pa[4];
            {
                __half2 t0; t0.x = __float2half(sfr[2*ks][0]);   t0.y = __float2half(sfr[2*ks][1]);
                __half2 t1; t1.x = __float2half(sfr[2*ks][2]);   t1.y = __float2half(sfr[2*ks][3]);
                __half2 t2; t2.x = __float2half(sfr[2*ks+1][0]); t2.y = __float2half(sfr[2*ks+1][1]);
                __half2 t3; t3.x = __float2half(sfr[2*ks+1][2]); t3.y = __float2half(sfr[2*ks+1][3]);
                pa[0] = *(uint32_t*)&t0; pa[1] = *(uint32_t*)&t1;
                pa[2] = *(uint32_t*)&t2; pa[3] = *(uint32_t*)&t3;
            }
            int ch = ks >> 1;
            uint32_t kb = (uint32_t)((ks & 1) * 32);
            uint32_t vb = stage + 10240 + (uint32_t)(ch * 5120) + kb;
            uint32_t bv[4][4];
            #pragma unroll
            for (int nt = 0; nt < 4; nt++)
                hg_ldm4(vb + (uint32_t)(nt * 16 * HG_ROWB) + boff, bv[nt]);
            #pragma unroll
            for (int nj = 0; nj < 8; nj++) {
                uint32_t b0 = bv[nj >> 1][(nj & 1) * 2];
                uint32_t b1 = bv[nj >> 1][(nj & 1) * 2 + 1];
                hg_mma(ofr[nj], pa, b0, b1);
            }
        }
    }

    // ---- epilogue: gate/sum, add value residual, fp16 store ----
    float gv = gate[h];
    float inv0 = gv / s0, inv1 = gv / s1;
    int row0 = qt * 64 + warpM + g;
    int row1 = row0 + 8;
    #pragma unroll
    for (int nj = 0; nj < 8; nj++) {
        int d = nj * 8 + tq * 2;
        size_t vs0 = (size_t)(b*T_ + row0) * 3072 + 2048 + h * HD_ + d;
        size_t vs1 = (size_t)(b*T_ + row1) * 3072 + 2048 + h * HD_ + d;
        float o00 = ofr[nj][0] * inv0 + qkv[vs0];
        float o01 = ofr[nj][1] * inv0 + qkv[vs0 + 1];
        float o10 = ofr[nj][2] * inv1 + qkv[vs1];
        float o11 = ofr[nj][3] * inv1 + qkv[vs1 + 1];
        __half2 p0; p0.x = __float2half(o00); p0.y = __float2half(o01);
        __half2 p1; p1.x = __float2half(o10); p1.y = __float2half(o11);
        *(__half2*)&obh[(size_t)(b*T_ + row0) * D_ + h * HD_ + d] = p0;
        *(__half2*)&obh[(size_t)(b*T_ + row1) * D_ + h * HD_ + d] = p1;
    }
}

// ================= launcher =================
extern "C" void kernel_launch(void* const* d_in, const int* in_sizes, int n_in,
                              void* d_out, int out_size) {
    const int*   ids   = (const int*)  d_in[0];
    const float* embed = (const float*)d_in[1];
    const float* pos   = (const float*)d_in[2];
    const float* Wq    = (const float*)d_in[3];
    const float* Wk    = (const float*)d_in[4];
    const float* Wv    = (const float*)d_in[5];
    const float* Wo    = (const float*)d_in[6];
    const float* ln1   = (const float*)d_in[7];
    const float* ln2   = (const float*)d_in[8];
    const float* qnw   = (const float*)d_in[9];
    const float* knw   = (const float*)d_in[10];
    const float* gate  = (const float*)d_in[11];
    const float* W1    = (const float*)d_in[12];
    const float* W2    = (const float*)d_in[13];
    const float* lnf   = (const float*)d_in[14];
    const float* Wlm   = (const float*)d_in[15];
    float* out = (float*)d_out;

    float *x,*qkv;
    __half *hh,*obh,*mph;
    __half *qTh,*qTl,*kTh,*vTh;
    __half *wqkv,*wo,*w1,*w2,*wlm;
    cudaGetSymbolAddress((void**)&x,   g_x);
    cudaGetSymbolAddress((void**)&qkv, g_qkv);
    cudaGetSymbolAddress((void**)&hh,  g_hh);
    cudaGetSymbolAddress((void**)&obh, g_obh);
    cudaGetSymbolAddress((void**)&mph, g_mph);
    cudaGetSymbolAddress((void**)&qTh, g_qTh);
    cudaGetSymbolAddress((void**)&qTl, g_qTl);
    cudaGetSymbolAddress((void**)&kTh, g_kTh);
    cudaGetSymbolAddress((void**)&vTh, g_vTh);
    cudaGetSymbolAddress((void**)&wqkv, g_wqkv);
    cudaGetSymbolAddress((void**)&wo,  g_wo);
    cudaGetSymbolAddress((void**)&w1,  g_w1);
    cudaGetSymbolAddress((void**)&w2,  g_w2);
    cudaGetSymbolAddress((void**)&wlm, g_wlm);

    const int SD1_128 = 4 * (1*128 + 128) * HG_ROWB;   // 81920
    const int SD1_64  = 4 * (1*64  + 128) * HG_ROWB;   // 61440
    const int SFLASH  = 61440;                         // Q 20480 + 2x20480 K/V
    cudaFuncSetAttribute(hgemmd_kernel<0,1,128>, cudaFuncAttributeMaxDynamicSharedMemorySize, SD1_128);
    cudaFuncSetAttribute(hgemmd_kernel<2,1,128>, cudaFuncAttributeMaxDynamicSharedMemorySize, SD1_128);
    cudaFuncSetAttribute(hgemmd_kernel<1,1,64>,  cudaFuncAttributeMaxDynamicSharedMemorySize, SD1_64);
    cudaFuncSetAttribute(flash_kernel, cudaFuncAttributeMaxDynamicSharedMemorySize, SFLASH);

    dim3 wb(32, 8);

    embed_kernel<<<BT_*D_/256, 256>>>(ids, embed, pos, x);
    rmsnorm_h_kernel<<<BT_, 256>>>(x, ln1, hh);
    wconv3_kernel<<<dim3(D_/32, D_/32, 3*L_), wb>>>(Wq, Wk, Wv, wqkv);
    hgemmd_kernel<0,1,128><<<dim3(3072/128, BT_/128), 256, SD1_128>>>(
        hh, nullptr, wqkv, nullptr, qkv, nullptr, D_, 3072, 3072);

    wconv_kernel<<<dim3(D_/32, D_/32, L_), wb>>>(Wo, wo, D_, D_, (long long)D_*D_, (long long)D_*D_);
    wconv_kernel<<<dim3(F_/32, D_/32, L_), wb>>>(W1, w1, D_, F_, (long long)D_*F_, (long long)F_*D_);
    wconv_kernel<<<dim3(D_/32, F_/32, L_), wb>>>(W2, w2, F_, D_, (long long)F_*D_, (long long)D_*F_);
    wconv_kernel<<<dim3(VPAD_/32, D_/32, 1), wb>>>(Wlm, wlm, D_, V_, 0, 0);

    for (int l = 0; l < L_; l++) {
        qknorm2_kernel<<<(B_*T_*H_)/8, 256>>>(qkv, qnw + (size_t)l*HD_, knw + (size_t)l*HD_,
                                              qTh, qTl, kTh);
        vtrans_kernel<<<dim3(T_/32, HD_/32, B_*H_), dim3(32,8)>>>(qkv, vTh);

        // fused attention: scores + softmax + PV + gate + value residual
        flash_kernel<<<dim3(T_/64, B_*H_), 128, SFLASH>>>(
            qTh, qTl, kTh, vTh, qkv, gate + (size_t)l*H_, obh);

        // Wo with fused residual into x (1-term, BM=64)
        hgemmd_kernel<1,1,64><<<dim3(D_/128, BT_/64), 256, SD1_64>>>(
            obh, nullptr, wo + (size_t)l*D_*D_, x, x, nullptr, D_, D_, D_);

        // MLP
        rmsnorm_h_kernel<<<BT_, 256>>>(x, ln2 + (size_t)l*D_, hh);
        hgemmd_kernel<2,1,128><<<dim3(F_/128, BT_/128), 256, SD1_128>>>(
            hh, nullptr, w1 + (size_t)l*F_*D_, nullptr, nullptr, mph, D_, F_, F_);
        hgemmd_kernel<1,1,64><<<dim3(D_/128, BT_/64), 256, SD1_64>>>(
            mph, nullptr, w2 + (size_t)l*D_*F_, x, x, nullptr, F_, D_, D_);

        if (l + 1 < L_) {
            rmsnorm_h_kernel<<<BT_, 256>>>(x, ln1 + (size_t)(l+1)*D_, hh);
            hgemmd_kernel<0,1,128><<<dim3(3072/128, BT_/128), 256, SD1_128>>>(
                hh, nullptr, wqkv + (size_t)(l+1)*3072*D_, nullptr, qkv, nullptr,
                D_, 3072, 3072);
        }
    }

    rmsnorm_h_kernel<<<BT_, 256>>>(x, lnf, hh);
    hgemmd_kernel<0,1,128><<<dim3(VPAD_/128, BT_/128), 256, SD1_128>>>(
        hh, nullptr, wlm, nullptr, out, nullptr, D_, V_, V_);
}

// round 16
// speedup vs baseline: 1.7673x; 1.0199x over previous
#include <cuda_runtime.h>
#include <cuda_fp16.h>
#include <math.h>
#include <stdint.h>

// Problem dims
#define L_ 12
#define B_ 2
#define T_ 1024
#define D_ 1024
#define H_ 16
#define HD_ 64
#define F_ 4096
#define V_ 50257
#define VPAD_ 50304
#define BT_ (B_*T_)

// ================= scratch (__device__ globals) =================
__device__ float g_x  [BT_*D_];
__device__ float g_qkv[BT_*3072];

__device__ __align__(256) __half g_hh [BT_*D_];
__device__ __align__(256) __half g_obh[BT_*D_];
__device__ __align__(256) __half g_mph[BT_*F_];

// attention operands (all single fp16 now)
__device__ __align__(256) __half g_qTh[BT_*D_];          // [B,H,T,HD]
__device__ __align__(256) __half g_kTh[BT_*D_];          // [B,H,T,HD]
__device__ __align__(256) __half g_vTh[BT_*D_];          // [B,H,HD,T]

// converted+transposed weights [N,K] layout, single fp16
__device__ __align__(256) __half g_wqkv[(size_t)L_*3072*D_];
__device__ __align__(256) __half g_wo  [(size_t)L_*D_*D_];
__device__ __align__(256) __half g_w1  [(size_t)L_*F_*D_];
__device__ __align__(256) __half g_w2  [(size_t)L_*D_*F_];
__device__ __align__(256) __half g_wlm [(size_t)VPAD_*D_];

// ================= small helpers =================
__device__ __forceinline__ uint32_t smem_u32(const void* p) {
    uint32_t a;
    asm("{ .reg .u64 t; cvta.to.shared.u64 t, %1; cvt.u32.u64 %0, t; }" : "=r"(a) : "l"(p));
    return a;
}

// ================= elementwise / conversion kernels =================
__global__ void embed_kernel(const int* __restrict__ ids, const float* __restrict__ emb,
                             const float* __restrict__ pos, float* __restrict__ x) {
    int idx = blockIdx.x * 256 + threadIdx.x;
    int row = idx >> 10;
    int c   = idx & 1023;
    int t   = row & (T_-1);
    x[idx] = emb[(size_t)ids[row]*D_ + c] + pos[(size_t)t*D_ + c];
}

__global__ void wconv_kernel(const float* __restrict__ W, __half* __restrict__ oh,
                             int K, int N, long long srcStride, long long dstStride) {
    __shared__ float tile[32][33];
    const float* Ws = W + (size_t)blockIdx.z * srcStride;
    __half* ohz = oh + (size_t)blockIdx.z * dstStride;
    int n0 = blockIdx.x * 32, k0 = blockIdx.y * 32;
    #pragma unroll
    for (int j = 0; j < 32; j += 8) {
        int kk = k0 + threadIdx.y + j;
        int nn = n0 + threadIdx.x;
        tile[threadIdx.y + j][threadIdx.x] = (nn < N) ? Ws[(size_t)kk*N + nn] : 0.f;
    }
    __syncthreads();
    #pragma unroll
    for (int j = 0; j < 32; j += 8) {
        int nn = n0 + threadIdx.y + j;
        int kk = k0 + threadIdx.x;
        ohz[(size_t)nn*K + kk] = __float2half(tile[threadIdx.x][threadIdx.y + j]);
    }
}

__global__ void wconv3_kernel(const float* __restrict__ Wq, const float* __restrict__ Wk,
                              const float* __restrict__ Wv, __half* __restrict__ dst) {
    __shared__ float tile[32][33];
    int z = blockIdx.z;
    int l = z / 3, sel = z % 3;
    const float* Ws = (sel == 0 ? Wq : sel == 1 ? Wk : Wv) + (size_t)l * D_ * D_;
    __half* od = dst + ((size_t)l * 3072 + sel * D_) * D_;
    int n0 = blockIdx.x * 32, k0 = blockIdx.y * 32;
    #pragma unroll
    for (int j = 0; j < 32; j += 8) {
        tile[threadIdx.y + j][threadIdx.x] = Ws[(size_t)(k0 + threadIdx.y + j)*D_ + n0 + threadIdx.x];
    }
    __syncthreads();
    #pragma unroll
    for (int j = 0; j < 32; j += 8) {
        int nn = n0 + threadIdx.y + j;
        int kk = k0 + threadIdx.x;
        od[(size_t)nn*D_ + kk] = __float2half(tile[threadIdx.x][threadIdx.y + j]);
    }
}

__global__ void rmsnorm_h_kernel(const float* __restrict__ x, const float* __restrict__ w,
                                 __half* __restrict__ oh) {
    __shared__ float red[256];
    int row = blockIdx.x;
    const float* xr = x + (size_t)row * D_;
    float v[4]; float ss = 0.f;
    #pragma unroll
    for (int i = 0; i < 4; i++) { v[i] = xr[threadIdx.x + 256*i]; ss += v[i]*v[i]; }
    red[threadIdx.x] = ss; __syncthreads();
    for (int s = 128; s > 0; s >>= 1) {
        if (threadIdx.x < s) red[threadIdx.x] += red[threadIdx.x + s];
        __syncthreads();
    }
    float r = rsqrtf(red[0] / (float)D_ + 1e-5f);
    #pragma unroll
    for (int i = 0; i < 4; i++) {
        int c = threadIdx.x + 256*i;
        oh[(size_t)row*D_ + c] = __float2half(w[c] * v[i] * r);
    }
}

// fused QK-norm: Q row and K row, both fp16 hi only; one warp per (b,t,h)
__global__ void qknorm2_kernel(const float* __restrict__ qkv,
                               const float* __restrict__ qw, const float* __restrict__ kw,
                               __half* __restrict__ qh, __half* __restrict__ kh) {
    int warp = (blockIdx.x * blockDim.x + threadIdx.x) >> 5;
    int lane = threadIdx.x & 31;
    int h  = warp & (H_-1);
    int bt = warp >> 4;
    int t  = bt & (T_-1);
    int b  = bt >> 10;
    size_t dst = ((size_t)((b*H_ + h)*T_ + t)) * HD_;

    {
        const float* src = qkv + (size_t)bt * 3072 + h * HD_;
        float x0 = src[lane], x1 = src[lane + 32];
        float ss = x0*x0 + x1*x1;
        #pragma unroll
        for (int o = 16; o > 0; o >>= 1) ss += __shfl_xor_sync(0xffffffffu, ss, o);
        float r = rsqrtf(ss / (float)HD_ + 1e-5f);
        qh[dst + lane]      = __float2half(qw[lane] * x0 * r);
        qh[dst + lane + 32] = __float2half(qw[lane + 32] * x1 * r);
    }
    {
        const float* src = qkv + (size_t)bt * 3072 + 1024 + h * HD_;
        float x0 = src[lane], x1 = src[lane + 32];
        float ss = x0*x0 + x1*x1;
        #pragma unroll
        for (int o = 16; o > 0; o >>= 1) ss += __shfl_xor_sync(0xffffffffu, ss, o);
        float r = rsqrtf(ss / (float)HD_ + 1e-5f);
        kh[dst + lane]      = __float2half(kw[lane] * x0 * r);
        kh[dst + lane + 32] = __float2half(kw[lane + 32] * x1 * r);
    }
}

// V: [B,T,3D](col 2048+) -> [B,H,HD,T] single fp16 via 32x32 tile transpose
__global__ void vtrans_kernel(const float* __restrict__ qkv, __half* __restrict__ vh) {
    __shared__ float tile[32][33];
    int z = blockIdx.z;
    int b = z >> 4, h = z & 15;
    int t0 = blockIdx.x * 32, d0 = blockIdx.y * 32;
    #pragma unroll
    for (int j = 0; j < 32; j += 8) {
        int t = t0 + threadIdx.y + j;
        tile[threadIdx.y + j][threadIdx.x] =
            qkv[(size_t)(b*T_ + t)*3072 + 2048 + h*HD_ + d0 + threadIdx.x];
    }
    __syncthreads();
    #pragma unroll
    for (int j = 0; j < 32; j += 8) {
        int d = d0 + threadIdx.y + j;
        size_t o = ((size_t)z * HD_ + d) * T_ + t0 + threadIdx.x;
        vh[o] = __float2half(tile[threadIdx.x][threadIdx.y + j]);
    }
}

// ================= shared HMMA building blocks =================
#define HG_ROWB 80

__device__ __forceinline__ void hg_ldm4(uint32_t addr, uint32_t* r) {
    asm volatile("ldmatrix.sync.aligned.m8n8.x4.shared.b16 {%0,%1,%2,%3}, [%4];"
        : "=r"(r[0]), "=r"(r[1]), "=r"(r[2]), "=r"(r[3]) : "r"(addr));
}
__device__ __forceinline__ void hg_mma(float* d, const uint32_t* a, uint32_t b0, uint32_t b1) {
    asm volatile("mma.sync.aligned.m16n8k16.row.col.f32.f16.f16.f32 "
        "{%0,%1,%2,%3}, {%4,%5,%6,%7}, {%8,%9}, {%0,%1,%2,%3};"
        : "+f"(d[0]), "+f"(d[1]), "+f"(d[2]), "+f"(d[3])
        : "r"(a[0]), "r"(a[1]), "r"(a[2]), "r"(a[3]), "r"(b0), "r"(b1));
}

// load TERMS*A-tiles + B-tile into one stage (dense GEMMs)
template<int BM, int BN, int TERMS>
__device__ __forceinline__ void hg_load2(uint32_t stg,
    const __half* Ah, const __half* Al, const __half* Bh,
    int m0, int n0, int K, int k0, int tid)
{
    constexpr int CA = BM * 4;
    constexpr int CB = BN * 4;
    constexpr int TOT = TERMS*CA + CB;
    #pragma unroll
    for (int p = 0; p < TOT/256; p++) {
        int c = tid + p * 256;
        const __half* base; int r0; uint32_t mo; int rr;
        if (c < CA)                          { base = Ah; r0 = m0; mo = 0;                 rr = c; }
        else if (TERMS == 2 && c < 2*CA)     { base = Al; r0 = m0; mo = BM*HG_ROWB;        rr = c - CA; }
        else                                 { base = Bh; r0 = n0; mo = TERMS*BM*HG_ROWB;  rr = c - TERMS*CA; }
        int r = rr >> 2, kc = rr & 3;
        uint32_t so = stg + mo + r * HG_ROWB + kc * 16;
        const void* ga = (const void*)(base + (size_t)(r0 + r) * K + k0 + kc * 8);
        asm volatile("cp.async.cg.shared.global [%0], [%1], 16;\n" :: "r"(so), "l"(ga));
    }
    asm volatile("cp.async.commit_group;\n" ::: "memory");
}

// ======== dense GEMM: BMx128 tile, pair double-buffer, TERMS A-side terms ========
template<int MODE, int TERMS, int BM>
__global__ __launch_bounds__(256, 2)
void hgemmd_kernel(const __half* __restrict__ Ah, const __half* __restrict__ Al,
                   const __half* __restrict__ Bh,
                   const float* __restrict__ AUX, float* __restrict__ C,
                   __half* __restrict__ Gh,
                   int K, int Nout, int ldc)
{
    constexpr int BN = 128;
    constexpr int MATA  = BM * HG_ROWB;
    constexpr int STAGE = (TERMS*BM + BN) * HG_ROWB;
    constexpr int MI = 2;
    constexpr int NJ = (BM == 64) ? 4 : 8;
    constexpr int NT = (BM == 64) ? 2 : 4;

    extern __shared__ char dsm[];
    uint32_t sb = smem_u32(dsm);

    const int tid  = threadIdx.x;
    const int lane = tid & 31;
    const int wid  = tid >> 5;
    const int warpM = (BM == 64) ? (wid & 1) * 32 : (wid & 3) * 32;
    const int warpN = (BM == 64) ? (wid >> 1) * 32 : (wid >> 2) * 64;

    const int m0 = blockIdx.y * BM;
    const int n0 = blockIdx.x * BN;

    const uint32_t aoff = (uint32_t)((lane & 15) * HG_ROWB + (lane >> 4) * 16);
    const uint32_t boff = (uint32_t)(((lane & 7) + ((lane >> 4) & 1) * 8) * HG_ROWB
                                     + ((lane >> 3) & 1) * 16);

    float acc[MI][NJ][4];
    #pragma unroll
    for (int i = 0; i < MI; i++)
        #pragma unroll
        for (int j = 0; j < NJ; j++)
            #pragma unroll
            for (int u = 0; u < 4; u++) acc[i][j][u] = 0.f;

    const int nk = K / 32;
    const int np = nk / 2;

    hg_load2<BM,128,TERMS>(sb,          Ah, Al, Bh, m0, n0, K, 0,  tid);
    hg_load2<BM,128,TERMS>(sb + STAGE,  Ah, Al, Bh, m0, n0, K, 32, tid);

    for (int ip = 0; ip < np; ip++) {
        int c0 = 2 * ip;
        asm volatile("cp.async.wait_group 0;\n" ::: "memory");
        __syncthreads();
        if (c0 + 2 < nk) {
            hg_load2<BM,128,TERMS>(sb + ((c0 + 2) & 3) * STAGE, Ah, Al, Bh, m0, n0, K, (c0 + 2) * 32, tid);
            hg_load2<BM,128,TERMS>(sb + ((c0 + 3) & 3) * STAGE, Ah, Al, Bh, m0, n0, K, (c0 + 3) * 32, tid);
        }

        #pragma unroll
        for (int half = 0; half < 2; half++) {
            uint32_t st  = sb + ((c0 + half) & 3) * STAGE;
            uint32_t sAh = st;
            uint32_t sAl = st + MATA;
            uint32_t sBh = st + TERMS*MATA;
            #pragma unroll
            for (int kq = 0; kq < 2; kq++) {
                uint32_t kb = kq * 32;
                uint32_t ah[MI][4], al[MI][4], bh[NT][4];
                #pragma unroll
                for (int mi = 0; mi < MI; mi++) {
                    uint32_t rb = (uint32_t)((warpM + mi * 16) * HG_ROWB) + kb;
                    hg_ldm4(sAh + rb + aoff, ah[mi]);
                    if (TERMS == 2) hg_ldm4(sAl + rb + aoff, al[mi]);
                }
                #pragma unroll
                for (int nt = 0; nt < NT; nt++) {
                    uint32_t rbn = (uint32_t)((warpN + nt * 16) * HG_ROWB) + kb;
                    hg_ldm4(sBh + rbn + boff, bh[nt]);
                }
                #pragma unroll
                for (int mi = 0; mi < MI; mi++) {
                    #pragma unroll
                    for (int nj = 0; nj < NJ; nj++) {
                        uint32_t b0 = bh[nj >> 1][(nj & 1) * 2];
                        uint32_t b1 = bh[nj >> 1][(nj & 1) * 2 + 1];
                        hg_mma(acc[mi][nj], ah[mi], b0, b1);
                        if (TERMS == 2) hg_mma(acc[mi][nj], al[mi], b0, b1);
                    }
                }
            }
        }
    }

    const int g = lane >> 2;
    const int tq = lane & 3;
    #pragma unroll
    for (int mi = 0; mi < MI; mi++) {
        int row0 = m0 + warpM + mi * 16 + g;
        int row1 = row0 + 8;
        #pragma unroll
        for (int nj = 0; nj < NJ; nj++) {
            int col = n0 + warpN + nj * 8 + tq * 2;
            float* a = acc[mi][nj];
            if (MODE == 1) {
                size_t o0 = (size_t)row0 * ldc + col;
                size_t o1 = (size_t)row1 * ldc + col;
                C[o0]     = a[0] + AUX[o0];
                C[o0 + 1] = a[1] + AUX[o0 + 1];
                C[o1]     = a[2] + AUX[o1];
                C[o1 + 1] = a[3] + AUX[o1 + 1];
            } else if (MODE == 2) {
                #pragma unroll
                for (int half = 0; half < 2; half++) {
                    int r = half ? row1 : row0;
                    float v0 = a[half * 2], v1 = a[half * 2 + 1];
                    float g0 = 0.5f * v0 * (1.0f + erff(v0 * 0.70710678118654752f));
                    float g1 = 0.5f * v1 * (1.0f + erff(v1 * 0.70710678118654752f));
                    __half2 hp; hp.x = __float2half(g0); hp.y = __float2half(g1);
                    *(__half2*)&Gh[(size_t)r * ldc + col] = hp;
                }
            } else {
                if (col < Nout) {
                    C[(size_t)row0 * ldc + col] = a[0];
                    C[(size_t)row1 * ldc + col] = a[2];
                }
                if (col + 1 < Nout) {
                    C[(size_t)row0 * ldc + col + 1] = a[1];
                    C[(size_t)row1 * ldc + col + 1] = a[3];
                }
            }
        }
    }
}

// ================= fused flash attention =================
// 64x64 fp16 tile -> 2 chunks of [64 rows, 32 cols], rows padded to 80B
__device__ __forceinline__ void fa_load64(uint32_t dst, const __half* __restrict__ src,
                                          int r0, int c0, int ld, int tid) {
    #pragma unroll
    for (int p = 0; p < 4; p++) {
        int c = tid + p * 128;
        int r = c >> 3, kc = c & 7;
        uint32_t so = dst + (uint32_t)((kc >> 2) * 5120 + r * HG_ROWB + (kc & 3) * 16);
        const void* ga = (const void*)(src + (size_t)(r0 + r) * ld + c0 + kc * 8);
        asm volatile("cp.async.cg.shared.global [%0], [%1], 16;\n" :: "r"(so), "l"(ga));
    }
}

// per CTA: one (b,h,q-tile of 64). 4 warps x 16 q-rows. Streams K/V tiles of 64.
// Q single fp16; online softmax (scale 1/8, causal); O = P@V; gate/sum + vres + fp16 store.
__global__ __launch_bounds__(128, 3)
void flash_kernel(const __half* __restrict__ qTh,
                  const __half* __restrict__ kTh, const __half* __restrict__ vTh,
                  const float* __restrict__ qkv, const float* __restrict__ gate,
                  __half* __restrict__ obh)
{
    extern __shared__ char dsm[];
    uint32_t sb = smem_u32(dsm);
    const uint32_t smQ  = sb;                 // Q hi 10240
    const uint32_t smKV = sb + 10240;         // 2 stages x (K 10240 + V 10240)

    const int tid  = threadIdx.x;
    const int lane = tid & 31;
    const int wid  = tid >> 5;
    const int qt = (int)(gridDim.x - 1 - blockIdx.x);   // heaviest first
    const int bh = blockIdx.y;
    const int b = bh >> 4, h = bh & 15;

    const __half* qh_b = qTh + (size_t)bh * T_ * HD_;
    const __half* kh_b = kTh + (size_t)bh * T_ * HD_;
    const __half* vh_b = vTh + (size_t)bh * HD_ * T_;

    fa_load64(smQ,          qh_b, qt*64, 0, HD_, tid);
    fa_load64(smKV,         kh_b, 0, 0, HD_, tid);
    fa_load64(smKV + 10240, vh_b, 0, 0, T_, tid);
    asm volatile("cp.async.commit_group;\n" ::: "memory");

    const uint32_t aoff = (uint32_t)((lane & 15) * HG_ROWB + (lane >> 4) * 16);
    const uint32_t boff = (uint32_t)(((lane & 7) + ((lane >> 4) & 1) * 8) * HG_ROWB
                                     + ((lane >> 3) & 1) * 16);
    const int warpM = wid * 16;
    const int g  = lane >> 2;
    const int tq = lane & 3;

    float ofr[8][4];
    #pragma unroll
    for (int j = 0; j < 8; j++)
        #pragma unroll
        for (int u = 0; u < 4; u++) ofr[j][u] = 0.f;
    float m0 = -1e30f, m1 = -1e30f, s0 = 0.f, s1 = 0.f;

    for (int kt = 0; kt <= qt; kt++) {
        asm volatile("cp.async.wait_group 0;\n" ::: "memory");
        __syncthreads();
        uint32_t stage = smKV + (uint32_t)((kt & 1) * 20480);
        if (kt < qt) {
            uint32_t nst = smKV + (uint32_t)(((kt + 1) & 1) * 20480);
            fa_load64(nst,         kh_b, (kt+1)*64, 0, HD_, tid);
            fa_load64(nst + 10240, vh_b, 0, (kt+1)*64, T_, tid);
            asm volatile("cp.async.commit_group;\n" ::: "memory");
        }

        // ---- S = Q @ K^T (1-term), fp32 frags ----
        float sfr[8][4];
        #pragma unroll
        for (int j = 0; j < 8; j++)
            #pragma unroll
            for (int u = 0; u < 4; u++) sfr[j][u] = 0.f;

        #pragma unroll
        for (int ks = 0; ks < 4; ks++) {
            int ch = ks >> 1;
            uint32_t kb = (uint32_t)((ks & 1) * 32);
            uint32_t aq[4], bk[4][4];
            uint32_t qb = smQ + (uint32_t)(ch * 5120 + warpM * HG_ROWB) + kb;
            hg_ldm4(qb + aoff, aq);
            uint32_t kbb = stage + (uint32_t)(ch * 5120) + kb;
            #pragma unroll
            for (int nt = 0; nt < 4; nt++)
                hg_ldm4(kbb + (uint32_t)(nt * 16 * HG_ROWB) + boff, bk[nt]);
            #pragma unroll
            for (int nj = 0; nj < 8; nj++) {
                uint32_t b0 = bk[nj >> 1][(nj & 1) * 2];
                uint32_t b1 = bk[nj >> 1][(nj & 1) * 2 + 1];
                hg_mma(sfr[nj], aq, b0, b1);
            }
        }

        // ---- scale + causal mask ----
        const bool diag = (kt == qt);
        #pragma unroll
        for (int nj = 0; nj < 8; nj++) {
            #pragma unroll
            for (int u = 0; u < 4; u++) {
                float v = sfr[nj][u] * 0.125f;
                if (diag) {
                    int cl = nj * 8 + tq * 2 + (u & 1);
                    int rl = warpM + g + ((u >> 1) ? 8 : 0);
                    if (cl > rl) v = -1e30f;
                }
                sfr[nj][u] = v;
            }
        }

        // ---- online softmax update ----
        float mx0 = -1e30f, mx1 = -1e30f;
        #pragma unroll
        for (int nj = 0; nj < 8; nj++) {
            mx0 = fmaxf(mx0, fmaxf(sfr[nj][0], sfr[nj][1]));
            mx1 = fmaxf(mx1, fmaxf(sfr[nj][2], sfr[nj][3]));
        }
        #pragma unroll
        for (int o = 1; o <= 2; o <<= 1) {
            mx0 = fmaxf(mx0, __shfl_xor_sync(0xffffffffu, mx0, o));
            mx1 = fmaxf(mx1, __shfl_xor_sync(0xffffffffu, mx1, o));
        }
        float nm0 = fmaxf(m0, mx0), nm1 = fmaxf(m1, mx1);
        float c0 = __expf(m0 - nm0), c1 = __expf(m1 - nm1);
        s0 *= c0; s1 *= c1;
        #pragma unroll
        for (int nj = 0; nj < 8; nj++) {
            ofr[nj][0] *= c0; ofr[nj][1] *= c0;
            ofr[nj][2] *= c1; ofr[nj][3] *= c1;
        }
        float rs0 = 0.f, rs1 = 0.f;
        #pragma unroll
        for (int nj = 0; nj < 8; nj++) {
            float p00 = __expf(sfr[nj][0] - nm0);
            float p01 = __expf(sfr[nj][1] - nm0);
            float p10 = __expf(sfr[nj][2] - nm1);
            float p11 = __expf(sfr[nj][3] - nm1);
            sfr[nj][0] = p00; sfr[nj][1] = p01; sfr[nj][2] = p10; sfr[nj][3] = p11;
            rs0 += p00 + p01; rs1 += p10 + p11;
        }
        #pragma unroll
        for (int o = 1; o <= 2; o <<= 1) {
            rs0 += __shfl_xor_sync(0xffffffffu, rs0, o);
            rs1 += __shfl_xor_sync(0xffffffffu, rs1, o);
        }
        s0 += rs0; s1 += rs1;
        m0 = nm0; m1 = nm1;

        // ---- O += P @ V  (P frags reinterpret as A frags) ----
        #pragma unroll
        for (int ks = 0; ks < 4; ks++) {
            uint32_t pa[4];
            {
                __half2 t0; t0.x = __float2half(sfr[2*ks][0]);   t0.y = __float2half(sfr[2*ks][1]);
                __half2 t1; t1.x = __float2half(sfr[2*ks][2]);   t1.y = __float2half(sfr[2*ks][3]);
                __half2 t2; t2.x = __float2half(sfr[2*ks+1][0]); t2.y = __float2half(sfr[2*ks+1][1]);
                __half2 t3; t3.x = __float2half(sfr[2*ks+1][2]); t3.y = __float2half(sfr[2*ks+1][3]);
                pa[0] = *(uint32_t*)&t0; pa[1] = *(uint32_t*)&t1;
                pa[2] = *(uint32_t*)&t2; pa[3] = *(uint32_t*)&t3;
            }
            int ch = ks >> 1;
            uint32_t kb = (uint32_t)((ks & 1) * 32);
            uint32_t vb = stage + 10240 + (uint32_t)(ch * 5120) + kb;
            uint32_t bv[4][4];
            #pragma unroll
            for (int nt = 0; nt < 4; nt++)
                hg_ldm4(vb + (uint32_t)(nt * 16 * HG_ROWB) + boff, bv[nt]);
            #pragma unroll
            for (int nj = 0; nj < 8; nj++) {
                uint32_t b0 = bv[nj >> 1][(nj & 1) * 2];
                uint32_t b1 = bv[nj >> 1][(nj & 1) * 2 + 1];
                hg_mma(ofr[nj], pa, b0, b1);
            }
        }
    }

    // ---- epilogue: gate/sum, add value residual, fp16 store ----
    float gv = gate[h];
    float inv0 = gv / s0, inv1 = gv / s1;
    int row0 = qt * 64 + warpM + g;
    int row1 = row0 + 8;
    #pragma unroll
    for (int nj = 0; nj < 8; nj++) {
        int d = nj * 8 + tq * 2;
        size_t vs0 = (size_t)(b*T_ + row0) * 3072 + 2048 + h * HD_ + d;
        size_t vs1 = (size_t)(b*T_ + row1) * 3072 + 2048 + h * HD_ + d;
        float o00 = ofr[nj][0] * inv0 + qkv[vs0];
        float o01 = ofr[nj][1] * inv0 + qkv[vs0 + 1];
        float o10 = ofr[nj][2] * inv1 + qkv[vs1];
        float o11 = ofr[nj][3] * inv1 + qkv[vs1 + 1];
        __half2 p0; p0.x = __float2half(o00); p0.y = __float2half(o01);
        __half2 p1; p1.x = __float2half(o10); p1.y = __float2half(o11);
        *(__half2*)&obh[(size_t)(b*T_ + row0) * D_ + h * HD_ + d] = p0;
        *(__half2*)&obh[(size_t)(b*T_ + row1) * D_ + h * HD_ + d] = p1;
    }
}

// ================= launcher =================
extern "C" void kernel_launch(void* const* d_in, const int* in_sizes, int n_in,
                              void* d_out, int out_size) {
    const int*   ids   = (const int*)  d_in[0];
    const float* embed = (const float*)d_in[1];
    const float* pos   = (const float*)d_in[2];
    const float* Wq    = (const float*)d_in[3];
    const float* Wk    = (const float*)d_in[4];
    const float* Wv    = (const float*)d_in[5];
    const float* Wo    = (const float*)d_in[6];
    const float* ln1   = (const float*)d_in[7];
    const float* ln2   = (const float*)d_in[8];
    const float* qnw   = (const float*)d_in[9];
    const float* knw   = (const float*)d_in[10];
    const float* gate  = (const float*)d_in[11];
    const float* W1    = (const float*)d_in[12];
    const float* W2    = (const float*)d_in[13];
    const float* lnf   = (const float*)d_in[14];
    const float* Wlm   = (const float*)d_in[15];
    float* out = (float*)d_out;

    float *x,*qkv;
    __half *hh,*obh,*mph;
    __half *qTh,*kTh,*vTh;
    __half *wqkv,*wo,*w1,*w2,*wlm;
    cudaGetSymbolAddress((void**)&x,   g_x);
    cudaGetSymbolAddress((void**)&qkv, g_qkv);
    cudaGetSymbolAddress((void**)&hh,  g_hh);
    cudaGetSymbolAddress((void**)&obh, g_obh);
    cudaGetSymbolAddress((void**)&mph, g_mph);
    cudaGetSymbolAddress((void**)&qTh, g_qTh);
    cudaGetSymbolAddress((void**)&kTh, g_kTh);
    cudaGetSymbolAddress((void**)&vTh, g_vTh);
    cudaGetSymbolAddress((void**)&wqkv, g_wqkv);
    cudaGetSymbolAddress((void**)&wo,  g_wo);
    cudaGetSymbolAddress((void**)&w1,  g_w1);
    cudaGetSymbolAddress((void**)&w2,  g_w2);
    cudaGetSymbolAddress((void**)&wlm, g_wlm);

    const int SD1_128 = 4 * (1*128 + 128) * HG_ROWB;   // 81920
    const int SD1_64  = 4 * (1*64  + 128) * HG_ROWB;   // 61440
    const int SFLASH  = 51200;                         // Q 10240 + 2x20480 K/V
    cudaFuncSetAttribute(hgemmd_kernel<0,1,128>, cudaFuncAttributeMaxDynamicSharedMemorySize, SD1_128);
    cudaFuncSetAttribute(hgemmd_kernel<2,1,128>, cudaFuncAttributeMaxDynamicSharedMemorySize, SD1_128);
    cudaFuncSetAttribute(hgemmd_kernel<1,1,64>,  cudaFuncAttributeMaxDynamicSharedMemorySize, SD1_64);
    cudaFuncSetAttribute(flash_kernel, cudaFuncAttributeMaxDynamicSharedMemorySize, SFLASH);

    dim3 wb(32, 8);

    embed_kernel<<<BT_*D_/256, 256>>>(ids, embed, pos, x);
    rmsnorm_h_kernel<<<BT_, 256>>>(x, ln1, hh);
    wconv3_kernel<<<dim3(D_/32, D_/32, 3*L_), wb>>>(Wq, Wk, Wv, wqkv);
    hgemmd_kernel<0,1,128><<<dim3(3072/128, BT_/128), 256, SD1_128>>>(
        hh, nullptr, wqkv, nullptr, qkv, nullptr, D_, 3072, 3072);

    wconv_kernel<<<dim3(D_/32, D_/32, L_), wb>>>(Wo, wo, D_, D_, (long long)D_*D_, (long long)D_*D_);
    wconv_kernel<<<dim3(F_/32, D_/32, L_), wb>>>(W1, w1, D_, F_, (long long)D_*F_, (long long)F_*D_);
    wconv_kernel<<<dim3(D_/32, F_/32, L_), wb>>>(W2, w2, F_, D_, (long long)F_*D_, (long long)D_*F_);
    wconv_kernel<<<dim3(VPAD_/32, D_/32, 1), wb>>>(Wlm, wlm, D_, V_, 0, 0);

    for (int l = 0; l < L_; l++) {
        qknorm2_kernel<<<(B_*T_*H_)/8, 256>>>(qkv, qnw + (size_t)l*HD_, knw + (size_t)l*HD_,
                                              qTh, kTh);
        vtrans_kernel<<<dim3(T_/32, HD_/32, B_*H_), dim3(32,8)>>>(qkv, vTh);

        // fused attention: scores + softmax + PV + gate + value residual
        flash_kernel<<<dim3(T_/64, B_*H_), 128, SFLASH>>>(
            qTh, kTh, vTh, qkv, gate + (size_t)l*H_, obh);

        // Wo with fused residual into x (1-term, BM=64)
        hgemmd_kernel<1,1,64><<<dim3(D_/128, BT_/64), 256, SD1_64>>>(
            obh, nullptr, wo + (size_t)l*D_*D_, x, x, nullptr, D_, D_, D_);

        // MLP
        rmsnorm_h_kernel<<<BT_, 256>>>(x, ln2 + (size_t)l*D_, hh);
        hgemmd_kernel<2,1,128><<<dim3(F_/128, BT_/128), 256, SD1_128>>>(
            hh, nullptr, w1 + (size_t)l*F_*D_, nullptr, nullptr, mph, D_, F_, F_);
        hgemmd_kernel<1,1,64><<<dim3(D_/128, BT_/64), 256, SD1_64>>>(
            mph, nullptr, w2 + (size_t)l*D_*F_, x, x, nullptr, F_, D_, D_);

        if (l + 1 < L_) {
            rmsnorm_h_kernel<<<BT_, 256>>>(x, ln1 + (size_t)(l+1)*D_, hh);
            hgemmd_kernel<0,1,128><<<dim3(3072/128, BT_/128), 256, SD1_128>>>(
                hh, nullptr, wqkv + (size_t)(l+1)*3072*D_, nullptr, qkv, nullptr,
                D_, 3072, 3072);
        }
    }

    rmsnorm_h_kernel<<<BT_, 256>>>(x, lnf, hh);
    hgemmd_kernel<0,1,128><<<dim3(VPAD_/128, BT_/128), 256, SD1_128>>>(
        hh, nullptr, wlm, nullptr, out, nullptr, D_, V_, V_);
}

// round 17
// speedup vs baseline: 1.7722x; 1.0027x over previous
#include <cuda_runtime.h>
#include <cuda_fp16.h>
#include <math.h>
#include <stdint.h>

// Problem dims
#define L_ 12
#define B_ 2
#define T_ 1024
#define D_ 1024
#define H_ 16
#define HD_ 64
#define F_ 4096
#define V_ 50257
#define VPAD_ 50304
#define BT_ (B_*T_)

// ================= scratch (__device__ globals) =================
__device__ float g_x  [BT_*D_];
__device__ float g_qkv[BT_*3072];

__device__ __align__(256) __half g_hh [BT_*D_];
__device__ __align__(256) __half g_obh[BT_*D_];
__device__ __align__(256) __half g_mph[BT_*F_];

// attention operands (single fp16)
__device__ __align__(256) __half g_qTh[BT_*D_];          // [B,H,T,HD]
__device__ __align__(256) __half g_kTh[BT_*D_];          // [B,H,T,HD]
__device__ __align__(256) __half g_vTh[BT_*D_];          // [B,H,HD,T]

// converted+transposed weights [N,K] layout, single fp16
__device__ __align__(256) __half g_wqkv[(size_t)L_*3072*D_];
__device__ __align__(256) __half g_wo  [(size_t)L_*D_*D_];
__device__ __align__(256) __half g_w1  [(size_t)L_*F_*D_];
__device__ __align__(256) __half g_w2  [(size_t)L_*D_*F_];
__device__ __align__(256) __half g_wlm [(size_t)VPAD_*D_];

// ================= small helpers =================
__device__ __forceinline__ uint32_t smem_u32(const void* p) {
    uint32_t a;
    asm("{ .reg .u64 t; cvta.to.shared.u64 t, %1; cvt.u32.u64 %0, t; }" : "=r"(a) : "l"(p));
    return a;
}

// ================= elementwise / conversion kernels =================
__global__ void embed_kernel(const int* __restrict__ ids, const float* __restrict__ emb,
                             const float* __restrict__ pos, float* __restrict__ x) {
    int idx = blockIdx.x * 256 + threadIdx.x;
    int row = idx >> 10;
    int c   = idx & 1023;
    int t   = row & (T_-1);
    x[idx] = emb[(size_t)ids[row]*D_ + c] + pos[(size_t)t*D_ + c];
}

__global__ void wconv_kernel(const float* __restrict__ W, __half* __restrict__ oh,
                             int K, int N, long long srcStride, long long dstStride) {
    __shared__ float tile[32][33];
    const float* Ws = W + (size_t)blockIdx.z * srcStride;
    __half* ohz = oh + (size_t)blockIdx.z * dstStride;
    int n0 = blockIdx.x * 32, k0 = blockIdx.y * 32;
    #pragma unroll
    for (int j = 0; j < 32; j += 8) {
        int kk = k0 + threadIdx.y + j;
        int nn = n0 + threadIdx.x;
        tile[threadIdx.y + j][threadIdx.x] = (nn < N) ? Ws[(size_t)kk*N + nn] : 0.f;
    }
    __syncthreads();
    #pragma unroll
    for (int j = 0; j < 32; j += 8) {
        int nn = n0 + threadIdx.y + j;
        int kk = k0 + threadIdx.x;
        ohz[(size_t)nn*K + kk] = __float2half(tile[threadIdx.x][threadIdx.y + j]);
    }
}

__global__ void wconv3_kernel(const float* __restrict__ Wq, const float* __restrict__ Wk,
                              const float* __restrict__ Wv, __half* __restrict__ dst) {
    __shared__ float tile[32][33];
    int z = blockIdx.z;
    int l = z / 3, sel = z % 3;
    const float* Ws = (sel == 0 ? Wq : sel == 1 ? Wk : Wv) + (size_t)l * D_ * D_;
    __half* od = dst + ((size_t)l * 3072 + sel * D_) * D_;
    int n0 = blockIdx.x * 32, k0 = blockIdx.y * 32;
    #pragma unroll
    for (int j = 0; j < 32; j += 8) {
        tile[threadIdx.y + j][threadIdx.x] = Ws[(size_t)(k0 + threadIdx.y + j)*D_ + n0 + threadIdx.x];
    }
    __syncthreads();
    #pragma unroll
    for (int j = 0; j < 32; j += 8) {
        int nn = n0 + threadIdx.y + j;
        int kk = k0 + threadIdx.x;
        od[(size_t)nn*D_ + kk] = __float2half(tile[threadIdx.x][threadIdx.y + j]);
    }
}

__global__ void rmsnorm_h_kernel(const float* __restrict__ x, const float* __restrict__ w,
                                 __half* __restrict__ oh) {
    __shared__ float red[256];
    int row = blockIdx.x;
    const float* xr = x + (size_t)row * D_;
    float v[4]; float ss = 0.f;
    #pragma unroll
    for (int i = 0; i < 4; i++) { v[i] = xr[threadIdx.x + 256*i]; ss += v[i]*v[i]; }
    red[threadIdx.x] = ss; __syncthreads();
    for (int s = 128; s > 0; s >>= 1) {
        if (threadIdx.x < s) red[threadIdx.x] += red[threadIdx.x + s];
        __syncthreads();
    }
    float r = rsqrtf(red[0] / (float)D_ + 1e-5f);
    #pragma unroll
    for (int i = 0; i < 4; i++) {
        int c = threadIdx.x + 256*i;
        oh[(size_t)row*D_ + c] = __float2half(w[c] * v[i] * r);
    }
}

// fused QK-norm: Q row and K row, both fp16 hi only; one warp per (b,t,h)
__global__ void qknorm2_kernel(const float* __restrict__ qkv,
                               const float* __restrict__ qw, const float* __restrict__ kw,
                               __half* __restrict__ qh, __half* __restrict__ kh) {
    int warp = (blockIdx.x * blockDim.x + threadIdx.x) >> 5;
    int lane = threadIdx.x & 31;
    int h  = warp & (H_-1);
    int bt = warp >> 4;
    int t  = bt & (T_-1);
    int b  = bt >> 10;
    size_t dst = ((size_t)((b*H_ + h)*T_ + t)) * HD_;

    {
        const float* src = qkv + (size_t)bt * 3072 + h * HD_;
        float x0 = src[lane], x1 = src[lane + 32];
        float ss = x0*x0 + x1*x1;
        #pragma unroll
        for (int o = 16; o > 0; o >>= 1) ss += __shfl_xor_sync(0xffffffffu, ss, o);
        float r = rsqrtf(ss / (float)HD_ + 1e-5f);
        qh[dst + lane]      = __float2half(qw[lane] * x0 * r);
        qh[dst + lane + 32] = __float2half(qw[lane + 32] * x1 * r);
    }
    {
        const float* src = qkv + (size_t)bt * 3072 + 1024 + h * HD_;
        float x0 = src[lane], x1 = src[lane + 32];
        float ss = x0*x0 + x1*x1;
        #pragma unroll
        for (int o = 16; o > 0; o >>= 1) ss += __shfl_xor_sync(0xffffffffu, ss, o);
        float r = rsqrtf(ss / (float)HD_ + 1e-5f);
        kh[dst + lane]      = __float2half(kw[lane] * x0 * r);
        kh[dst + lane + 32] = __float2half(kw[lane + 32] * x1 * r);
    }
}

// V: [B,T,3D](col 2048+) -> [B,H,HD,T] single fp16 via 32x32 tile transpose
__global__ void vtrans_kernel(const float* __restrict__ qkv, __half* __restrict__ vh) {
    __shared__ float tile[32][33];
    int z = blockIdx.z;
    int b = z >> 4, h = z & 15;
    int t0 = blockIdx.x * 32, d0 = blockIdx.y * 32;
    #pragma unroll
    for (int j = 0; j < 32; j += 8) {
        int t = t0 + threadIdx.y + j;
        tile[threadIdx.y + j][threadIdx.x] =
            qkv[(size_t)(b*T_ + t)*3072 + 2048 + h*HD_ + d0 + threadIdx.x];
    }
    __syncthreads();
    #pragma unroll
    for (int j = 0; j < 32; j += 8) {
        int d = d0 + threadIdx.y + j;
        size_t o = ((size_t)z * HD_ + d) * T_ + t0 + threadIdx.x;
        vh[o] = __float2half(tile[threadIdx.x][threadIdx.y + j]);
    }
}

// ================= shared HMMA building blocks =================
#define HG_ROWB 80

__device__ __forceinline__ void hg_ldm4(uint32_t addr, uint32_t* r) {
    asm volatile("ldmatrix.sync.aligned.m8n8.x4.shared.b16 {%0,%1,%2,%3}, [%4];"
        : "=r"(r[0]), "=r"(r[1]), "=r"(r[2]), "=r"(r[3]) : "r"(addr));
}
__device__ __forceinline__ void hg_mma(float* d, const uint32_t* a, uint32_t b0, uint32_t b1) {
    asm volatile("mma.sync.aligned.m16n8k16.row.col.f32.f16.f16.f32 "
        "{%0,%1,%2,%3}, {%4,%5,%6,%7}, {%8,%9}, {%0,%1,%2,%3};"
        : "+f"(d[0]), "+f"(d[1]), "+f"(d[2]), "+f"(d[3])
        : "r"(a[0]), "r"(a[1]), "r"(a[2]), "r"(a[3]), "r"(b0), "r"(b1));
}

// load A-tile + B-tile into one stage (dense, 1-term, THREADS threads)
template<int BM, int BN, int THREADS>
__device__ __forceinline__ void hg_load1(uint32_t stg,
    const __half* Ah, const __half* Bh,
    int m0, int n0, int K, int k0, int tid)
{
    constexpr int CA = BM * 4;
    constexpr int CB = BN * 4;
    constexpr int TOT = CA + CB;
    #pragma unroll
    for (int p = 0; p < TOT/THREADS; p++) {
        int c = tid + p * THREADS;
        const __half* base; int r0; uint32_t mo; int rr;
        if (c < CA) { base = Ah; r0 = m0; mo = 0;           rr = c; }
        else        { base = Bh; r0 = n0; mo = BM*HG_ROWB;  rr = c - CA; }
        int r = rr >> 2, kc = rr & 3;
        uint32_t so = stg + mo + r * HG_ROWB + kc * 16;
        const void* ga = (const void*)(base + (size_t)(r0 + r) * K + k0 + kc * 8);
        asm volatile("cp.async.cg.shared.global [%0], [%1], 16;\n" :: "r"(so), "l"(ga));
    }
    asm volatile("cp.async.commit_group;\n" ::: "memory");
}

// ======== dense GEMM: BMx128 tile, 128 threads (4 warps), pair double-buffer ========
// BM=128: 2x2 warps, warp tile 64x64 (MI=4, NT=4, ratio 4).
// BM=64 : 1x4 warps, warp tile 64x32 (MI=4, NT=2, ratio 2.67).
// C[M,N] = Ah[M,K] @ Bh[N,K]^T.  MODE: 0=plain(guard Nout), 1=+RES, 2=GELU->fp16 hi
template<int MODE, int BM>
__global__ __launch_bounds__(128, 2)
void hgemmd_kernel(const __half* __restrict__ Ah,
                   const __half* __restrict__ Bh,
                   const float* __restrict__ AUX, float* __restrict__ C,
                   __half* __restrict__ Gh,
                   int K, int Nout, int ldc)
{
    constexpr int BN = 128;
    constexpr int STAGE = (BM + BN) * HG_ROWB;
    constexpr int MI = 4;
    constexpr int NJ = (BM == 64) ? 4 : 8;
    constexpr int NT = (BM == 64) ? 2 : 4;

    extern __shared__ char dsm[];
    uint32_t sb = smem_u32(dsm);

    const int tid  = threadIdx.x;
    const int lane = tid & 31;
    const int wid  = tid >> 5;
    const int warpM = (BM == 64) ? 0 : (wid & 1) * 64;
    const int warpN = (BM == 64) ? wid * 32 : (wid >> 1) * 64;

    const int m0 = blockIdx.y * BM;
    const int n0 = blockIdx.x * BN;

    const uint32_t aoff = (uint32_t)((lane & 15) * HG_ROWB + (lane >> 4) * 16);
    const uint32_t boff = (uint32_t)(((lane & 7) + ((lane >> 4) & 1) * 8) * HG_ROWB
                                     + ((lane >> 3) & 1) * 16);

    float acc[MI][NJ][4];
    #pragma unroll
    for (int i = 0; i < MI; i++)
        #pragma unroll
        for (int j = 0; j < NJ; j++)
            #pragma unroll
            for (int u = 0; u < 4; u++) acc[i][j][u] = 0.f;

    const int nk = K / 32;
    const int np = nk / 2;

    hg_load1<BM,128,128>(sb,          Ah, Bh, m0, n0, K, 0,  tid);
    hg_load1<BM,128,128>(sb + STAGE,  Ah, Bh, m0, n0, K, 32, tid);

    for (int ip = 0; ip < np; ip++) {
        int c0 = 2 * ip;
        asm volatile("cp.async.wait_group 0;\n" ::: "memory");
        __syncthreads();
        if (c0 + 2 < nk) {
            hg_load1<BM,128,128>(sb + ((c0 + 2) & 3) * STAGE, Ah, Bh, m0, n0, K, (c0 + 2) * 32, tid);
            hg_load1<BM,128,128>(sb + ((c0 + 3) & 3) * STAGE, Ah, Bh, m0, n0, K, (c0 + 3) * 32, tid);
        }

        #pragma unroll
        for (int half = 0; half < 2; half++) {
            uint32_t st  = sb + ((c0 + half) & 3) * STAGE;
            uint32_t sBh = st + BM*HG_ROWB;
            #pragma unroll
            for (int kq = 0; kq < 2; kq++) {
                uint32_t kb = kq * 32;
                uint32_t ah[MI][4], bh[NT][4];
                #pragma unroll
                for (int mi = 0; mi < MI; mi++) {
                    uint32_t rb = (uint32_t)((warpM + mi * 16) * HG_ROWB) + kb;
                    hg_ldm4(st + rb + aoff, ah[mi]);
                }
                #pragma unroll
                for (int nt = 0; nt < NT; nt++) {
                    uint32_t rbn = (uint32_t)((warpN + nt * 16) * HG_ROWB) + kb;
                    hg_ldm4(sBh + rbn + boff, bh[nt]);
                }
                #pragma unroll
                for (int mi = 0; mi < MI; mi++) {
                    #pragma unroll
                    for (int nj = 0; nj < NJ; nj++) {
                        uint32_t b0 = bh[nj >> 1][(nj & 1) * 2];
                        uint32_t b1 = bh[nj >> 1][(nj & 1) * 2 + 1];
                        hg_mma(acc[mi][nj], ah[mi], b0, b1);
                    }
                }
            }
        }
    }

    const int g = lane >> 2;
    const int tq = lane & 3;
    #pragma unroll
    for (int mi = 0; mi < MI; mi++) {
        int row0 = m0 + warpM + mi * 16 + g;
        int row1 = row0 + 8;
        #pragma unroll
        for (int nj = 0; nj < NJ; nj++) {
            int col = n0 + warpN + nj * 8 + tq * 2;
            float* a = acc[mi][nj];
            if (MODE == 1) {
                size_t o0 = (size_t)row0 * ldc + col;
                size_t o1 = (size_t)row1 * ldc + col;
                C[o0]     = a[0] + AUX[o0];
                C[o0 + 1] = a[1] + AUX[o0 + 1];
                C[o1]     = a[2] + AUX[o1];
                C[o1 + 1] = a[3] + AUX[o1 + 1];
            } else if (MODE == 2) {
                #pragma unroll
                for (int half = 0; half < 2; half++) {
                    int r = half ? row1 : row0;
                    float v0 = a[half * 2], v1 = a[half * 2 + 1];
                    float g0 = 0.5f * v0 * (1.0f + erff(v0 * 0.70710678118654752f));
                    float g1 = 0.5f * v1 * (1.0f + erff(v1 * 0.70710678118654752f));
                    __half2 hp; hp.x = __float2half(g0); hp.y = __float2half(g1);
                    *(__half2*)&Gh[(size_t)r * ldc + col] = hp;
                }
            } else {
                if (col < Nout) {
                    C[(size_t)row0 * ldc + col] = a[0];
                    C[(size_t)row1 * ldc + col] = a[2];
                }
                if (col + 1 < Nout) {
                    C[(size_t)row0 * ldc + col + 1] = a[1];
                    C[(size_t)row1 * ldc + col + 1] = a[3];
                }
            }
        }
    }
}

// ================= fused flash attention =================
// 64x64 fp16 tile -> 2 chunks of [64 rows, 32 cols], rows padded to 80B
__device__ __forceinline__ void fa_load64(uint32_t dst, const __half* __restrict__ src,
                                          int r0, int c0, int ld, int tid) {
    #pragma unroll
    for (int p = 0; p < 4; p++) {
        int c = tid + p * 128;
        int r = c >> 3, kc = c & 7;
        uint32_t so = dst + (uint32_t)((kc >> 2) * 5120 + r * HG_ROWB + (kc & 3) * 16);
        const void* ga = (const void*)(src + (size_t)(r0 + r) * ld + c0 + kc * 8);
        asm volatile("cp.async.cg.shared.global [%0], [%1], 16;\n" :: "r"(so), "l"(ga));
    }
}

// per CTA: one (b,h,q-tile of 64). 4 warps x 16 q-rows. Streams K/V tiles of 64.
__global__ __launch_bounds__(128, 3)
void flash_kernel(const __half* __restrict__ qTh,
                  const __half* __restrict__ kTh, const __half* __restrict__ vTh,
                  const float* __restrict__ qkv, const float* __restrict__ gate,
                  __half* __restrict__ obh)
{
    extern __shared__ char dsm[];
    uint32_t sb = smem_u32(dsm);
    const uint32_t smQ  = sb;
    const uint32_t smKV = sb + 10240;

    const int tid  = threadIdx.x;
    const int lane = tid & 31;
    const int wid  = tid >> 5;
    const int qt = (int)(gridDim.x - 1 - blockIdx.x);
    const int bh = blockIdx.y;
    const int b = bh >> 4, h = bh & 15;

    const __half* qh_b = qTh + (size_t)bh * T_ * HD_;
    const __half* kh_b = kTh + (size_t)bh * T_ * HD_;
    const __half* vh_b = vTh + (size_t)bh * HD_ * T_;

    fa_load64(smQ,          qh_b, qt*64, 0, HD_, tid);
    fa_load64(smKV,         kh_b, 0, 0, HD_, tid);
    fa_load64(smKV + 10240, vh_b, 0, 0, T_, tid);
    asm volatile("cp.async.commit_group;\n" ::: "memory");

    const uint32_t aoff = (uint32_t)((lane & 15) * HG_ROWB + (lane >> 4) * 16);
    const uint32_t boff = (uint32_t)(((lane & 7) + ((lane >> 4) & 1) * 8) * HG_ROWB
                                     + ((lane >> 3) & 1) * 16);
    const int warpM = wid * 16;
    const int g  = lane >> 2;
    const int tq = lane & 3;

    float ofr[8][4];
    #pragma unroll
    for (int j = 0; j < 8; j++)
        #pragma unroll
        for (int u = 0; u < 4; u++) ofr[j][u] = 0.f;
    float m0 = -1e30f, m1 = -1e30f, s0 = 0.f, s1 = 0.f;

    for (int kt = 0; kt <= qt; kt++) {
        asm volatile("cp.async.wait_group 0;\n" ::: "memory");
        __syncthreads();
        uint32_t stage = smKV + (uint32_t)((kt & 1) * 20480);
        if (kt < qt) {
            uint32_t nst = smKV + (uint32_t)(((kt + 1) & 1) * 20480);
            fa_load64(nst,         kh_b, (kt+1)*64, 0, HD_, tid);
            fa_load64(nst + 10240, vh_b, 0, (kt+1)*64, T_, tid);
            asm volatile("cp.async.commit_group;\n" ::: "memory");
        }

        float sfr[8][4];
        #pragma unroll
        for (int j = 0; j < 8; j++)
            #pragma unroll
            for (int u = 0; u < 4; u++) sfr[j][u] = 0.f;

        #pragma unroll
        for (int ks = 0; ks < 4; ks++) {
            int ch = ks >> 1;
            uint32_t kb = (uint32_t)((ks & 1) * 32);
            uint32_t aq[4], bk[4][4];
            uint32_t qb = smQ + (uint32_t)(ch * 5120 + warpM * HG_ROWB) + kb;
            hg_ldm4(qb + aoff, aq);
            uint32_t kbb = stage + (uint32_t)(ch * 5120) + kb;
            #pragma unroll
            for (int nt = 0; nt < 4; nt++)
                hg_ldm4(kbb + (uint32_t)(nt * 16 * HG_ROWB) + boff, bk[nt]);
            #pragma unroll
            for (int nj = 0; nj < 8; nj++) {
                uint32_t b0 = bk[nj >> 1][(nj & 1) * 2];
                uint32_t b1 = bk[nj >> 1][(nj & 1) * 2 + 1];
                hg_mma(sfr[nj], aq, b0, b1);
            }
        }

        const bool diag = (kt == qt);
        #pragma unroll
        for (int nj = 0; nj < 8; nj++) {
            #pragma unroll
            for (int u = 0; u < 4; u++) {
                float v = sfr[nj][u] * 0.125f;
                if (diag) {
                    int cl = nj * 8 + tq * 2 + (u & 1);
                    int rl = warpM + g + ((u >> 1) ? 8 : 0);
                    if (cl > rl) v = -1e30f;
                }
                sfr[nj][u] = v;
            }
        }

        float mx0 = -1e30f, mx1 = -1e30f;
        #pragma unroll
        for (int nj = 0; nj < 8; nj++) {
            mx0 = fmaxf(mx0, fmaxf(sfr[nj][0], sfr[nj][1]));
            mx1 = fmaxf(mx1, fmaxf(sfr[nj][2], sfr[nj][3]));
        }
        #pragma unroll
        for (int o = 1; o <= 2; o <<= 1) {
            mx0 = fmaxf(mx0, __shfl_xor_sync(0xffffffffu, mx0, o));
            mx1 = fmaxf(mx1, __shfl_xor_sync(0xffffffffu, mx1, o));
        }
        float nm0 = fmaxf(m0, mx0), nm1 = fmaxf(m1, mx1);
        float c0 = __expf(m0 - nm0), c1 = __expf(m1 - nm1);
        s0 *= c0; s1 *= c1;
        #pragma unroll
        for (int nj = 0; nj < 8; nj++) {
            ofr[nj][0] *= c0; ofr[nj][1] *= c0;
            ofr[nj][2] *= c1; ofr[nj][3] *= c1;
        }
        float rs0 = 0.f, rs1 = 0.f;
        #pragma unroll
        for (int nj = 0; nj < 8; nj++) {
            float p00 = __expf(sfr[nj][0] - nm0);
            float p01 = __expf(sfr[nj][1] - nm0);
            float p10 = __expf(sfr[nj][2] - nm1);
            float p11 = __expf(sfr[nj][3] - nm1);
            sfr[nj][0] = p00; sfr[nj][1] = p01; sfr[nj][2] = p10; sfr[nj][3] = p11;
            rs0 += p00 + p01; rs1 += p10 + p11;
        }
        #pragma unroll
        for (int o = 1; o <= 2; o <<= 1) {
            rs0 += __shfl_xor_sync(0xffffffffu, rs0, o);
            rs1 += __shfl_xor_sync(0xffffffffu, rs1, o);
        }
        s0 += rs0; s1 += rs1;
        m0 = nm0; m1 = nm1;

        #pragma unroll
        for (int ks = 0; ks < 4; ks++) {
            uint32_t pa[4];
            {
                __half2 t0; t0.x = __float2half(sfr[2*ks][0]);   t0.y = __float2half(sfr[2*ks][1]);
                __half2 t1; t1.x = __float2half(sfr[2*ks][2]);   t1.y = __float2half(sfr[2*ks][3]);
                __half2 t2; t2.x = __float2half(sfr[2*ks+1][0]); t2.y = __float2half(sfr[2*ks+1][1]);
                __half2 t3; t3.x = __float2half(sfr[2*ks+1][2]); t3.y = __float2half(sfr[2*ks+1][3]);
                pa[0] = *(uint32_t*)&t0; pa[1] = *(uint32_t*)&t1;
                pa[2] = *(uint32_t*)&t2; pa[3] = *(uint32_t*)&t3;
            }
            int ch = ks >> 1;
            uint32_t kb = (uint32_t)((ks & 1) * 32);
            uint32_t vb = stage + 10240 + (uint32_t)(ch * 5120) + kb;
            uint32_t bv[4][4];
            #pragma unroll
            for (int nt = 0; nt < 4; nt++)
                hg_ldm4(vb + (uint32_t)(nt * 16 * HG_ROWB) + boff, bv[nt]);
            #pragma unroll
            for (int nj = 0; nj < 8; nj++) {
                uint32_t b0 = bv[nj >> 1][(nj & 1) * 2];
                uint32_t b1 = bv[nj >> 1][(nj & 1) * 2 + 1];
                hg_mma(ofr[nj], pa, b0, b1);
            }
        }
    }

    float gv = gate[h];
    float inv0 = gv / s0, inv1 = gv / s1;
    int row0 = qt * 64 + warpM + g;
    int row1 = row0 + 8;
    #pragma unroll
    for (int nj = 0; nj < 8; nj++) {
        int d = nj * 8 + tq * 2;
        size_t vs0 = (size_t)(b*T_ + row0) * 3072 + 2048 + h * HD_ + d;
        size_t vs1 = (size_t)(b*T_ + row1) * 3072 + 2048 + h * HD_ + d;
        float o00 = ofr[nj][0] * inv0 + qkv[vs0];
        float o01 = ofr[nj][1] * inv0 + qkv[vs0 + 1];
        float o10 = ofr[nj][2] * inv1 + qkv[vs1];
        float o11 = ofr[nj][3] * inv1 + qkv[vs1 + 1];
        __half2 p0; p0.x = __float2half(o00); p0.y = __float2half(o01);
        __half2 p1; p1.x = __float2half(o10); p1.y = __float2half(o11);
        *(__half2*)&obh[(size_t)(b*T_ + row0) * D_ + h * HD_ + d] = p0;
        *(__half2*)&obh[(size_t)(b*T_ + row1) * D_ + h * HD_ + d] = p1;
    }
}

// ================= launcher =================
extern "C" void kernel_launch(void* const* d_in, const int* in_sizes, int n_in,
                              void* d_out, int out_size) {
    const int*   ids   = (const int*)  d_in[0];
    const float* embed = (const float*)d_in[1];
    const float* pos   = (const float*)d_in[2];
    const float* Wq    = (const float*)d_in[3];
    const float* Wk    = (const float*)d_in[4];
    const float* Wv    = (const float*)d_in[5];
    const float* Wo    = (const float*)d_in[6];
    const float* ln1   = (const float*)d_in[7];
    const float* ln2   = (const float*)d_in[8];
    const float* qnw   = (const float*)d_in[9];
    const float* knw   = (const float*)d_in[10];
    const float* gate  = (const float*)d_in[11];
    const float* W1    = (const float*)d_in[12];
    const float* W2    = (const float*)d_in[13];
    const float* lnf   = (const float*)d_in[14];
    const float* Wlm   = (const float*)d_in[15];
    float* out = (float*)d_out;

    float *x,*qkv;
    __half *hh,*obh,*mph;
    __half *qTh,*kTh,*vTh;
    __half *wqkv,*wo,*w1,*w2,*wlm;
    cudaGetSymbolAddress((void**)&x,   g_x);
    cudaGetSymbolAddress((void**)&qkv, g_qkv);
    cudaGetSymbolAddress((void**)&hh,  g_hh);
    cudaGetSymbolAddress((void**)&obh, g_obh);
    cudaGetSymbolAddress((void**)&mph, g_mph);
    cudaGetSymbolAddress((void**)&qTh, g_qTh);
    cudaGetSymbolAddress((void**)&kTh, g_kTh);
    cudaGetSymbolAddress((void**)&vTh, g_vTh);
    cudaGetSymbolAddress((void**)&wqkv, g_wqkv);
    cudaGetSymbolAddress((void**)&wo,  g_wo);
    cudaGetSymbolAddress((void**)&w1,  g_w1);
    cudaGetSymbolAddress((void**)&w2,  g_w2);
    cudaGetSymbolAddress((void**)&wlm, g_wlm);

    const int SD_128 = 4 * (128 + 128) * HG_ROWB;   // 81920 (BM=128)
    const int SD_64  = 4 * (64  + 128) * HG_ROWB;   // 61440 (BM=64)
    const int SFLASH = 51200;
    cudaFuncSetAttribute(hgemmd_kernel<0,128>, cudaFuncAttributeMaxDynamicSharedMemorySize, SD_128);
    cudaFuncSetAttribute(hgemmd_kernel<2,128>, cudaFuncAttributeMaxDynamicSharedMemorySize, SD_128);
    cudaFuncSetAttribute(hgemmd_kernel<1,64>,  cudaFuncAttributeMaxDynamicSharedMemorySize, SD_64);
    cudaFuncSetAttribute(flash_kernel, cudaFuncAttributeMaxDynamicSharedMemorySize, SFLASH);

    dim3 wb(32, 8);

    embed_kernel<<<BT_*D_/256, 256>>>(ids, embed, pos, x);
    rmsnorm_h_kernel<<<BT_, 256>>>(x, ln1, hh);
    wconv3_kernel<<<dim3(D_/32, D_/32, 3*L_), wb>>>(Wq, Wk, Wv, wqkv);
    hgemmd_kernel<0,128><<<dim3(3072/128, BT_/128), 128, SD_128>>>(
        hh, wqkv, nullptr, qkv, nullptr, D_, 3072, 3072);

    wconv_kernel<<<dim3(D_/32, D_/32, L_), wb>>>(Wo, wo, D_, D_, (long long)D_*D_, (long long)D_*D_);
    wconv_kernel<<<dim3(F_/32, D_/32, L_), wb>>>(W1, w1, D_, F_, (long long)D_*F_, (long long)F_*D_);
    wconv_kernel<<<dim3(D_/32, F_/32, L_), wb>>>(W2, w2, F_, D_, (long long)F_*D_, (long long)D_*F_);
    wconv_kernel<<<dim3(VPAD_/32, D_/32, 1), wb>>>(Wlm, wlm, D_, V_, 0, 0);

    for (int l = 0; l < L_; l++) {
        qknorm2_kernel<<<(B_*T_*H_)/8, 256>>>(qkv, qnw + (size_t)l*HD_, knw + (size_t)l*HD_,
                                              qTh, kTh);
        vtrans_kernel<<<dim3(T_/32, HD_/32, B_*H_), dim3(32,8)>>>(qkv, vTh);

        flash_kernel<<<dim3(T_/64, B_*H_), 128, SFLASH>>>(
            qTh, kTh, vTh, qkv, gate + (size_t)l*H_, obh);

        hgemmd_kernel<1,64><<<dim3(D_/128, BT_/64), 128, SD_64>>>(
            obh, wo + (size_t)l*D_*D_, x, x, nullptr, D_, D_, D_);

        rmsnorm_h_kernel<<<BT_, 256>>>(x, ln2 + (size_t)l*D_, hh);
        hgemmd_kernel<2,128><<<dim3(F_/128, BT_/128), 128, SD_128>>>(
            hh, w1 + (size_t)l*F_*D_, nullptr, nullptr, mph, D_, F_, F_);
        hgemmd_kernel<1,64><<<dim3(D_/128, BT_/64), 128, SD_64>>>(
            mph, w2 + (size_t)l*D_*F_, x, x, nullptr, F_, D_, D_);

        if (l + 1 < L_) {
            rmsnorm_h_kernel<<<BT_, 256>>>(x, ln1 + (size_t)(l+1)*D_, hh);
            hgemmd_kernel<0,128><<<dim3(3072/128, BT_/128), 128, SD_128>>>(
                hh, wqkv + (size_t)(l+1)*3072*D_, nullptr, qkv, nullptr, D_, 3072, 3072);
        }
    }

    rmsnorm_h_kernel<<<BT_, 256>>>(x, lnf, hh);
    hgemmd_kernel<0,128><<<dim3(VPAD_/128, BT_/128), 128, SD_128>>>(
        hh, wlm, nullptr, out, nullptr, D_, V_, V_);
}